// round 9
// baseline (speedup 1.0000x reference)
#include <cuda_runtime.h>
#include <math.h>

// ---------------- problem constants ----------------
#define NB   2        // batch
#define H1   128      // conv1/conv2 spatial
#define W1   128
#define HP   63       // pooled spatial
#define NQ   8        // 4 crops * batch 2
#define HO   48       // conv5 output spatial
#define PX5  2304     // 48*48

// ---------------- intermediate buffers (device globals; no allocation) ----------------
__device__ float g_a[NB*64*H1*W1];     // conv1 out            (8 MB)
__device__ float g_b[NB*64*H1*W1];     // conv2+LRN out        (8 MB)
__device__ float g_p[NQ*64*HP*HP];     // crops+maxpool out    (8.1 MB)
__device__ float g_c[NQ*64*HP*HP];     // conv3 out
__device__ float g_d[NQ*64*HP*HP];     // conv4+LRN out
__device__ float g_e[NQ*1024*HO*HO];   // conv5 out            (75.5 MB)
__device__ float g_f[NQ*1024*HO*HO];   // conv6 out            (75.5 MB)

// =====================================================================
// Generic 64-output-channel direct conv, SAME padding, 16x16 spatial tile.
// Thread microtile: 8 co x 8 px (fixed col, rows rbase, rbase+2, ...).
// Warp = one co-group -> weight LDS are uniform (broadcast).
// Patch rows padded to stride 48 (48 mod 32 == 16 -> conflict-free).
// Optional fused LRN (size=2, alpha=2e-5, beta=0.75, k=1).
// =====================================================================
template<int K, int CIN, int CCH, bool DO_LRN>
__global__ __launch_bounds__(256) void conv_tile(
    const float* __restrict__ in, const float* __restrict__ w,
    const float* __restrict__ bias, float* __restrict__ out,
    int H, int W)
{
    constexpr int KK    = K * K;
    constexpr int PAD   = K / 2;
    constexpr int PH    = 16 + K - 1;         // patch logical extent
    constexpr int PATCH = CCH * PH * 48;      // padded-stride patch
    constexpr int WELE  = 64 * CCH * KK;
    __shared__ float sm[PATCH + WELE];
    float* patch = sm;
    float* wsm   = sm + PATCH;

    const int tid   = threadIdx.x;
    const int cog   = tid >> 5;       // 0..7 (8 co per thread)
    const int pxt   = tid & 31;
    const int col   = pxt & 15;
    const int rbase = pxt >> 4;       // rows rbase + 2*i
    const int x0 = blockIdx.x * 16;
    const int y0 = blockIdx.y * 16;
    const int n  = blockIdx.z;

    float acc[8][8];
    #pragma unroll
    for (int c = 0; c < 8; c++)
        #pragma unroll
        for (int i = 0; i < 8; i++) acc[c][i] = 0.f;

    for (int cb = 0; cb < CIN; cb += CCH) {
        __syncthreads();
        // --- load input patch (zero-padded) ---
        for (int idx = tid; idx < CCH * PH * PH; idx += 256) {
            int ci = idx / (PH * PH);
            int rr = (idx / PH) % PH;
            int cc = idx % PH;
            int gy = y0 - PAD + rr;
            int gx = x0 - PAD + cc;
            float v = 0.f;
            if (gy >= 0 && gy < H && gx >= 0 && gx < W)
                v = in[((n * CIN + cb + ci) * H + gy) * W + gx];
            patch[(ci * PH + rr) * 48 + cc] = v;
        }
        // --- load weight chunk: wsm[co][ci][tap] ---
        for (int idx = tid; idx < WELE; idx += 256) {
            int co  = idx / (CCH * KK);
            int rem = idx % (CCH * KK);
            wsm[idx] = w[(co * CIN + cb) * KK + rem];
        }
        __syncthreads();

        #pragma unroll 1
        for (int ci = 0; ci < CCH; ci++) {
            const float* prow = &patch[ci * PH * 48];
            const float* wrow = &wsm[(cog * 8) * CCH * KK + ci * KK];
            #pragma unroll 1
            for (int ky = 0; ky < K; ky++) {
                #pragma unroll
                for (int kx = 0; kx < K; kx++) {
                    float v[8];
                    #pragma unroll
                    for (int i = 0; i < 8; i++)
                        v[i] = prow[(rbase + 2 * i + ky) * 48 + col + kx];
                    #pragma unroll
                    for (int c = 0; c < 8; c++) {
                        float wv = wrow[c * CCH * KK + ky * K + kx];
                        #pragma unroll
                        for (int i = 0; i < 8; i++)
                            acc[c][i] = fmaf(wv, v[i], acc[c][i]);
                    }
                }
            }
        }
    }

    // --- epilogue: bias + relu (+ LRN) ---
    #pragma unroll
    for (int c = 0; c < 8; c++) {
        float bb = bias[cog * 8 + c];
        #pragma unroll
        for (int i = 0; i < 8; i++)
            acc[c][i] = fmaxf(acc[c][i] + bb, 0.f);
    }

    if (DO_LRN) {
        __syncthreads();                 // everyone done reading patch
        float* edge = sm;                // reuse smem: [8 cog][32 pxt][8 i]
        #pragma unroll
        for (int i = 0; i < 8; i++)
            edge[(cog * 32 + pxt) * 8 + i] = acc[7][i];   // raw last channel of group
        __syncthreads();
        float prev[8];
        #pragma unroll
        for (int i = 0; i < 8; i++)
            prev[i] = (cog > 0) ? edge[((cog - 1) * 32 + pxt) * 8 + i] : 0.f;
        // descending c so acc[c-1] is still pre-LRN
        #pragma unroll
        for (int c = 7; c >= 0; c--) {
            #pragma unroll
            for (int i = 0; i < 8; i++) {
                float cur = acc[c][i];
                float pv  = (c > 0) ? acc[c - 1][i] : prev[i];
                float dnm = 1.f + 1e-5f * (pv * pv + cur * cur); // alpha*0.5 = 1e-5
                acc[c][i] = cur * powf(dnm, -0.75f);
            }
        }
    }

    // --- store ---
    #pragma unroll
    for (int c = 0; c < 8; c++) {
        int co = cog * 8 + c;
        #pragma unroll
        for (int i = 0; i < 8; i++) {
            int y = y0 + rbase + 2 * i;
            int x = x0 + col;
            if (y < H && x < W)
                out[((n * 64 + co) * H + y) * W + x] = acc[c][i];
        }
    }
}

// =====================================================================
// crops (4 shifted views) + 2x2/2 maxpool:  (2,64,128,128) -> (8,64,63,63)
// =====================================================================
__global__ void pool_kernel(const float* __restrict__ in, float* __restrict__ out)
{
    int id = blockIdx.x * 256 + threadIdx.x;
    if (id >= NQ * 64 * HP * HP) return;
    int j = id % HP;
    int i = (id / HP) % HP;
    int c = (id / (HP * HP)) % 64;
    int q = id / (64 * HP * HP);
    int n = q & 1;
    int crop = q >> 1;
    int dy = crop & 1;          // crop1 = h[1:, :-1]
    int dx = crop >> 1;         // crop2 = h[:-1, 1:]
    const float* base = in + ((size_t)(n * 64 + c) * H1) * W1;
    int y = dy + 2 * i, x = dx + 2 * j;
    float m = fmaxf(fmaxf(base[y * W1 + x],       base[y * W1 + x + 1]),
                    fmaxf(base[(y + 1) * W1 + x], base[(y + 1) * W1 + x + 1]));
    out[id] = m;
}

// =====================================================================
// conv5: 16x16 VALID, 64 -> 1024.  (8,64,63,63) -> (8,1024,48,48)
// Block: 64 co x 16x16 px tile; loop cin, weight tap-chunks of 64.
// =====================================================================
__global__ __launch_bounds__(256) void conv5_kernel(
    const float* __restrict__ in, const float* __restrict__ w,
    const float* __restrict__ bias, float* __restrict__ out)
{
    __shared__ float patch[31 * 48];
    __shared__ float wsm[64 * 64];

    const int tid   = threadIdx.x;
    const int cog   = tid >> 5;
    const int pxt   = tid & 31;
    const int col   = pxt & 15;
    const int rbase = pxt >> 4;
    const int bx = blockIdx.x, by = blockIdx.y;
    const int n   = blockIdx.z >> 4;
    const int cot = blockIdx.z & 15;

    float acc[8][8];
    #pragma unroll
    for (int c = 0; c < 8; c++)
        #pragma unroll
        for (int i = 0; i < 8; i++) acc[c][i] = 0.f;

    for (int ci = 0; ci < 64; ci++) {
        __syncthreads();
        // patch 31x31 (always in-bounds for VALID conv)
        for (int idx = tid; idx < 31 * 31; idx += 256) {
            int r = idx / 31, c2 = idx % 31;
            patch[r * 48 + c2] =
                in[((n * 64 + ci) * HP + by * 16 + r) * HP + bx * 16 + c2];
        }
        for (int tb = 0; tb < 256; tb += 64) {
            __syncthreads();
            for (int idx = tid; idx < 4096; idx += 256) {
                int coL = idx >> 6, t = idx & 63;
                wsm[idx] = w[((cot * 64 + coL) * 64 + ci) * 256 + tb + t];
            }
            __syncthreads();
            #pragma unroll 4
            for (int t = 0; t < 64; t++) {
                int tap = tb + t;
                int ky = tap >> 4, kx = tap & 15;
                float v[8];
                #pragma unroll
                for (int i = 0; i < 8; i++)
                    v[i] = patch[(rbase + 2 * i + ky) * 48 + col + kx];
                #pragma unroll
                for (int c = 0; c < 8; c++) {
                    float wv = wsm[(cog * 8 + c) * 64 + t];
                    #pragma unroll
                    for (int i = 0; i < 8; i++)
                        acc[c][i] = fmaf(wv, v[i], acc[c][i]);
                }
            }
        }
    }

    #pragma unroll
    for (int c = 0; c < 8; c++) {
        int co = cot * 64 + cog * 8 + c;
        float bb = bias[co];
        #pragma unroll
        for (int i = 0; i < 8; i++) {
            int y = by * 16 + rbase + 2 * i;
            int x = bx * 16 + col;
            out[((n * 1024 + co) * HO + y) * HO + x] = fmaxf(acc[c][i] + bb, 0.f);
        }
    }
}

// =====================================================================
// conv6: 1x1, 1024 -> 1024 == GEMM. Block: 64 co x 256 px, K-chunk 16.
// =====================================================================
__global__ __launch_bounds__(256) void conv6_kernel(
    const float* __restrict__ in, const float* __restrict__ w,
    const float* __restrict__ bias, float* __restrict__ out)
{
    __shared__ float Wsm[64 * 16];    // [co][kk]
    __shared__ float Bsm[16 * 256];   // [kk][px]

    const int tid = threadIdx.x;
    const int cog = tid >> 5;
    const int pxt = tid & 31;
    const int bx = blockIdx.x;        // px tile 0..8
    const int by = blockIdx.y;        // co tile 0..15
    const int q  = blockIdx.z;        // 0..7

    float acc[8][8];
    #pragma unroll
    for (int c = 0; c < 8; c++)
        #pragma unroll
        for (int i = 0; i < 8; i++) acc[c][i] = 0.f;

    for (int kb = 0; kb < 1024; kb += 16) {
        __syncthreads();
        for (int idx = tid; idx < 1024; idx += 256) {
            int co = idx >> 4, kk = idx & 15;
            Wsm[idx] = w[(by * 64 + co) * 1024 + kb + kk];
        }
        for (int idx = tid; idx < 4096; idx += 256) {
            int kk = idx >> 8, j = idx & 255;
            Bsm[idx] = in[(q * 1024 + kb + kk) * PX5 + bx * 256 + j];
        }
        __syncthreads();
        #pragma unroll 4
        for (int kk = 0; kk < 16; kk++) {
            float v[8];
            #pragma unroll
            for (int i = 0; i < 8; i++)
                v[i] = Bsm[kk * 256 + pxt + 32 * i];
            #pragma unroll
            for (int c = 0; c < 8; c++) {
                float wv = Wsm[(cog * 8 + c) * 16 + kk];
                #pragma unroll
                for (int i = 0; i < 8; i++)
                    acc[c][i] = fmaf(wv, v[i], acc[c][i]);
            }
        }
    }

    #pragma unroll
    for (int c = 0; c < 8; c++) {
        int co = by * 64 + cog * 8 + c;
        float bb = bias[co];
        #pragma unroll
        for (int i = 0; i < 8; i++) {
            int px = bx * 256 + pxt + 32 * i;
            out[(q * 1024 + co) * PX5 + px] = fmaxf(acc[c][i] + bb, 0.f);
        }
    }
}

// =====================================================================
// conv7 (1x1, 1024 -> 1) + sigmoid + interweave -> d_out (2,1,96,96)
// out[n, 2h+s, 2w+t] = y[n + 2s + 4t, h, w]
// =====================================================================
__global__ void conv7_kernel(const float* __restrict__ in,
                             const float* __restrict__ w7,
                             const float* __restrict__ b7,
                             float* __restrict__ out)
{
    int id = blockIdx.x * 256 + threadIdx.x;
    if (id >= NQ * PX5) return;
    int hw = id % PX5;
    int q  = id / PX5;
    float acc = b7[0];
    const float* p = in + (size_t)q * 1024 * PX5 + hw;
    #pragma unroll 4
    for (int ci = 0; ci < 1024; ci++)
        acc = fmaf(p[ci * PX5], w7[ci], acc);
    float s = 1.f / (1.f + expf(-acc));
    int h = hw / HO, wv = hw % HO;
    int n = q & 1, ss = (q >> 1) & 1, t = q >> 2;
    out[n * 96 * 96 + (2 * h + ss) * 96 + (2 * wv + t)] = s;
}

// =====================================================================
// launch
// =====================================================================
extern "C" void kernel_launch(void* const* d_in, const int* in_sizes, int n_in,
                              void* d_out, int out_size)
{
    const float* x  = (const float*)d_in[0];
    const float* w1 = (const float*)d_in[1];  const float* b1 = (const float*)d_in[2];
    const float* w2 = (const float*)d_in[3];  const float* b2 = (const float*)d_in[4];
    const float* w3 = (const float*)d_in[5];  const float* b3 = (const float*)d_in[6];
    const float* w4 = (const float*)d_in[7];  const float* b4 = (const float*)d_in[8];
    const float* w5 = (const float*)d_in[9];  const float* b5 = (const float*)d_in[10];
    const float* w6 = (const float*)d_in[11]; const float* b6 = (const float*)d_in[12];
    const float* w7 = (const float*)d_in[13]; const float* b7 = (const float*)d_in[14];

    void *pa, *pb, *pp, *pc, *pd, *pe, *pf;
    cudaGetSymbolAddress(&pa, g_a);
    cudaGetSymbolAddress(&pb, g_b);
    cudaGetSymbolAddress(&pp, g_p);
    cudaGetSymbolAddress(&pc, g_c);
    cudaGetSymbolAddress(&pd, g_d);
    cudaGetSymbolAddress(&pe, g_e);
    cudaGetSymbolAddress(&pf, g_f);

    // conv1: 7x7 SAME, 1->64, relu
    conv_tile<7, 1, 1, false><<<dim3(8, 8, NB), 256>>>(x, w1, b1, (float*)pa, H1, W1);
    // conv2: 5x5 SAME, 64->64, relu + LRN
    conv_tile<5, 64, 4, true><<<dim3(8, 8, NB), 256>>>((float*)pa, w2, b2, (float*)pb, H1, W1);
    // crops + maxpool
    pool_kernel<<<(NQ * 64 * HP * HP + 255) / 256, 256>>>((float*)pb, (float*)pp);
    // conv3: 3x3 SAME, relu
    conv_tile<3, 64, 8, false><<<dim3(4, 4, NQ), 256>>>((float*)pp, w3, b3, (float*)pc, HP, HP);
    // conv4: 3x3 SAME, relu + LRN
    conv_tile<3, 64, 8, true><<<dim3(4, 4, NQ), 256>>>((float*)pc, w4, b4, (float*)pd, HP, HP);
    // conv5: 16x16 VALID, 64->1024, relu
    conv5_kernel<<<dim3(3, 3, NQ * 16), 256>>>((float*)pd, w5, b5, (float*)pe);
    // conv6: 1x1, 1024->1024, relu
    conv6_kernel<<<dim3(9, 16, NQ), 256>>>((float*)pe, w6, b6, (float*)pf);
    // conv7 + sigmoid + interweave
    conv7_kernel<<<(NQ * PX5 + 255) / 256, 256>>>((float*)pf, w7, b7, (float*)d_out);
}

// round 10
// speedup vs baseline: 1.0565x; 1.0565x over previous
#include <cuda_runtime.h>
#include <math.h>

// ---------------- problem constants ----------------
#define NB   2        // batch
#define H1   128      // conv1/conv2 spatial
#define W1   128
#define HP   63       // pooled spatial
#define NQ   8        // 4 crops * batch 2
#define HO   48       // conv5 output spatial
#define PX5  2304     // 48*48

typedef unsigned long long u64;

// ---------------- f32x2 packed-FMA helpers (FFMA2; ptxas never auto-fuses) ----
__device__ __forceinline__ u64 pack2(float lo, float hi) {
    u64 r; asm("mov.b64 %0, {%1, %2};" : "=l"(r) : "f"(lo), "f"(hi)); return r;
}
__device__ __forceinline__ void unpack2(u64 v, float& lo, float& hi) {
    asm("mov.b64 {%0, %1}, %2;" : "=f"(lo), "=f"(hi) : "l"(v));
}
__device__ __forceinline__ void fma2(u64& d, u64 a, u64 b) {
    asm("fma.rn.f32x2 %0, %1, %2, %0;" : "+l"(d) : "l"(a), "l"(b));
}

// ---------------- intermediate buffers (device globals; no allocation) ----------------
__device__ float g_a[NB*64*H1*W1];     // conv1 out            (8 MB)
__device__ float g_b[NB*64*H1*W1];     // conv2+LRN out        (8 MB)
__device__ float g_p[NQ*64*HP*HP];     // crops+maxpool out    (8.1 MB)
__device__ float g_c[NQ*64*HP*HP];     // conv3 out
__device__ float g_d[NQ*64*HP*HP];     // conv4+LRN out
__device__ float g_e[NQ*1024*HO*HO];   // conv5 out            (75.5 MB)
__device__ float g_f[NQ*1024*HO*HO];   // conv6 out            (75.5 MB)

// =====================================================================
// Generic 64-output-channel direct conv, SAME padding, 16x16 spatial tile.
// Thread microtile: 8 co x 8 px. Accumulators packed as f32x2 pairs over px.
// Weights pre-duplicated {w,w} in smem -> single LDS.64 broadcast per FFMA2 group.
// Patch rows padded to stride 48 (48 mod 32 == 16 -> conflict-free).
// Optional fused LRN (size=2, alpha=2e-5, beta=0.75, k=1).
// =====================================================================
template<int K, int CIN, int CCH, bool DO_LRN>
__global__ __launch_bounds__(256, 2) void conv_tile(
    const float* __restrict__ in, const float* __restrict__ w,
    const float* __restrict__ bias, float* __restrict__ out,
    int H, int W)
{
    constexpr int KK    = K * K;
    constexpr int PAD   = K / 2;
    constexpr int PH    = 16 + K - 1;         // patch logical extent
    constexpr int WELE  = 64 * CCH * KK;
    __shared__ float patch[CCH * PH * 48];
    __shared__ u64   wsm2[WELE];

    const int tid   = threadIdx.x;
    const int cog   = tid >> 5;       // 0..7 (8 co per thread)
    const int pxt   = tid & 31;
    const int col   = pxt & 15;
    const int rbase = pxt >> 4;       // rows rbase + 2*i
    const int x0 = blockIdx.x * 16;
    const int y0 = blockIdx.y * 16;
    const int n  = blockIdx.z;

    u64 acc2[8][4];                   // [co][px-pair]  (pair = i=2j, i=2j+1)
    #pragma unroll
    for (int c = 0; c < 8; c++)
        #pragma unroll
        for (int j = 0; j < 4; j++) acc2[c][j] = 0ull;

    for (int cb = 0; cb < CIN; cb += CCH) {
        __syncthreads();
        // --- load input patch (zero-padded) ---
        for (int idx = tid; idx < CCH * PH * PH; idx += 256) {
            int ci = idx / (PH * PH);
            int rr = (idx / PH) % PH;
            int cc = idx % PH;
            int gy = y0 - PAD + rr;
            int gx = x0 - PAD + cc;
            float v = 0.f;
            if (gy >= 0 && gy < H && gx >= 0 && gx < W)
                v = in[((n * CIN + cb + ci) * H + gy) * W + gx];
            patch[(ci * PH + rr) * 48 + cc] = v;
        }
        // --- load weight chunk, duplicated {w,w}: wsm2[co][ci][tap] ---
        for (int idx = tid; idx < WELE; idx += 256) {
            int co  = idx / (CCH * KK);
            int rem = idx % (CCH * KK);
            float wv = w[(co * CIN + cb) * KK + rem];
            wsm2[idx] = pack2(wv, wv);
        }
        __syncthreads();

        #pragma unroll 1
        for (int ci = 0; ci < CCH; ci++) {
            const float* prow = &patch[ci * PH * 48];
            const u64* wrow = &wsm2[(cog * 8) * CCH * KK + ci * KK];
            #pragma unroll 1
            for (int ky = 0; ky < K; ky++) {
                #pragma unroll
                for (int kx = 0; kx < K; kx++) {
                    float v[8];
                    #pragma unroll
                    for (int i = 0; i < 8; i++)
                        v[i] = prow[(rbase + 2 * i + ky) * 48 + col + kx];
                    u64 vp[4];
                    #pragma unroll
                    for (int j = 0; j < 4; j++)
                        vp[j] = pack2(v[2 * j], v[2 * j + 1]);
                    #pragma unroll
                    for (int c = 0; c < 8; c++) {
                        u64 wp = wrow[c * CCH * KK + ky * K + kx];
                        #pragma unroll
                        for (int j = 0; j < 4; j++)
                            fma2(acc2[c][j], wp, vp[j]);
                    }
                }
            }
        }
    }

    // --- unpack -> epilogue: bias + relu (+ LRN) ---
    float acc[8][8];
    #pragma unroll
    for (int c = 0; c < 8; c++) {
        float bb = bias[cog * 8 + c];
        #pragma unroll
        for (int j = 0; j < 4; j++) {
            float lo, hi;
            unpack2(acc2[c][j], lo, hi);
            acc[c][2 * j]     = fmaxf(lo + bb, 0.f);
            acc[c][2 * j + 1] = fmaxf(hi + bb, 0.f);
        }
    }

    if (DO_LRN) {
        __syncthreads();                 // everyone done reading patch
        float* edge = patch;             // reuse smem: [8 cog][32 pxt][8 i]
        #pragma unroll
        for (int i = 0; i < 8; i++)
            edge[(cog * 32 + pxt) * 8 + i] = acc[7][i];   // raw last channel of group
        __syncthreads();
        float prev[8];
        #pragma unroll
        for (int i = 0; i < 8; i++)
            prev[i] = (cog > 0) ? edge[((cog - 1) * 32 + pxt) * 8 + i] : 0.f;
        // descending c so acc[c-1] is still pre-LRN
        #pragma unroll
        for (int c = 7; c >= 0; c--) {
            #pragma unroll
            for (int i = 0; i < 8; i++) {
                float cur = acc[c][i];
                float pv  = (c > 0) ? acc[c - 1][i] : prev[i];
                float dnm = 1.f + 1e-5f * (pv * pv + cur * cur); // alpha*0.5 = 1e-5
                acc[c][i] = cur * powf(dnm, -0.75f);
            }
        }
    }

    // --- store ---
    #pragma unroll
    for (int c = 0; c < 8; c++) {
        int co = cog * 8 + c;
        #pragma unroll
        for (int i = 0; i < 8; i++) {
            int y = y0 + rbase + 2 * i;
            int x = x0 + col;
            if (y < H && x < W)
                out[((n * 64 + co) * H + y) * W + x] = acc[c][i];
        }
    }
}

// =====================================================================
// crops (4 shifted views) + 2x2/2 maxpool:  (2,64,128,128) -> (8,64,63,63)
// =====================================================================
__global__ void pool_kernel(const float* __restrict__ in, float* __restrict__ out)
{
    int id = blockIdx.x * 256 + threadIdx.x;
    if (id >= NQ * 64 * HP * HP) return;
    int j = id % HP;
    int i = (id / HP) % HP;
    int c = (id / (HP * HP)) % 64;
    int q = id / (64 * HP * HP);
    int n = q & 1;
    int crop = q >> 1;
    int dy = crop & 1;          // crop1 = h[1:, :-1]
    int dx = crop >> 1;         // crop2 = h[:-1, 1:]
    const float* base = in + ((size_t)(n * 64 + c) * H1) * W1;
    int y = dy + 2 * i, x = dx + 2 * j;
    float m = fmaxf(fmaxf(base[y * W1 + x],       base[y * W1 + x + 1]),
                    fmaxf(base[(y + 1) * W1 + x], base[(y + 1) * W1 + x + 1]));
    out[id] = m;
}

// =====================================================================
// conv5: 16x16 VALID, 64 -> 1024.  (8,64,63,63) -> (8,1024,48,48)
// Block: 64 co x 16x16 px tile; loop cin, weight tap-chunks of 64.
// f32x2-packed accumulators; duplicated weights in smem (LDS.64 broadcast).
// =====================================================================
__global__ __launch_bounds__(256, 2) void conv5_kernel(
    const float* __restrict__ in, const float* __restrict__ w,
    const float* __restrict__ bias, float* __restrict__ out)
{
    __shared__ float patch[31 * 48];     // ~6 KB
    __shared__ u64   wsm2[64 * 64];      // 32 KB, entries {w,w}

    const int tid   = threadIdx.x;
    const int cog   = tid >> 5;
    const int pxt   = tid & 31;
    const int col   = pxt & 15;
    const int rbase = pxt >> 4;
    const int bx = blockIdx.x, by = blockIdx.y;
    const int n   = blockIdx.z >> 4;
    const int cot = blockIdx.z & 15;

    u64 acc2[8][4];
    #pragma unroll
    for (int c = 0; c < 8; c++)
        #pragma unroll
        for (int j = 0; j < 4; j++) acc2[c][j] = 0ull;

    for (int ci = 0; ci < 64; ci++) {
        __syncthreads();
        // patch 31x31 (always in-bounds for VALID conv)
        for (int idx = tid; idx < 31 * 31; idx += 256) {
            int r = idx / 31, c2 = idx % 31;
            patch[r * 48 + c2] =
                in[((n * 64 + ci) * HP + by * 16 + r) * HP + bx * 16 + c2];
        }
        for (int tb = 0; tb < 256; tb += 64) {
            __syncthreads();
            for (int idx = tid; idx < 4096; idx += 256) {
                int coL = idx >> 6, t = idx & 63;
                float wv = w[((cot * 64 + coL) * 64 + ci) * 256 + tb + t];
                wsm2[idx] = pack2(wv, wv);
            }
            __syncthreads();
            #pragma unroll 4
            for (int t = 0; t < 64; t++) {
                int tap = tb + t;
                int ky = tap >> 4, kx = tap & 15;
                float v[8];
                #pragma unroll
                for (int i = 0; i < 8; i++)
                    v[i] = patch[(rbase + 2 * i + ky) * 48 + col + kx];
                u64 vp[4];
                #pragma unroll
                for (int j = 0; j < 4; j++)
                    vp[j] = pack2(v[2 * j], v[2 * j + 1]);
                #pragma unroll
                for (int c = 0; c < 8; c++) {
                    u64 wp = wsm2[(cog * 8 + c) * 64 + t];
                    #pragma unroll
                    for (int j = 0; j < 4; j++)
                        fma2(acc2[c][j], wp, vp[j]);
                }
            }
        }
    }

    #pragma unroll
    for (int c = 0; c < 8; c++) {
        int co = cot * 64 + cog * 8 + c;
        float bb = bias[co];
        #pragma unroll
        for (int j = 0; j < 4; j++) {
            float lo, hi;
            unpack2(acc2[c][j], lo, hi);
            int x  = bx * 16 + col;
            int y0 = by * 16 + rbase + 4 * j;       // i=2j   -> row rbase+4j
            int y1 = y0 + 2;                        // i=2j+1 -> row rbase+4j+2
            out[((n * 1024 + co) * HO + y0) * HO + x] = fmaxf(lo + bb, 0.f);
            out[((n * 1024 + co) * HO + y1) * HO + x] = fmaxf(hi + bb, 0.f);
        }
    }
}

// =====================================================================
// conv6: 1x1, 1024 -> 1024 == GEMM. Block: 64 co x 256 px, K-chunk 16.
// f32x2-packed accumulators; duplicated weights (LDS.64 broadcast).
// =====================================================================
__global__ __launch_bounds__(256, 2) void conv6_kernel(
    const float* __restrict__ in, const float* __restrict__ w,
    const float* __restrict__ bias, float* __restrict__ out)
{
    __shared__ u64   Wsm2[64 * 16];   // [co][kk], {w,w}   8 KB
    __shared__ float Bsm[16 * 256];   // [kk][px]         16 KB

    const int tid = threadIdx.x;
    const int cog = tid >> 5;
    const int pxt = tid & 31;
    const int bx = blockIdx.x;        // px tile 0..8
    const int by = blockIdx.y;        // co tile 0..15
    const int q  = blockIdx.z;        // 0..7

    u64 acc2[8][4];
    #pragma unroll
    for (int c = 0; c < 8; c++)
        #pragma unroll
        for (int j = 0; j < 4; j++) acc2[c][j] = 0ull;

    for (int kb = 0; kb < 1024; kb += 16) {
        __syncthreads();
        for (int idx = tid; idx < 1024; idx += 256) {
            int co = idx >> 4, kk = idx & 15;
            float wv = w[(by * 64 + co) * 1024 + kb + kk];
            Wsm2[idx] = pack2(wv, wv);
        }
        for (int idx = tid; idx < 4096; idx += 256) {
            int kk = idx >> 8, j = idx & 255;
            Bsm[idx] = in[(q * 1024 + kb + kk) * PX5 + bx * 256 + j];
        }
        __syncthreads();
        #pragma unroll 4
        for (int kk = 0; kk < 16; kk++) {
            float v[8];
            #pragma unroll
            for (int i = 0; i < 8; i++)
                v[i] = Bsm[kk * 256 + pxt + 32 * i];
            u64 vp[4];
            #pragma unroll
            for (int j = 0; j < 4; j++)
                vp[j] = pack2(v[2 * j], v[2 * j + 1]);
            #pragma unroll
            for (int c = 0; c < 8; c++) {
                u64 wp = Wsm2[(cog * 8 + c) * 16 + kk];
                #pragma unroll
                for (int j = 0; j < 4; j++)
                    fma2(acc2[c][j], wp, vp[j]);
            }
        }
    }

    #pragma unroll
    for (int c = 0; c < 8; c++) {
        int co = by * 64 + cog * 8 + c;
        float bb = bias[co];
        #pragma unroll
        for (int j = 0; j < 4; j++) {
            float lo, hi;
            unpack2(acc2[c][j], lo, hi);
            int px0 = bx * 256 + pxt + 64 * j;       // i=2j
            int px1 = px0 + 32;                      // i=2j+1
            out[(q * 1024 + co) * PX5 + px0] = fmaxf(lo + bb, 0.f);
            out[(q * 1024 + co) * PX5 + px1] = fmaxf(hi + bb, 0.f);
        }
    }
}

// =====================================================================
// conv7 (1x1, 1024 -> 1) + sigmoid + interweave -> d_out (2,1,96,96)
// out[n, 2h+s, 2w+t] = y[n + 2s + 4t, h, w]
// =====================================================================
__global__ void conv7_kernel(const float* __restrict__ in,
                             const float* __restrict__ w7,
                             const float* __restrict__ b7,
                             float* __restrict__ out)
{
    int id = blockIdx.x * 256 + threadIdx.x;
    if (id >= NQ * PX5) return;
    int hw = id % PX5;
    int q  = id / PX5;
    float acc = b7[0];
    const float* p = in + (size_t)q * 1024 * PX5 + hw;
    #pragma unroll 8
    for (int ci = 0; ci < 1024; ci++)
        acc = fmaf(p[ci * PX5], w7[ci], acc);
    float s = 1.f / (1.f + expf(-acc));
    int h = hw / HO, wv = hw % HO;
    int n = q & 1, ss = (q >> 1) & 1, t = q >> 2;
    out[n * 96 * 96 + (2 * h + ss) * 96 + (2 * wv + t)] = s;
}

// =====================================================================
// launch
// =====================================================================
extern "C" void kernel_launch(void* const* d_in, const int* in_sizes, int n_in,
                              void* d_out, int out_size)
{
    const float* x  = (const float*)d_in[0];
    const float* w1 = (const float*)d_in[1];  const float* b1 = (const float*)d_in[2];
    const float* w2 = (const float*)d_in[3];  const float* b2 = (const float*)d_in[4];
    const float* w3 = (const float*)d_in[5];  const float* b3 = (const float*)d_in[6];
    const float* w4 = (const float*)d_in[7];  const float* b4 = (const float*)d_in[8];
    const float* w5 = (const float*)d_in[9];  const float* b5 = (const float*)d_in[10];
    const float* w6 = (const float*)d_in[11]; const float* b6 = (const float*)d_in[12];
    const float* w7 = (const float*)d_in[13]; const float* b7 = (const float*)d_in[14];

    void *pa, *pb, *pp, *pc, *pd, *pe, *pf;
    cudaGetSymbolAddress(&pa, g_a);
    cudaGetSymbolAddress(&pb, g_b);
    cudaGetSymbolAddress(&pp, g_p);
    cudaGetSymbolAddress(&pc, g_c);
    cudaGetSymbolAddress(&pd, g_d);
    cudaGetSymbolAddress(&pe, g_e);
    cudaGetSymbolAddress(&pf, g_f);

    // conv1: 7x7 SAME, 1->64, relu
    conv_tile<7, 1, 1, false><<<dim3(8, 8, NB), 256>>>(x, w1, b1, (float*)pa, H1, W1);
    // conv2: 5x5 SAME, 64->64, relu + LRN
    conv_tile<5, 64, 4, true><<<dim3(8, 8, NB), 256>>>((float*)pa, w2, b2, (float*)pb, H1, W1);
    // crops + maxpool
    pool_kernel<<<(NQ * 64 * HP * HP + 255) / 256, 256>>>((float*)pb, (float*)pp);
    // conv3: 3x3 SAME, relu
    conv_tile<3, 64, 8, false><<<dim3(4, 4, NQ), 256>>>((float*)pp, w3, b3, (float*)pc, HP, HP);
    // conv4: 3x3 SAME, relu + LRN
    conv_tile<3, 64, 8, true><<<dim3(4, 4, NQ), 256>>>((float*)pc, w4, b4, (float*)pd, HP, HP);
    // conv5: 16x16 VALID, 64->1024, relu
    conv5_kernel<<<dim3(3, 3, NQ * 16), 256>>>((float*)pd, w5, b5, (float*)pe);
    // conv6: 1x1, 1024->1024, relu
    conv6_kernel<<<dim3(9, 16, NQ), 256>>>((float*)pe, w6, b6, (float*)pf);
    // conv7 + sigmoid + interweave
    conv7_kernel<<<(NQ * PX5 + 255) / 256, 256>>>((float*)pf, w7, b7, (float*)d_out);
}

// round 13
// speedup vs baseline: 2.4587x; 2.3272x over previous
#include <cuda_runtime.h>
#include <cuda_bf16.h>
#include <math.h>
#include <stdint.h>

// ---------------- problem constants ----------------
#define NB   2
#define H1   128
#define W1   128
#define HP   63
#define NQ   8
#define HO   48
#define PX5  2304

typedef unsigned long long u64;

// ---------------- f32x2 helpers ----------------
__device__ __forceinline__ u64 pack2(float lo, float hi) {
    u64 r; asm("mov.b64 %0, {%1, %2};" : "=l"(r) : "f"(lo), "f"(hi)); return r;
}
__device__ __forceinline__ void unpack2(u64 v, float& lo, float& hi) {
    asm("mov.b64 {%0, %1}, %2;" : "=f"(lo), "=f"(hi) : "l"(v));
}
__device__ __forceinline__ void fma2(u64& d, u64 a, u64 b) {
    asm("fma.rn.f32x2 %0, %1, %2, %0;" : "+l"(d) : "l"(a), "l"(b));
}

// ---------------- intermediate buffers ----------------
__device__ float g_a[NB*64*H1*W1];
__device__ float g_b[NB*64*H1*W1];
__device__ float g_p[NQ*64*HP*HP];
__device__ float g_c[NQ*64*HP*HP];
__device__ float g_d[NQ*64*HP*HP];
__device__ float g_e[NQ*1024*HO*HO];
__device__ float g_f[NQ*1024*HO*HO];

// bf16-split staging for conv5 MMA (uint4 for 16B alignment)
__device__ uint4 g_wh[8*256*1024];   // [cotile][tap] 16KB swizzled tiles [128co x 64ci], hi
__device__ uint4 g_wl[8*256*1024];   // lo
__device__ uint4 g_th[258048];       // [q][y63][x64][ci64] bf16 hi
__device__ uint4 g_tl[258048];       // lo

// ---------------- smem addr helper ----------------
__device__ __forceinline__ uint32_t s2u(const void* p) {
    uint32_t a;
    asm("{ .reg .u64 t; cvta.to.shared.u64 t, %1; cvt.u32.u64 %0, t; }" : "=r"(a) : "l"(p));
    return a;
}

// ---------------- portable tensor-core primitives (sm_80+, OK on base sm_103) ----
#define LDSM4(r, addr) \
    asm volatile("ldmatrix.sync.aligned.m8n8.x4.shared.b16 {%0,%1,%2,%3}, [%4];" \
        : "=r"((r)[0]), "=r"((r)[1]), "=r"((r)[2]), "=r"((r)[3]) : "r"(addr))

#define LDSM2(r, addr) \
    asm volatile("ldmatrix.sync.aligned.m8n8.x2.shared.b16 {%0,%1}, [%2];" \
        : "=r"((r)[0]), "=r"((r)[1]) : "r"(addr))

#define MMA16816(c, a, b) \
    asm volatile("mma.sync.aligned.m16n8k16.row.col.f32.bf16.bf16.f32 " \
        "{%0,%1,%2,%3}, {%4,%5,%6,%7}, {%8,%9}, {%0,%1,%2,%3};" \
        : "+f"((c)[0]), "+f"((c)[1]), "+f"((c)[2]), "+f"((c)[3]) \
        : "r"((a)[0]), "r"((a)[1]), "r"((a)[2]), "r"((a)[3]), \
          "r"((b)[0]), "r"((b)[1]))

__device__ __forceinline__ uint32_t swz(uint32_t x) { return x ^ ((x >> 3) & 0x70); }

// =====================================================================
// conv_tile (conv1-4), unchanged (fp32 f32x2)
// =====================================================================
template<int K, int CIN, int CCH, bool DO_LRN>
__global__ __launch_bounds__(256, 2) void conv_tile(
    const float* __restrict__ in, const float* __restrict__ w,
    const float* __restrict__ bias, float* __restrict__ out,
    int H, int W)
{
    constexpr int KK    = K * K;
    constexpr int PAD   = K / 2;
    constexpr int PH    = 16 + K - 1;
    constexpr int WELE  = 64 * CCH * KK;
    __shared__ float patch[CCH * PH * 48];
    __shared__ u64   wsm2[WELE];

    const int tid   = threadIdx.x;
    const int cog   = tid >> 5;
    const int pxt   = tid & 31;
    const int col   = pxt & 15;
    const int rbase = pxt >> 4;
    const int x0 = blockIdx.x * 16;
    const int y0 = blockIdx.y * 16;
    const int n  = blockIdx.z;

    u64 acc2[8][4];
    #pragma unroll
    for (int c = 0; c < 8; c++)
        #pragma unroll
        for (int j = 0; j < 4; j++) acc2[c][j] = 0ull;

    for (int cb = 0; cb < CIN; cb += CCH) {
        __syncthreads();
        for (int idx = tid; idx < CCH * PH * PH; idx += 256) {
            int ci = idx / (PH * PH);
            int rr = (idx / PH) % PH;
            int cc = idx % PH;
            int gy = y0 - PAD + rr;
            int gx = x0 - PAD + cc;
            float v = 0.f;
            if (gy >= 0 && gy < H && gx >= 0 && gx < W)
                v = in[((n * CIN + cb + ci) * H + gy) * W + gx];
            patch[(ci * PH + rr) * 48 + cc] = v;
        }
        for (int idx = tid; idx < WELE; idx += 256) {
            int co  = idx / (CCH * KK);
            int rem = idx % (CCH * KK);
            float wv = w[(co * CIN + cb) * KK + rem];
            wsm2[idx] = pack2(wv, wv);
        }
        __syncthreads();

        #pragma unroll 1
        for (int ci = 0; ci < CCH; ci++) {
            const float* prow = &patch[ci * PH * 48];
            const u64* wrow = &wsm2[(cog * 8) * CCH * KK + ci * KK];
            #pragma unroll 1
            for (int ky = 0; ky < K; ky++) {
                #pragma unroll
                for (int kx = 0; kx < K; kx++) {
                    float v[8];
                    #pragma unroll
                    for (int i = 0; i < 8; i++)
                        v[i] = prow[(rbase + 2 * i + ky) * 48 + col + kx];
                    u64 vp[4];
                    #pragma unroll
                    for (int j = 0; j < 4; j++)
                        vp[j] = pack2(v[2 * j], v[2 * j + 1]);
                    #pragma unroll
                    for (int c = 0; c < 8; c++) {
                        u64 wp = wrow[c * CCH * KK + ky * K + kx];
                        #pragma unroll
                        for (int j = 0; j < 4; j++)
                            fma2(acc2[c][j], wp, vp[j]);
                    }
                }
            }
        }
    }

    float acc[8][8];
    #pragma unroll
    for (int c = 0; c < 8; c++) {
        float bb = bias[cog * 8 + c];
        #pragma unroll
        for (int j = 0; j < 4; j++) {
            float lo, hi;
            unpack2(acc2[c][j], lo, hi);
            acc[c][2 * j]     = fmaxf(lo + bb, 0.f);
            acc[c][2 * j + 1] = fmaxf(hi + bb, 0.f);
        }
    }

    if (DO_LRN) {
        __syncthreads();
        float* edge = patch;
        #pragma unroll
        for (int i = 0; i < 8; i++)
            edge[(cog * 32 + pxt) * 8 + i] = acc[7][i];
        __syncthreads();
        float prev[8];
        #pragma unroll
        for (int i = 0; i < 8; i++)
            prev[i] = (cog > 0) ? edge[((cog - 1) * 32 + pxt) * 8 + i] : 0.f;
        #pragma unroll
        for (int c = 7; c >= 0; c--) {
            #pragma unroll
            for (int i = 0; i < 8; i++) {
                float cur = acc[c][i];
                float pv  = (c > 0) ? acc[c - 1][i] : prev[i];
                float dnm = 1.f + 1e-5f * (pv * pv + cur * cur);
                acc[c][i] = cur * powf(dnm, -0.75f);
            }
        }
    }

    #pragma unroll
    for (int c = 0; c < 8; c++) {
        int co = cog * 8 + c;
        #pragma unroll
        for (int i = 0; i < 8; i++) {
            int y = y0 + rbase + 2 * i;
            int x = x0 + col;
            if (y < H && x < W)
                out[((n * 64 + co) * H + y) * W + x] = acc[c][i];
        }
    }
}

// =====================================================================
// crops + maxpool
// =====================================================================
__global__ void pool_kernel(const float* __restrict__ in, float* __restrict__ out)
{
    int id = blockIdx.x * 256 + threadIdx.x;
    if (id >= NQ * 64 * HP * HP) return;
    int j = id % HP;
    int i = (id / HP) % HP;
    int c = (id / (HP * HP)) % 64;
    int q = id / (64 * HP * HP);
    int n = q & 1;
    int crop = q >> 1;
    int dy = crop & 1;
    int dx = crop >> 1;
    const float* base = in + ((size_t)(n * 64 + c) * H1) * W1;
    int y = dy + 2 * i, x = dx + 2 * j;
    float m = fmaxf(fmaxf(base[y * W1 + x],       base[y * W1 + x + 1]),
                    fmaxf(base[(y + 1) * W1 + x], base[(y + 1) * W1 + x + 1]));
    out[id] = m;
}

// =====================================================================
// transform: conv4 output -> [q][y63][x64][ci64] bf16 hi/lo (x=63 zero pad)
// =====================================================================
__global__ void tr_input_kernel(const float* __restrict__ src)
{
    int id = blockIdx.x * 256 + threadIdx.x;
    if (id >= NQ * 63 * 64 * 64) return;
    int ci = id & 63;
    int x  = (id >> 6) & 63;
    int qy = id >> 12;            // q*63 + y
    int y  = qy % 63;
    int q  = qy / 63;
    float v = 0.f;
    if (x < 63) v = src[((q * 64 + ci) * HP + y) * HP + x];
    __nv_bfloat16 h = __float2bfloat16(v);
    __nv_bfloat16 l = __float2bfloat16(v - __bfloat162float(h));
    ((__nv_bfloat16*)g_th)[id] = h;
    ((__nv_bfloat16*)g_tl)[id] = l;
}

// =====================================================================
// transform: w5 -> swizzled tiles [cotile][tap][128co x 64ci] hi/lo
// byte offset within tile: swz(co*128 + ci*2)  ==  chunk c^(co&7) -> ldmatrix-ready
// =====================================================================
__global__ void tr_w5_kernel(const float* __restrict__ w5)
{
    int id = blockIdx.x * 256 + threadIdx.x;
    if (id >= 1024 * 256 * 64) return;
    int ci  = id & 63;
    int tap = (id >> 6) & 255;
    int co  = id >> 14;
    float v = w5[(co * 64 + ci) * 256 + tap];
    __nv_bfloat16 h = __float2bfloat16(v);
    __nv_bfloat16 l = __float2bfloat16(v - __bfloat162float(h));
    int cotile = co >> 7, co128 = co & 127;
    uint32_t off = swz((uint32_t)(co128 * 128 + ci * 2));
    size_t dst = (size_t)(cotile * 256 + tap) * 16384 + off;
    *(__nv_bfloat16*)((char*)g_wh + dst) = h;
    *(__nv_bfloat16*)((char*)g_wl + dst) = l;
}

// =====================================================================
// conv5 via mma.sync (bf16 3-pass split: AhBh + AhBl + AlBh, fp32 accum).
// Block: 512 thr = 16 warps. Tile: 128 co x 4 rows x 48 px. Grid (12,8,8).
// Warp (cog,h): co16 = cog*16, rows {2h, 2h+1}, 48 px -> acc[2][6][4].
// A: per-tap coop load of pre-swizzled 32KB (hi+lo), ldmatrix.x4 frags.
// B: row slabs [x64][ci64] hi/lo loaded per ky with XOR swizzle; non-trans
//    ldmatrix.x2 over x-rows yields the col-major k x n fragment directly.
// =====================================================================
#define C5_SLAB   32768                 // slabs start after A (hi 16K + lo 16K)
#define C5_SMEM   (32768 + 65536)       // 96 KB

__global__ __launch_bounds__(512, 1) void conv5_mma(
    const float* __restrict__ bias, float* __restrict__ out)
{
    extern __shared__ char sm[];
    char* As = sm;                      // A hi @0, A lo @16384
    char* Slab = sm + C5_SLAB;          // 8 slabs x 8KB: s = yy*2 + sel

    const int tid  = threadIdx.x;
    const int lane = tid & 31;
    const int wid  = tid >> 5;          // 0..15
    const int cog  = wid >> 1;          // 0..7
    const int h    = wid & 1;           // rows {2h, 2h+1}
    const int yblk = blockIdx.x, cotile = blockIdx.y, q = blockIdx.z;
    const int Y0 = yblk * 4;
    const int m  = cog * 16;

    const uint32_t sA    = s2u(As);
    const uint32_t sSlab = s2u(Slab);

    // ldmatrix lane precomputes
    const int ar  = lane & 15;          // A row-in-16
    const int acp = lane >> 4;          // A chunk parity (x4 upper mats)
    const int bxl = lane & 7;           // B x-row offset (x2 uses lanes 0-15)
    const int bp  = (lane >> 3) & 1;    // B chunk parity

    float acc[2][6][4];
    #pragma unroll
    for (int r = 0; r < 2; r++)
        #pragma unroll
        for (int nt = 0; nt < 6; nt++)
            #pragma unroll
            for (int j = 0; j < 4; j++) acc[r][nt][j] = 0.f;

    for (int ky = 0; ky < 16; ky++) {
        __syncthreads();
        // load 8 slabs (yy 0..3 x hi/lo), applying XOR-16B swizzle
        for (int i = tid; i < 4096; i += 512) {
            int s = i >> 9;
            int j = i & 511;
            int x = j >> 3, c = j & 7;
            int yy = s >> 1, sel = s & 1;
            const uint4* src = (sel ? g_tl : g_th) + (size_t)(q * 63 + Y0 + ky + yy) * 512;
            ((uint4*)Slab)[s * 512 + x * 8 + (c ^ (x & 7))] = src[j];
        }

        for (int kx = 0; kx < 16; kx++) {
            const int t = ky * 16 + kx;
            __syncthreads();
            // coop load A tile (32KB: hi+lo), already swizzled in gmem
            {
                const uint4* sh = g_wh + (size_t)(cotile * 256 + t) * 1024;
                const uint4* sl = g_wl + (size_t)(cotile * 256 + t) * 1024;
                ((uint4*)As)[tid]                 = sh[tid];
                ((uint4*)As)[tid + 512]           = sh[tid + 512];
                ((uint4*)(As + 16384))[tid]       = sl[tid];
                ((uint4*)(As + 16384))[tid + 512] = sl[tid + 512];
            }
            __syncthreads();

            // A fragments: 4 k-steps x (hi, lo)
            uint32_t Ah[4][4], Al[4][4];
            {
                const uint32_t rowoff = sA + (uint32_t)(m + ar) * 128;
                #pragma unroll
                for (int k = 0; k < 4; k++) {
                    uint32_t ch = (uint32_t)(((2 * k + acp) ^ (ar & 7)) * 16);
                    LDSM4(Ah[k], rowoff + ch);
                    LDSM4(Al[k], rowoff + ch + 16384);
                }
            }

            // B fragments + MMAs
            const int xk = kx + bxl;
            const uint32_t xoff = (uint32_t)xk * 128;
            #pragma unroll
            for (int rr = 0; rr < 2; rr++) {
                const int row = 2 * h + rr;
                const uint32_t hbase = sSlab + (uint32_t)(row * 2 + 0) * 8192 + xoff;
                const uint32_t lbase = sSlab + (uint32_t)(row * 2 + 1) * 8192 + xoff;
                #pragma unroll
                for (int k = 0; k < 4; k++) {
                    const uint32_t ch = (uint32_t)(((2 * k + bp) ^ (xk & 7)) * 16);
                    #pragma unroll
                    for (int nt = 0; nt < 6; nt++) {
                        const uint32_t off = (uint32_t)(nt * 1024) + ch;
                        uint32_t bh[2], bl[2];
                        LDSM2(bh, hbase + off);
                        MMA16816(acc[rr][nt], Ah[k], bh);
                        MMA16816(acc[rr][nt], Al[k], bh);
                        LDSM2(bl, lbase + off);
                        MMA16816(acc[rr][nt], Ah[k], bl);
                    }
                }
            }
        }
    }

    // epilogue: bias + relu, direct store
    {
        const int co_l = lane >> 2;
        const int col2 = 2 * (lane & 3);
        const int co0 = cotile * 128 + m + co_l;
        const int co1 = co0 + 8;
        const float b0 = bias[co0];
        const float b1 = bias[co1];
        #pragma unroll
        for (int rr = 0; rr < 2; rr++) {
            const int y = Y0 + 2 * h + rr;
            float* o0 = out + ((size_t)(q * 1024 + co0) * HO + y) * HO;
            float* o1 = out + ((size_t)(q * 1024 + co1) * HO + y) * HO;
            #pragma unroll
            for (int nt = 0; nt < 6; nt++) {
                const int px = nt * 8 + col2;
                o0[px]     = fmaxf(acc[rr][nt][0] + b0, 0.f);
                o0[px + 1] = fmaxf(acc[rr][nt][1] + b0, 0.f);
                o1[px]     = fmaxf(acc[rr][nt][2] + b1, 0.f);
                o1[px + 1] = fmaxf(acc[rr][nt][3] + b1, 0.f);
            }
        }
    }
}

// =====================================================================
// conv6: 1x1 GEMM, fp32 (unchanged)
// =====================================================================
__global__ __launch_bounds__(256, 2) void conv6_kernel(
    const float* __restrict__ in, const float* __restrict__ w,
    const float* __restrict__ bias, float* __restrict__ out)
{
    __shared__ u64   Wsm2[64 * 16];
    __shared__ float Bsm[16 * 256];

    const int tid = threadIdx.x;
    const int cog = tid >> 5;
    const int pxt = tid & 31;
    const int bx = blockIdx.x;
    const int by = blockIdx.y;
    const int q  = blockIdx.z;

    u64 acc2[8][4];
    #pragma unroll
    for (int c = 0; c < 8; c++)
        #pragma unroll
        for (int j = 0; j < 4; j++) acc2[c][j] = 0ull;

    for (int kb = 0; kb < 1024; kb += 16) {
        __syncthreads();
        for (int idx = tid; idx < 1024; idx += 256) {
            int co = idx >> 4, kk = idx & 15;
            float wv = w[(by * 64 + co) * 1024 + kb + kk];
            Wsm2[idx] = pack2(wv, wv);
        }
        for (int idx = tid; idx < 4096; idx += 256) {
            int kk = idx >> 8, j = idx & 255;
            Bsm[idx] = in[(q * 1024 + kb + kk) * PX5 + bx * 256 + j];
        }
        __syncthreads();
        #pragma unroll 4
        for (int kk = 0; kk < 16; kk++) {
            float v[8];
            #pragma unroll
            for (int i = 0; i < 8; i++)
                v[i] = Bsm[kk * 256 + pxt + 32 * i];
            u64 vp[4];
            #pragma unroll
            for (int j = 0; j < 4; j++)
                vp[j] = pack2(v[2 * j], v[2 * j + 1]);
            #pragma unroll
            for (int c = 0; c < 8; c++) {
                u64 wp = Wsm2[(cog * 8 + c) * 16 + kk];
                #pragma unroll
                for (int j = 0; j < 4; j++)
                    fma2(acc2[c][j], wp, vp[j]);
            }
        }
    }

    #pragma unroll
    for (int c = 0; c < 8; c++) {
        int co = by * 64 + cog * 8 + c;
        float bb = bias[co];
        #pragma unroll
        for (int j = 0; j < 4; j++) {
            float lo, hi;
            unpack2(acc2[c][j], lo, hi);
            int px0 = bx * 256 + pxt + 64 * j;
            int px1 = px0 + 32;
            out[(q * 1024 + co) * PX5 + px0] = fmaxf(lo + bb, 0.f);
            out[(q * 1024 + co) * PX5 + px1] = fmaxf(hi + bb, 0.f);
        }
    }
}

// =====================================================================
// conv7 + sigmoid + interweave
// =====================================================================
__global__ void conv7_kernel(const float* __restrict__ in,
                             const float* __restrict__ w7,
                             const float* __restrict__ b7,
                             float* __restrict__ out)
{
    int id = blockIdx.x * 256 + threadIdx.x;
    if (id >= NQ * PX5) return;
    int hw = id % PX5;
    int q  = id / PX5;
    float acc = b7[0];
    const float* p = in + (size_t)q * 1024 * PX5 + hw;
    #pragma unroll 8
    for (int ci = 0; ci < 1024; ci++)
        acc = fmaf(p[ci * PX5], w7[ci], acc);
    float s = 1.f / (1.f + expf(-acc));
    int h = hw / HO, wv = hw % HO;
    int n = q & 1, ss = (q >> 1) & 1, t = q >> 2;
    out[n * 96 * 96 + (2 * h + ss) * 96 + (2 * wv + t)] = s;
}

// =====================================================================
// launch
// =====================================================================
extern "C" void kernel_launch(void* const* d_in, const int* in_sizes, int n_in,
                              void* d_out, int out_size)
{
    const float* x  = (const float*)d_in[0];
    const float* w1 = (const float*)d_in[1];  const float* b1 = (const float*)d_in[2];
    const float* w2 = (const float*)d_in[3];  const float* b2 = (const float*)d_in[4];
    const float* w3 = (const float*)d_in[5];  const float* b3 = (const float*)d_in[6];
    const float* w4 = (const float*)d_in[7];  const float* b4 = (const float*)d_in[8];
    const float* w5 = (const float*)d_in[9];  const float* b5 = (const float*)d_in[10];
    const float* w6 = (const float*)d_in[11]; const float* b6 = (const float*)d_in[12];
    const float* w7 = (const float*)d_in[13]; const float* b7 = (const float*)d_in[14];

    void *pa, *pb, *pp, *pc, *pd, *pe, *pf;
    cudaGetSymbolAddress(&pa, g_a);
    cudaGetSymbolAddress(&pb, g_b);
    cudaGetSymbolAddress(&pp, g_p);
    cudaGetSymbolAddress(&pc, g_c);
    cudaGetSymbolAddress(&pd, g_d);
    cudaGetSymbolAddress(&pe, g_e);
    cudaGetSymbolAddress(&pf, g_f);

    cudaFuncSetAttribute(conv5_mma, cudaFuncAttributeMaxDynamicSharedMemorySize, C5_SMEM);

    // weight transform for conv5 (independent; runs up front)
    tr_w5_kernel<<<(1024 * 256 * 64 + 255) / 256, 256>>>(w5);

    conv_tile<7, 1, 1, false><<<dim3(8, 8, NB), 256>>>(x, w1, b1, (float*)pa, H1, W1);
    conv_tile<5, 64, 4, true><<<dim3(8, 8, NB), 256>>>((float*)pa, w2, b2, (float*)pb, H1, W1);
    pool_kernel<<<(NQ * 64 * HP * HP + 255) / 256, 256>>>((float*)pb, (float*)pp);
    conv_tile<3, 64, 8, false><<<dim3(4, 4, NQ), 256>>>((float*)pp, w3, b3, (float*)pc, HP, HP);
    conv_tile<3, 64, 8, true><<<dim3(4, 4, NQ), 256>>>((float*)pc, w4, b4, (float*)pd, HP, HP);

    // input transform + tensor-core conv5
    tr_input_kernel<<<(NQ * 63 * 64 * 64 + 255) / 256, 256>>>((float*)pd);
    conv5_mma<<<dim3(12, 8, NQ), 512, C5_SMEM>>>(b5, (float*)pe);

    conv6_kernel<<<dim3(9, 16, NQ), 256>>>((float*)pe, w6, b6, (float*)pf);
    conv7_kernel<<<(NQ * PX5 + 255) / 256, 256>>>((float*)pf, w7, b7, (float*)d_out);
}

// round 14
// speedup vs baseline: 3.3561x; 1.3650x over previous
#include <cuda_runtime.h>
#include <cuda_bf16.h>
#include <math.h>
#include <stdint.h>

// ---------------- problem constants ----------------
#define NB   2
#define H1   128
#define W1   128
#define HP   63
#define NQ   8
#define HO   48
#define PX5  2304

typedef unsigned long long u64;

// ---------------- f32x2 helpers ----------------
__device__ __forceinline__ u64 pack2(float lo, float hi) {
    u64 r; asm("mov.b64 %0, {%1, %2};" : "=l"(r) : "f"(lo), "f"(hi)); return r;
}
__device__ __forceinline__ void unpack2(u64 v, float& lo, float& hi) {
    asm("mov.b64 {%0, %1}, %2;" : "=f"(lo), "=f"(hi) : "l"(v));
}
__device__ __forceinline__ void fma2(u64& d, u64 a, u64 b) {
    asm("fma.rn.f32x2 %0, %1, %2, %0;" : "+l"(d) : "l"(a), "l"(b));
}

// ---------------- intermediate buffers ----------------
__device__ float g_a[NB*64*H1*W1];
__device__ float g_b[NB*64*H1*W1];
__device__ float g_p[NQ*64*HP*HP];
__device__ float g_c[NQ*64*HP*HP];
__device__ float g_d[NQ*64*HP*HP];
__device__ float g_e[NQ*1024*HO*HO];
__device__ float g_f[NQ*1024*HO*HO];

// bf16-split staging
__device__ uint4 g_wh[8*256*1024];    // w5 tiles [cotile][tap] 16KB swizzled, hi
__device__ uint4 g_wl[8*256*1024];    // lo
__device__ uint4 g_th[258048];        // input [q][y63][x64][ci64] bf16 hi
__device__ uint4 g_tl[258048];        // lo
__device__ uint4 g_w6h[131072];       // w6 tiles [cotile8][kc16] 16KB swizzled, hi (2MB)
__device__ uint4 g_w6l[131072];       // lo
__device__ uint4 g_eh[2359296];       // conv5 out transposed [q][px2304][co1024] bf16 hi (37.7MB)
__device__ uint4 g_el[2359296];       // lo

// ---------------- smem addr helper ----------------
__device__ __forceinline__ uint32_t s2u(const void* p) {
    uint32_t a;
    asm("{ .reg .u64 t; cvta.to.shared.u64 t, %1; cvt.u32.u64 %0, t; }" : "=r"(a) : "l"(p));
    return a;
}

// ---------------- portable tensor-core primitives (sm_80+) ----------------
#define LDSM4(r, addr) \
    asm volatile("ldmatrix.sync.aligned.m8n8.x4.shared.b16 {%0,%1,%2,%3}, [%4];" \
        : "=r"((r)[0]), "=r"((r)[1]), "=r"((r)[2]), "=r"((r)[3]) : "r"(addr))

#define MMA16816(c, a, b) \
    asm volatile("mma.sync.aligned.m16n8k16.row.col.f32.bf16.bf16.f32 " \
        "{%0,%1,%2,%3}, {%4,%5,%6,%7}, {%8,%9}, {%0,%1,%2,%3};" \
        : "+f"((c)[0]), "+f"((c)[1]), "+f"((c)[2]), "+f"((c)[3]) \
        : "r"((a)[0]), "r"((a)[1]), "r"((a)[2]), "r"((a)[3]), \
          "r"((b)[0]), "r"((b)[1]))

#define CP16(dst, src) \
    asm volatile("cp.async.cg.shared.global [%0], [%1], 16;" :: "r"(dst), "l"(src))
#define CP_COMMIT asm volatile("cp.async.commit_group;")
#define CP_WAIT0  asm volatile("cp.async.wait_group 0;")

__device__ __forceinline__ uint32_t swz(uint32_t x) { return x ^ ((x >> 3) & 0x70); }

__device__ __forceinline__ uint32_t bfpack(float a, float b) {
    __nv_bfloat162 p;
    p.x = __float2bfloat16(a);
    p.y = __float2bfloat16(b);
    return *(uint32_t*)&p;
}

// =====================================================================
// conv_tile (conv1-4), fp32 f32x2 (unchanged, proven)
// =====================================================================
template<int K, int CIN, int CCH, bool DO_LRN>
__global__ __launch_bounds__(256, 2) void conv_tile(
    const float* __restrict__ in, const float* __restrict__ w,
    const float* __restrict__ bias, float* __restrict__ out,
    int H, int W)
{
    constexpr int KK    = K * K;
    constexpr int PAD   = K / 2;
    constexpr int PH    = 16 + K - 1;
    constexpr int WELE  = 64 * CCH * KK;
    __shared__ float patch[CCH * PH * 48];
    __shared__ u64   wsm2[WELE];

    const int tid   = threadIdx.x;
    const int cog   = tid >> 5;
    const int pxt   = tid & 31;
    const int col   = pxt & 15;
    const int rbase = pxt >> 4;
    const int x0 = blockIdx.x * 16;
    const int y0 = blockIdx.y * 16;
    const int n  = blockIdx.z;

    u64 acc2[8][4];
    #pragma unroll
    for (int c = 0; c < 8; c++)
        #pragma unroll
        for (int j = 0; j < 4; j++) acc2[c][j] = 0ull;

    for (int cb = 0; cb < CIN; cb += CCH) {
        __syncthreads();
        for (int idx = tid; idx < CCH * PH * PH; idx += 256) {
            int ci = idx / (PH * PH);
            int rr = (idx / PH) % PH;
            int cc = idx % PH;
            int gy = y0 - PAD + rr;
            int gx = x0 - PAD + cc;
            float v = 0.f;
            if (gy >= 0 && gy < H && gx >= 0 && gx < W)
                v = in[((n * CIN + cb + ci) * H + gy) * W + gx];
            patch[(ci * PH + rr) * 48 + cc] = v;
        }
        for (int idx = tid; idx < WELE; idx += 256) {
            int co  = idx / (CCH * KK);
            int rem = idx % (CCH * KK);
            float wv = w[(co * CIN + cb) * KK + rem];
            wsm2[idx] = pack2(wv, wv);
        }
        __syncthreads();

        #pragma unroll 1
        for (int ci = 0; ci < CCH; ci++) {
            const float* prow = &patch[ci * PH * 48];
            const u64* wrow = &wsm2[(cog * 8) * CCH * KK + ci * KK];
            #pragma unroll 1
            for (int ky = 0; ky < K; ky++) {
                #pragma unroll
                for (int kx = 0; kx < K; kx++) {
                    float v[8];
                    #pragma unroll
                    for (int i = 0; i < 8; i++)
                        v[i] = prow[(rbase + 2 * i + ky) * 48 + col + kx];
                    u64 vp[4];
                    #pragma unroll
                    for (int j = 0; j < 4; j++)
                        vp[j] = pack2(v[2 * j], v[2 * j + 1]);
                    #pragma unroll
                    for (int c = 0; c < 8; c++) {
                        u64 wp = wrow[c * CCH * KK + ky * K + kx];
                        #pragma unroll
                        for (int j = 0; j < 4; j++)
                            fma2(acc2[c][j], wp, vp[j]);
                    }
                }
            }
        }
    }

    float acc[8][8];
    #pragma unroll
    for (int c = 0; c < 8; c++) {
        float bb = bias[cog * 8 + c];
        #pragma unroll
        for (int j = 0; j < 4; j++) {
            float lo, hi;
            unpack2(acc2[c][j], lo, hi);
            acc[c][2 * j]     = fmaxf(lo + bb, 0.f);
            acc[c][2 * j + 1] = fmaxf(hi + bb, 0.f);
        }
    }

    if (DO_LRN) {
        __syncthreads();
        float* edge = patch;
        #pragma unroll
        for (int i = 0; i < 8; i++)
            edge[(cog * 32 + pxt) * 8 + i] = acc[7][i];
        __syncthreads();
        float prev[8];
        #pragma unroll
        for (int i = 0; i < 8; i++)
            prev[i] = (cog > 0) ? edge[((cog - 1) * 32 + pxt) * 8 + i] : 0.f;
        #pragma unroll
        for (int c = 7; c >= 0; c--) {
            #pragma unroll
            for (int i = 0; i < 8; i++) {
                float cur = acc[c][i];
                float pv  = (c > 0) ? acc[c - 1][i] : prev[i];
                float dnm = 1.f + 1e-5f * (pv * pv + cur * cur);
                acc[c][i] = cur * powf(dnm, -0.75f);
            }
        }
    }

    #pragma unroll
    for (int c = 0; c < 8; c++) {
        int co = cog * 8 + c;
        #pragma unroll
        for (int i = 0; i < 8; i++) {
            int y = y0 + rbase + 2 * i;
            int x = x0 + col;
            if (y < H && x < W)
                out[((n * 64 + co) * H + y) * W + x] = acc[c][i];
        }
    }
}

// =====================================================================
// crops + maxpool
// =====================================================================
__global__ void pool_kernel(const float* __restrict__ in, float* __restrict__ out)
{
    int id = blockIdx.x * 256 + threadIdx.x;
    if (id >= NQ * 64 * HP * HP) return;
    int j = id % HP;
    int i = (id / HP) % HP;
    int c = (id / (HP * HP)) % 64;
    int q = id / (64 * HP * HP);
    int n = q & 1;
    int crop = q >> 1;
    int dy = crop & 1;
    int dx = crop >> 1;
    const float* base = in + ((size_t)(n * 64 + c) * H1) * W1;
    int y = dy + 2 * i, x = dx + 2 * j;
    float m = fmaxf(fmaxf(base[y * W1 + x],       base[y * W1 + x + 1]),
                    fmaxf(base[(y + 1) * W1 + x], base[(y + 1) * W1 + x + 1]));
    out[id] = m;
}

// =====================================================================
// transform: conv4 output -> [q][y63][x64][ci64] bf16 hi/lo (x=63 zero pad)
// =====================================================================
__global__ void tr_input_kernel(const float* __restrict__ src)
{
    int id = blockIdx.x * 256 + threadIdx.x;
    if (id >= NQ * 63 * 64 * 64) return;
    int ci = id & 63;
    int x  = (id >> 6) & 63;
    int qy = id >> 12;
    int y  = qy % 63;
    int q  = qy / 63;
    float v = 0.f;
    if (x < 63) v = src[((q * 64 + ci) * HP + y) * HP + x];
    __nv_bfloat16 h = __float2bfloat16(v);
    __nv_bfloat16 l = __float2bfloat16(v - __bfloat162float(h));
    ((__nv_bfloat16*)g_th)[id] = h;
    ((__nv_bfloat16*)g_tl)[id] = l;
}

// =====================================================================
// transform: w5 -> swizzled tiles, vectorized (uint4 writes; swizzle is
// 16B-granular so an 8-ci chunk stays one dense uint4).
// thread: (co, j=ci-chunk, tap); tap fastest -> coalesced reads.
// =====================================================================
__global__ void tr_w5_kernel(const float* __restrict__ w5)
{
    int id = blockIdx.x * 256 + threadIdx.x;
    if (id >= 1024 * 8 * 256) return;
    int tap = id & 255;
    int j   = (id >> 8) & 7;
    int co  = id >> 11;

    uint32_t hh[4], ll[4];
    #pragma unroll
    for (int p = 0; p < 4; p++) {
        float v0 = w5[(co * 64 + j * 8 + 2 * p)     * 256 + tap];
        float v1 = w5[(co * 64 + j * 8 + 2 * p + 1) * 256 + tap];
        __nv_bfloat16 h0 = __float2bfloat16(v0);
        __nv_bfloat16 h1 = __float2bfloat16(v1);
        float r0 = v0 - __bfloat162float(h0);
        float r1 = v1 - __bfloat162float(h1);
        __nv_bfloat162 ph; ph.x = h0; ph.y = h1;
        hh[p] = *(uint32_t*)&ph;
        ll[p] = bfpack(r0, r1);
    }
    int cotile = co >> 7, co128 = co & 127;
    uint32_t off = swz((uint32_t)(co128 * 128 + j * 16)) >> 4;
    size_t base = (size_t)(cotile * 256 + tap) * 1024 + off;
    g_wh[base] = make_uint4(hh[0], hh[1], hh[2], hh[3]);
    g_wl[base] = make_uint4(ll[0], ll[1], ll[2], ll[3]);
}

// =====================================================================
// transform: w6 (1024x1024) -> swizzled tiles [cotile8][kc16][128co x 64ci] hi/lo
// =====================================================================
__global__ void tr_w6_kernel(const float* __restrict__ w6)
{
    int id = blockIdx.x * 256 + threadIdx.x;
    if (id >= 1024 * 16 * 8) return;
    int jj = id & 7;
    int kc = (id >> 3) & 15;
    int co = id >> 7;

    uint32_t hh[4], ll[4];
    #pragma unroll
    for (int p = 0; p < 4; p++) {
        float v0 = w6[co * 1024 + kc * 64 + jj * 8 + 2 * p];
        float v1 = w6[co * 1024 + kc * 64 + jj * 8 + 2 * p + 1];
        __nv_bfloat16 h0 = __float2bfloat16(v0);
        __nv_bfloat16 h1 = __float2bfloat16(v1);
        float r0 = v0 - __bfloat162float(h0);
        float r1 = v1 - __bfloat162float(h1);
        __nv_bfloat162 ph; ph.x = h0; ph.y = h1;
        hh[p] = *(uint32_t*)&ph;
        ll[p] = bfpack(r0, r1);
    }
    int cotile = co >> 7, co128 = co & 127;
    uint32_t off = swz((uint32_t)(co128 * 128 + jj * 16)) >> 4;
    size_t base = (size_t)(cotile * 16 + kc) * 1024 + off;
    g_w6h[base] = make_uint4(hh[0], hh[1], hh[2], hh[3]);
    g_w6l[base] = make_uint4(ll[0], ll[1], ll[2], ll[3]);
}

// =====================================================================
// transpose: g_e f32 [q][co1024][px2304] -> g_eh/g_el bf16 [q][px2304][co1024]
// 32x32 smem tile, both sides coalesced.
// =====================================================================
__global__ void transp_e_kernel()
{
    __shared__ float tile[32][33];
    const int tx = threadIdx.x, ty = threadIdx.y;
    const int px0 = blockIdx.x * 32, co0 = blockIdx.y * 32, q = blockIdx.z;

    #pragma unroll
    for (int i = 0; i < 4; i++)
        tile[ty + 8 * i][tx] = g_e[((size_t)(q * 1024 + co0 + ty + 8 * i)) * PX5 + px0 + tx];
    __syncthreads();
    __nv_bfloat16* oh = (__nv_bfloat16*)g_eh;
    __nv_bfloat16* ol = (__nv_bfloat16*)g_el;
    #pragma unroll
    for (int i = 0; i < 4; i++) {
        float v = tile[tx][ty + 8 * i];
        __nv_bfloat16 h = __float2bfloat16(v);
        __nv_bfloat16 l = __float2bfloat16(v - __bfloat162float(h));
        size_t o = ((size_t)(q * 2304 + px0 + ty + 8 * i)) * 1024 + co0 + tx;
        oh[o] = h;
        ol[o] = l;
    }
}

// =====================================================================
// conv5 via mma.sync, bf16 3-pass split.  Block 512 thr / 16 warps,
// tile 128co x 4 rows x 48px, grid (12,8,8).
// A: cp.async double-buffered pre-swizzled 32KB tiles (1 bar/tap).
// B: per-ky row slabs; ldmatrix x4 covers nt pairs.
// =====================================================================
#define C5_ABUF 32768
#define C5_SLAB 65536
#define C5_SMEM 131072

__global__ __launch_bounds__(512, 1) void conv5_mma(
    const float* __restrict__ bias, float* __restrict__ out)
{
    extern __shared__ char sm[];
    const uint32_t sA    = s2u(sm);               // 2 bufs x (hi 16K + lo 16K)
    const uint32_t sSlab = sA + C5_SLAB;          // 8 slabs x 8KB
    char* Slab = sm + C5_SLAB;

    const int tid  = threadIdx.x;
    const int lane = tid & 31;
    const int wid  = tid >> 5;
    const int cog  = wid >> 1;
    const int h    = wid & 1;
    const int yblk = blockIdx.x, cotile = blockIdx.y, q = blockIdx.z;
    const int Y0 = yblk * 4;
    const int m  = cog * 16;

    const int ar  = lane & 15;
    const int acp = lane >> 4;
    const int bxl = lane & 7;
    const int bp  = (lane >> 3) & 1;
    const int nb  = lane >> 4;
    const uint32_t nbadd = (uint32_t)nb * 1024;

    float acc[2][6][4];
    #pragma unroll
    for (int r = 0; r < 2; r++)
        #pragma unroll
        for (int nt = 0; nt < 6; nt++)
            #pragma unroll
            for (int j = 0; j < 4; j++) acc[r][nt][j] = 0.f;

    // prologue: async-load A tile for tap 0 into buf0
    {
        const uint4* sh = g_wh + (size_t)(cotile * 256) * 1024;
        const uint4* sl = g_wl + (size_t)(cotile * 256) * 1024;
        CP16(sA + tid * 16,                 sh + tid);
        CP16(sA + (tid + 512) * 16,         sh + tid + 512);
        CP16(sA + 16384 + tid * 16,         sl + tid);
        CP16(sA + 16384 + (tid + 512) * 16, sl + tid + 512);
        CP_COMMIT;
        CP_WAIT0;
    }

    #pragma unroll 1
    for (int t = 0; t < 256; t++) {
        const int kx = t & 15;
        if (kx == 0) {
            const int ky = t >> 4;
            // load 8 slabs (yy 0..3 x hi/lo) with XOR-16B swizzle
            for (int i = tid; i < 4096; i += 512) {
                int s = i >> 9;
                int j = i & 511;
                int x = j >> 3, c = j & 7;
                int yy = s >> 1, sel = s & 1;
                const uint4* src = (sel ? g_tl : g_th) + (size_t)(q * 63 + Y0 + ky + yy) * 512;
                ((uint4*)Slab)[s * 512 + x * 8 + (c ^ (x & 7))] = src[j];
            }
            __syncthreads();
        }

        const uint32_t bufA = sA + (uint32_t)(t & 1) * C5_ABUF;

        // A fragments: 4 k-steps x (hi, lo)
        uint32_t Ah[4][4], Al[4][4];
        {
            const uint32_t rowoff = bufA + (uint32_t)(m + ar) * 128;
            #pragma unroll
            for (int k = 0; k < 4; k++) {
                uint32_t ch = (uint32_t)(((2 * k + acp) ^ (ar & 7)) * 16);
                LDSM4(Ah[k], rowoff + ch);
                LDSM4(Al[k], rowoff + ch + 16384);
            }
        }

        // prefetch A for next tap into the other buffer
        {
            int tn = t + 1; if (tn > 255) tn = 255;
            const uint4* sh = g_wh + (size_t)(cotile * 256 + tn) * 1024;
            const uint4* sl = g_wl + (size_t)(cotile * 256 + tn) * 1024;
            uint32_t dA = sA + (uint32_t)((t + 1) & 1) * C5_ABUF;
            CP16(dA + tid * 16,                 sh + tid);
            CP16(dA + (tid + 512) * 16,         sh + tid + 512);
            CP16(dA + 16384 + tid * 16,         sl + tid);
            CP16(dA + 16384 + (tid + 512) * 16, sl + tid + 512);
            CP_COMMIT;
        }

        // B fragments + MMAs
        const uint32_t rowbyte = (uint32_t)(kx + bxl) * 128;
        const uint32_t xorb = (uint32_t)((kx + bxl) & 7);
        #pragma unroll
        for (int rr = 0; rr < 2; rr++) {
            const uint32_t hb = sSlab + (uint32_t)(4 * h + 2 * rr) * 8192 + rowbyte + nbadd;
            const uint32_t lb = hb + 8192;
            #pragma unroll
            for (int k = 0; k < 4; k++) {
                const uint32_t ch = (uint32_t)(((uint32_t)(2 * k + bp) ^ xorb) * 16);
                #pragma unroll
                for (int p = 0; p < 3; p++) {
                    const uint32_t off = (uint32_t)(p * 2048) + ch;
                    uint32_t rh[4], rl[4];
                    LDSM4(rh, hb + off);
                    MMA16816(acc[rr][2 * p],     Ah[k], rh);
                    MMA16816(acc[rr][2 * p],     Al[k], rh);
                    MMA16816(acc[rr][2 * p + 1], Ah[k], rh + 2);
                    MMA16816(acc[rr][2 * p + 1], Al[k], rh + 2);
                    LDSM4(rl, lb + off);
                    MMA16816(acc[rr][2 * p],     Ah[k], rl);
                    MMA16816(acc[rr][2 * p + 1], Ah[k], rl + 2);
                }
            }
        }

        CP_WAIT0;
        __syncthreads();
    }

    // epilogue: bias + relu, direct store
    {
        const int co_l = lane >> 2;
        const int col2 = 2 * (lane & 3);
        const int co0 = cotile * 128 + m + co_l;
        const int co1 = co0 + 8;
        const float b0 = bias[co0];
        const float b1 = bias[co1];
        #pragma unroll
        for (int rr = 0; rr < 2; rr++) {
            const int y = Y0 + 2 * h + rr;
            float* o0 = out + ((size_t)(q * 1024 + co0) * HO + y) * HO;
            float* o1 = out + ((size_t)(q * 1024 + co1) * HO + y) * HO;
            #pragma unroll
            for (int nt = 0; nt < 6; nt++) {
                const int px = nt * 8 + col2;
                o0[px]     = fmaxf(acc[rr][nt][0] + b0, 0.f);
                o0[px + 1] = fmaxf(acc[rr][nt][1] + b0, 0.f);
                o1[px]     = fmaxf(acc[rr][nt][2] + b1, 0.f);
                o1[px + 1] = fmaxf(acc[rr][nt][3] + b1, 0.f);
            }
        }
    }
}

// =====================================================================
// conv6 via mma.sync, bf16 3-pass split.  Block 512 thr / 16 warps.
// Tile: M=128 co x N=128 px, K=1024 in 16 chunks of 64, cp.async
// double-buffered (A 32KB + B 32KB per chunk).  Grid (18, 8, 8).
// Warp: m16 = (wid&7)*16, n-half = (wid>>3)*64 -> acc[8][4].
// =====================================================================
#define C6_BUF  65536
#define C6_SMEM 131072

__global__ __launch_bounds__(512, 1) void conv6_mma(
    const float* __restrict__ bias, float* __restrict__ out)
{
    extern __shared__ char sm[];
    const uint32_t sB0 = s2u(sm);    // buf: Ah@0 Al@16K Bh@32K Bl@48K

    const int tid  = threadIdx.x;
    const int lane = tid & 31;
    const int wid  = tid >> 5;
    const int mw   = (wid & 7) * 16;
    const int nh   = wid >> 3;
    const int bx = blockIdx.x, cotile = blockIdx.y, q = blockIdx.z;
    const int px0 = bx * 128;

    const int ar  = lane & 15;
    const int acp = lane >> 4;
    const int bxl = lane & 7;
    const int bp  = (lane >> 3) & 1;
    const int nb  = lane >> 4;

    float acc[8][4];
    #pragma unroll
    for (int nt = 0; nt < 8; nt++)
        #pragma unroll
        for (int j = 0; j < 4; j++) acc[nt][j] = 0.f;

    // chunk loader (4096 uint4 -> 8 cp.async per thread)
    auto load_chunk = [&](int kc, uint32_t dbuf) {
        const uint4* ah = g_w6h + (size_t)(cotile * 16 + kc) * 1024;
        const uint4* al = g_w6l + (size_t)(cotile * 16 + kc) * 1024;
        #pragma unroll
        for (int r = 0; r < 2; r++) {
            int i = tid + r * 512;
            CP16(dbuf + i * 16,         ah + i);
            CP16(dbuf + 16384 + i * 16, al + i);
        }
        #pragma unroll
        for (int r = 0; r < 2; r++) {
            int j = tid + r * 512;
            int n = j >> 3, c = j & 7;
            size_t src = (size_t)(q * 2304 + px0 + n) * 128 + kc * 8 + c;
            uint32_t dst = (uint32_t)(n * 128 + (c ^ (n & 7)) * 16);
            CP16(dbuf + 32768 + dst, g_eh + src);
            CP16(dbuf + 49152 + dst, g_el + src);
        }
        CP_COMMIT;
    };

    load_chunk(0, sB0);
    CP_WAIT0;
    __syncthreads();

    #pragma unroll 1
    for (int kc = 0; kc < 16; kc++) {
        const uint32_t buf = sB0 + (uint32_t)(kc & 1) * C6_BUF;

        // A fragments
        uint32_t Ah[4][4], Al[4][4];
        {
            const uint32_t rowoff = buf + (uint32_t)(mw + ar) * 128;
            #pragma unroll
            for (int k = 0; k < 4; k++) {
                uint32_t ch = (uint32_t)(((2 * k + acp) ^ (ar & 7)) * 16);
                LDSM4(Ah[k], rowoff + ch);
                LDSM4(Al[k], rowoff + ch + 16384);
            }
        }

        // prefetch next chunk
        {
            int kn = kc + 1; if (kn > 15) kn = 15;
            load_chunk(kn, sB0 + (uint32_t)((kc + 1) & 1) * C6_BUF);
        }

        // B fragments + MMAs
        const uint32_t hb = buf + 32768 + (uint32_t)(nh * 64 + nb * 8 + bxl) * 128;
        const uint32_t lb = hb + 16384;
        #pragma unroll
        for (int k = 0; k < 4; k++) {
            const uint32_t ch = (uint32_t)(((uint32_t)(2 * k + bp) ^ (uint32_t)bxl) * 16);
            #pragma unroll
            for (int p = 0; p < 4; p++) {
                const uint32_t off = (uint32_t)(p * 2048) + ch;
                uint32_t rh[4], rl[4];
                LDSM4(rh, hb + off);
                MMA16816(acc[2 * p],     Ah[k], rh);
                MMA16816(acc[2 * p],     Al[k], rh);
                MMA16816(acc[2 * p + 1], Ah[k], rh + 2);
                MMA16816(acc[2 * p + 1], Al[k], rh + 2);
                LDSM4(rl, lb + off);
                MMA16816(acc[2 * p],     Ah[k], rl);
                MMA16816(acc[2 * p + 1], Ah[k], rl + 2);
            }
        }

        CP_WAIT0;
        __syncthreads();
    }

    // epilogue
    {
        const int co0 = cotile * 128 + mw + (lane >> 2);
        const int co1 = co0 + 8;
        const float b0 = bias[co0];
        const float b1 = bias[co1];
        float* o0 = out + (size_t)(q * 1024 + co0) * PX5;
        float* o1 = out + (size_t)(q * 1024 + co1) * PX5;
        #pragma unroll
        for (int nt = 0; nt < 8; nt++) {
            const int px = px0 + nh * 64 + nt * 8 + 2 * (lane & 3);
            o0[px]     = fmaxf(acc[nt][0] + b0, 0.f);
            o0[px + 1] = fmaxf(acc[nt][1] + b0, 0.f);
            o1[px]     = fmaxf(acc[nt][2] + b1, 0.f);
            o1[px + 1] = fmaxf(acc[nt][3] + b1, 0.f);
        }
    }
}

// =====================================================================
// conv7 + sigmoid + interweave
// =====================================================================
__global__ void conv7_kernel(const float* __restrict__ in,
                             const float* __restrict__ w7,
                             const float* __restrict__ b7,
                             float* __restrict__ out)
{
    int id = blockIdx.x * 256 + threadIdx.x;
    if (id >= NQ * PX5) return;
    int hw = id % PX5;
    int q  = id / PX5;
    float acc = b7[0];
    const float* p = in + (size_t)q * 1024 * PX5 + hw;
    #pragma unroll 8
    for (int ci = 0; ci < 1024; ci++)
        acc = fmaf(p[ci * PX5], w7[ci], acc);
    float s = 1.f / (1.f + expf(-acc));
    int h = hw / HO, wv = hw % HO;
    int n = q & 1, ss = (q >> 1) & 1, t = q >> 2;
    out[n * 96 * 96 + (2 * h + ss) * 96 + (2 * wv + t)] = s;
}

// =====================================================================
// launch
// =====================================================================
extern "C" void kernel_launch(void* const* d_in, const int* in_sizes, int n_in,
                              void* d_out, int out_size)
{
    const float* x  = (const float*)d_in[0];
    const float* w1 = (const float*)d_in[1];  const float* b1 = (const float*)d_in[2];
    const float* w2 = (const float*)d_in[3];  const float* b2 = (const float*)d_in[4];
    const float* w3 = (const float*)d_in[5];  const float* b3 = (const float*)d_in[6];
    const float* w4 = (const float*)d_in[7];  const float* b4 = (const float*)d_in[8];
    const float* w5 = (const float*)d_in[9];  const float* b5 = (const float*)d_in[10];
    const float* w6 = (const float*)d_in[11]; const float* b6 = (const float*)d_in[12];
    const float* w7 = (const float*)d_in[13]; const float* b7 = (const float*)d_in[14];

    void *pa, *pb, *pp, *pc, *pd, *pe, *pf;
    cudaGetSymbolAddress(&pa, g_a);
    cudaGetSymbolAddress(&pb, g_b);
    cudaGetSymbolAddress(&pp, g_p);
    cudaGetSymbolAddress(&pc, g_c);
    cudaGetSymbolAddress(&pd, g_d);
    cudaGetSymbolAddress(&pe, g_e);
    cudaGetSymbolAddress(&pf, g_f);

    cudaFuncSetAttribute(conv5_mma, cudaFuncAttributeMaxDynamicSharedMemorySize, C5_SMEM);
    cudaFuncSetAttribute(conv6_mma, cudaFuncAttributeMaxDynamicSharedMemorySize, C6_SMEM);

    // weight transforms (independent; run up front)
    tr_w5_kernel<<<(1024 * 8 * 256 + 255) / 256, 256>>>(w5);
    tr_w6_kernel<<<(1024 * 16 * 8 + 255) / 256, 256>>>(w6);

    conv_tile<7, 1, 1, false><<<dim3(8, 8, NB), 256>>>(x, w1, b1, (float*)pa, H1, W1);
    conv_tile<5, 64, 4, true><<<dim3(8, 8, NB), 256>>>((float*)pa, w2, b2, (float*)pb, H1, W1);
    pool_kernel<<<(NQ * 64 * HP * HP + 255) / 256, 256>>>((float*)pb, (float*)pp);
    conv_tile<3, 64, 8, false><<<dim3(4, 4, NQ), 256>>>((float*)pp, w3, b3, (float*)pc, HP, HP);
    conv_tile<3, 64, 8, true><<<dim3(4, 4, NQ), 256>>>((float*)pc, w4, b4, (float*)pd, HP, HP);

    // input transform + tensor-core conv5
    tr_input_kernel<<<(NQ * 63 * 64 * 64 + 255) / 256, 256>>>((float*)pd);
    conv5_mma<<<dim3(12, 8, NQ), 512, C5_SMEM>>>(b5, (float*)pe);

    // transpose conv5 output -> bf16 split [px][co], then tensor-core conv6
    transp_e_kernel<<<dim3(72, 32, NQ), dim3(32, 8)>>>();
    conv6_mma<<<dim3(18, 8, NQ), 512, C6_SMEM>>>(b6, (float*)pf);

    conv7_kernel<<<(NQ * PX5 + 255) / 256, 256>>>((float*)pf, w7, b7, (float*)d_out);
}

// round 15
// speedup vs baseline: 3.8192x; 1.1380x over previous
#include <cuda_runtime.h>
#include <cuda_bf16.h>
#include <math.h>
#include <stdint.h>

// ---------------- problem constants ----------------
#define NB   2
#define H1   128
#define W1   128
#define HP   63
#define NQ   8
#define HO   48
#define PX5  2304

typedef unsigned long long u64;

// ---------------- f32x2 helpers ----------------
__device__ __forceinline__ u64 pack2(float lo, float hi) {
    u64 r; asm("mov.b64 %0, {%1, %2};" : "=l"(r) : "f"(lo), "f"(hi)); return r;
}
__device__ __forceinline__ void unpack2(u64 v, float& lo, float& hi) {
    asm("mov.b64 {%0, %1}, %2;" : "=f"(lo), "=f"(hi) : "l"(v));
}
__device__ __forceinline__ void fma2(u64& d, u64 a, u64 b) {
    asm("fma.rn.f32x2 %0, %1, %2, %0;" : "+l"(d) : "l"(a), "l"(b));
}

// ---------------- intermediate buffers ----------------
__device__ float g_a2[NB*H1*W1*64];    // conv1 out, channel-last      (4MB)
__device__ float g_b2[NB*H1*W1*64];    // conv2+LRN out, channel-last  (4MB)
__device__ float g_p[NQ*64*HP*HP];     // crops+maxpool out (NCHW)
__device__ float g_c[NQ*64*HP*HP];     // conv3 out
__device__ float g_d[NQ*64*HP*HP];     // conv4+LRN out
__device__ float g_e[NQ*1024*HO*HO];   // conv5 out
__device__ float g_f[NQ*1024*HO*HO];   // conv6 out

// bf16-split staging
__device__ uint4 g_wh[8*256*1024];     // w5 tiles [cotile][tap] 16KB swizzled, hi
__device__ uint4 g_wl[8*256*1024];     // lo
__device__ uint4 g_th[258048];         // conv5 input [q][y63][x64][ci64] hi
__device__ uint4 g_tl[258048];         // lo
__device__ uint4 g_w6h[131072];        // w6 tiles [cotile8][kc16] hi
__device__ uint4 g_w6l[131072];        // lo
__device__ uint4 g_eh[2359296];        // conv5 out transposed [q][px][co] hi
__device__ uint4 g_el[2359296];        // lo
__device__ uint4 g_w2h[25*512];        // w2 tiles [tap25][64co x 64ci] hi
__device__ uint4 g_w2l[25*512];        // lo
__device__ uint4 g_tah[287424];        // conv2 input [n][y'132][x'136][ci64] hi (pad 2)
__device__ uint4 g_tal[287424];        // lo

// ---------------- smem addr helper ----------------
__device__ __forceinline__ uint32_t s2u(const void* p) {
    uint32_t a;
    asm("{ .reg .u64 t; cvta.to.shared.u64 t, %1; cvt.u32.u64 %0, t; }" : "=r"(a) : "l"(p));
    return a;
}

// ---------------- portable tensor-core primitives (sm_80+) ----------------
#define LDSM4(r, addr) \
    asm volatile("ldmatrix.sync.aligned.m8n8.x4.shared.b16 {%0,%1,%2,%3}, [%4];" \
        : "=r"((r)[0]), "=r"((r)[1]), "=r"((r)[2]), "=r"((r)[3]) : "r"(addr))

#define MMA16816(c, a, b) \
    asm volatile("mma.sync.aligned.m16n8k16.row.col.f32.bf16.bf16.f32 " \
        "{%0,%1,%2,%3}, {%4,%5,%6,%7}, {%8,%9}, {%0,%1,%2,%3};" \
        : "+f"((c)[0]), "+f"((c)[1]), "+f"((c)[2]), "+f"((c)[3]) \
        : "r"((a)[0]), "r"((a)[1]), "r"((a)[2]), "r"((a)[3]), \
          "r"((b)[0]), "r"((b)[1]))

#define CP16(dst, src) \
    asm volatile("cp.async.cg.shared.global [%0], [%1], 16;" :: "r"(dst), "l"(src))
#define CP_COMMIT asm volatile("cp.async.commit_group;")
#define CP_WAIT0  asm volatile("cp.async.wait_group 0;")

__device__ __forceinline__ uint32_t swz(uint32_t x) { return x ^ ((x >> 3) & 0x70); }

__device__ __forceinline__ uint32_t bfpack(float a, float b) {
    __nv_bfloat162 p;
    p.x = __float2bfloat16(a);
    p.y = __float2bfloat16(b);
    return *(uint32_t*)&p;
}

// =====================================================================
// conv_tile (conv1, conv3, conv4), fp32 f32x2
// =====================================================================
template<int K, int CIN, int CCH, bool DO_LRN, bool CHLAST>
__global__ __launch_bounds__(256, 2) void conv_tile(
    const float* __restrict__ in, const float* __restrict__ w,
    const float* __restrict__ bias, float* __restrict__ out,
    int H, int W)
{
    constexpr int KK    = K * K;
    constexpr int PAD   = K / 2;
    constexpr int PH    = 16 + K - 1;
    constexpr int WELE  = 64 * CCH * KK;
    __shared__ float patch[CCH * PH * 48];
    __shared__ u64   wsm2[WELE];

    const int tid   = threadIdx.x;
    const int cog   = tid >> 5;
    const int pxt   = tid & 31;
    const int col   = pxt & 15;
    const int rbase = pxt >> 4;
    const int x0 = blockIdx.x * 16;
    const int y0 = blockIdx.y * 16;
    const int n  = blockIdx.z;

    u64 acc2[8][4];
    #pragma unroll
    for (int c = 0; c < 8; c++)
        #pragma unroll
        for (int j = 0; j < 4; j++) acc2[c][j] = 0ull;

    for (int cb = 0; cb < CIN; cb += CCH) {
        __syncthreads();
        for (int idx = tid; idx < CCH * PH * PH; idx += 256) {
            int ci = idx / (PH * PH);
            int rr = (idx / PH) % PH;
            int cc = idx % PH;
            int gy = y0 - PAD + rr;
            int gx = x0 - PAD + cc;
            float v = 0.f;
            if (gy >= 0 && gy < H && gx >= 0 && gx < W)
                v = in[((n * CIN + cb + ci) * H + gy) * W + gx];
            patch[(ci * PH + rr) * 48 + cc] = v;
        }
        for (int idx = tid; idx < WELE; idx += 256) {
            int co  = idx / (CCH * KK);
            int rem = idx % (CCH * KK);
            float wv = w[(co * CIN + cb) * KK + rem];
            wsm2[idx] = pack2(wv, wv);
        }
        __syncthreads();

        #pragma unroll 1
        for (int ci = 0; ci < CCH; ci++) {
            const float* prow = &patch[ci * PH * 48];
            const u64* wrow = &wsm2[(cog * 8) * CCH * KK + ci * KK];
            #pragma unroll 1
            for (int ky = 0; ky < K; ky++) {
                #pragma unroll
                for (int kx = 0; kx < K; kx++) {
                    float v[8];
                    #pragma unroll
                    for (int i = 0; i < 8; i++)
                        v[i] = prow[(rbase + 2 * i + ky) * 48 + col + kx];
                    u64 vp[4];
                    #pragma unroll
                    for (int j = 0; j < 4; j++)
                        vp[j] = pack2(v[2 * j], v[2 * j + 1]);
                    #pragma unroll
                    for (int c = 0; c < 8; c++) {
                        u64 wp = wrow[c * CCH * KK + ky * K + kx];
                        #pragma unroll
                        for (int j = 0; j < 4; j++)
                            fma2(acc2[c][j], wp, vp[j]);
                    }
                }
            }
        }
    }

    float acc[8][8];
    #pragma unroll
    for (int c = 0; c < 8; c++) {
        float bb = bias[cog * 8 + c];
        #pragma unroll
        for (int j = 0; j < 4; j++) {
            float lo, hi;
            unpack2(acc2[c][j], lo, hi);
            acc[c][2 * j]     = fmaxf(lo + bb, 0.f);
            acc[c][2 * j + 1] = fmaxf(hi + bb, 0.f);
        }
    }

    if (DO_LRN) {
        __syncthreads();
        float* edge = patch;
        #pragma unroll
        for (int i = 0; i < 8; i++)
            edge[(cog * 32 + pxt) * 8 + i] = acc[7][i];
        __syncthreads();
        float prev[8];
        #pragma unroll
        for (int i = 0; i < 8; i++)
            prev[i] = (cog > 0) ? edge[((cog - 1) * 32 + pxt) * 8 + i] : 0.f;
        #pragma unroll
        for (int c = 7; c >= 0; c--) {
            #pragma unroll
            for (int i = 0; i < 8; i++) {
                float cur = acc[c][i];
                float pv  = (c > 0) ? acc[c - 1][i] : prev[i];
                float dnm = 1.f + 1e-5f * (pv * pv + cur * cur);
                acc[c][i] = cur * powf(dnm, -0.75f);
            }
        }
    }

    #pragma unroll
    for (int c = 0; c < 8; c++) {
        int co = cog * 8 + c;
        #pragma unroll
        for (int i = 0; i < 8; i++) {
            int y = y0 + rbase + 2 * i;
            int x = x0 + col;
            if (y < H && x < W) {
                if (CHLAST)
                    out[((n * H + y) * W + x) * 64 + co] = acc[c][i];
                else
                    out[((n * 64 + co) * H + y) * W + x] = acc[c][i];
            }
        }
    }
}

// =====================================================================
// transform: conv1 out (channel-last f32) -> padded transposed bf16 split
// [n][y'132][x'136][ci64], y'=y+2, x'=x+2, zeros outside
// =====================================================================
__global__ void tr_a_kernel()
{
    int id = blockIdx.x * 256 + threadIdx.x;
    if (id >= NB * 132 * 136 * 64) return;
    int ci = id & 63;
    int x  = (id >> 6) % 136;
    int r  = (id >> 6) / 136;
    int y  = r % 132;
    int n  = r / 132;
    float v = 0.f;
    if (y >= 2 && y < 130 && x >= 2 && x < 130)
        v = g_a2[((n * H1 + (y - 2)) * W1 + (x - 2)) * 64 + ci];
    __nv_bfloat16 h = __float2bfloat16(v);
    __nv_bfloat16 l = __float2bfloat16(v - __bfloat162float(h));
    ((__nv_bfloat16*)g_tah)[id] = h;
    ((__nv_bfloat16*)g_tal)[id] = l;
}

// =====================================================================
// transform: w2 [64,64,5,5] -> swizzled tiles [tap25][64co x 64ci] hi/lo
// =====================================================================
__global__ void tr_w2_kernel(const float* __restrict__ w2)
{
    int id = blockIdx.x * 256 + threadIdx.x;
    if (id >= 64 * 8 * 25) return;
    int tap = id % 25;
    int j   = (id / 25) & 7;
    int co  = id / 200;

    uint32_t hh[4], ll[4];
    #pragma unroll
    for (int p = 0; p < 4; p++) {
        float v0 = w2[(co * 64 + j * 8 + 2 * p)     * 25 + tap];
        float v1 = w2[(co * 64 + j * 8 + 2 * p + 1) * 25 + tap];
        __nv_bfloat16 h0 = __float2bfloat16(v0);
        __nv_bfloat16 h1 = __float2bfloat16(v1);
        float r0 = v0 - __bfloat162float(h0);
        float r1 = v1 - __bfloat162float(h1);
        __nv_bfloat162 ph; ph.x = h0; ph.y = h1;
        hh[p] = *(uint32_t*)&ph;
        ll[p] = bfpack(r0, r1);
    }
    uint32_t off = swz((uint32_t)(co * 128 + j * 16)) >> 4;
    size_t base = (size_t)tap * 512 + off;
    g_w2h[base] = make_uint4(hh[0], hh[1], hh[2], hh[3]);
    g_w2l[base] = make_uint4(ll[0], ll[1], ll[2], ll[3]);
}

// =====================================================================
// conv2 via mma.sync, bf16 3-pass split + fused LRN.
// Block 256 thr / 8 warps = 4 m16 x 2 n-halves. Tile M=64co x N=64px,
// one output row y, K=64 per tap, 25 taps. Grid (2 xh, 128 y, 2 n).
// Slabs (5 input rows, 68 x-entries) loaded once; A double-buffered.
// =====================================================================
#define C2_SLAB  32768
#define C2_SMEM  119808   // A 2x16K + slabs 2x43520

__global__ __launch_bounds__(256, 1) void conv2_mma(
    const float* __restrict__ bias, float* __restrict__ out)
{
    extern __shared__ char sm[];
    const uint32_t sA    = s2u(sm);
    const uint32_t sSlab = sA + C2_SLAB;

    const int tid  = threadIdx.x;
    const int lane = tid & 31;
    const int wid  = tid >> 5;
    const int mw   = (wid & 3) * 16;
    const int nh   = wid >> 2;
    const int xh = blockIdx.x, y = blockIdx.y, n = blockIdx.z;

    const int ar  = lane & 15;
    const int acp = lane >> 4;
    const int bxl = lane & 7;
    const int bp  = (lane >> 3) & 1;
    const int nb  = lane >> 4;

    float acc[4][4];
    #pragma unroll
    for (int nt = 0; nt < 4; nt++)
        #pragma unroll
        for (int j = 0; j < 4; j++) acc[nt][j] = 0.f;

    // load 5 slabs (hi+lo), swizzled: slab ky = rows x' = xh*64 + [0,68)
    for (int i = tid; i < 5440; i += 256) {
        int sel = i >= 2720;
        int j = sel ? i - 2720 : i;
        int ky = j / 544;
        int jj = j % 544;
        int r = jj >> 3, c = jj & 7;
        const uint4* src = (sel ? g_tal : g_tah)
            + ((size_t)(n * 132 + y + ky) * 136 + xh * 64 + r) * 8;
        ((uint4*)(sm + C2_SLAB))[(size_t)sel * 2720 + ky * 544 + r * 8 + (c ^ (r & 7))] = src[c];
    }
    // prologue: A tap 0
    {
        #pragma unroll
        for (int i = 0; i < 2; i++) {
            CP16(sA + (tid + i * 256) * 16,        g_w2h + tid + i * 256);
            CP16(sA + 8192 + (tid + i * 256) * 16, g_w2l + tid + i * 256);
        }
        CP_COMMIT;
        CP_WAIT0;
    }
    __syncthreads();

    #pragma unroll 1
    for (int t = 0; t < 25; t++) {
        const int ky = t / 5, kx = t % 5;
        const uint32_t bufA = sA + (uint32_t)(t & 1) * 16384;

        uint32_t Ah[4][4], Al[4][4];
        {
            const uint32_t rowoff = bufA + (uint32_t)(mw + ar) * 128;
            #pragma unroll
            for (int k = 0; k < 4; k++) {
                uint32_t ch = (uint32_t)(((2 * k + acp) ^ (ar & 7)) * 16);
                LDSM4(Ah[k], rowoff + ch);
                LDSM4(Al[k], rowoff + ch + 8192);
            }
        }

        // prefetch next tap's A
        {
            int tn = t + 1; if (tn > 24) tn = 24;
            uint32_t dA = sA + (uint32_t)((t + 1) & 1) * 16384;
            #pragma unroll
            for (int i = 0; i < 2; i++) {
                CP16(dA + (tid + i * 256) * 16,        g_w2h + (size_t)tn * 512 + tid + i * 256);
                CP16(dA + 8192 + (tid + i * 256) * 16, g_w2l + (size_t)tn * 512 + tid + i * 256);
            }
            CP_COMMIT;
        }

        const uint32_t slabh = sSlab + (uint32_t)ky * 8704;
        const uint32_t slabl = slabh + 43520;
        const uint32_t rowbyte = (uint32_t)(kx + nh * 32 + nb * 8 + bxl) * 128;
        const uint32_t xorb = (uint32_t)((kx + bxl) & 7);
        #pragma unroll
        for (int k = 0; k < 4; k++) {
            const uint32_t ch = (uint32_t)(((uint32_t)(2 * k + bp) ^ xorb) * 16);
            #pragma unroll
            for (int p = 0; p < 2; p++) {
                const uint32_t off = rowbyte + (uint32_t)(p * 2048) + ch;
                uint32_t rh[4], rl[4];
                LDSM4(rh, slabh + off);
                MMA16816(acc[2 * p],     Ah[k], rh);
                MMA16816(acc[2 * p],     Al[k], rh);
                MMA16816(acc[2 * p + 1], Ah[k], rh + 2);
                MMA16816(acc[2 * p + 1], Al[k], rh + 2);
                LDSM4(rl, slabl + off);
                MMA16816(acc[2 * p],     Ah[k], rl);
                MMA16816(acc[2 * p + 1], Ah[k], rl + 2);
            }
        }

        CP_WAIT0;
        __syncthreads();
    }

    // epilogue: bias + relu into smem, then LRN, write channel-last
    float* L = (float*)sm;   // [64co][65]
    {
        const int r0 = mw + (lane >> 2);
        const int r1 = r0 + 8;
        const float b0 = bias[r0];
        const float b1 = bias[r1];
        #pragma unroll
        for (int nt = 0; nt < 4; nt++) {
            const int px = nh * 32 + nt * 8 + 2 * (lane & 3);
            L[r0 * 65 + px]     = fmaxf(acc[nt][0] + b0, 0.f);
            L[r0 * 65 + px + 1] = fmaxf(acc[nt][1] + b0, 0.f);
            L[r1 * 65 + px]     = fmaxf(acc[nt][2] + b1, 0.f);
            L[r1 * 65 + px + 1] = fmaxf(acc[nt][3] + b1, 0.f);
        }
    }
    __syncthreads();
    {
        const int co = tid >> 2;
        const int pxb = (tid & 3) * 16;
        float* o = out + ((size_t)(n * H1 + y) * W1 + xh * 64 + pxb) * 64 + co;
        #pragma unroll
        for (int e = 0; e < 16; e++) {
            int px = pxb + e;
            float cur = L[co * 65 + px];
            float pv  = co ? L[(co - 1) * 65 + px] : 0.f;
            float dnm = 1.f + 1e-5f * (pv * pv + cur * cur);
            o[e * 64] = cur * powf(dnm, -0.75f);
        }
    }
}

// =====================================================================
// crops + maxpool: channel-last in (g_b2), NCHW out (g_p)
// =====================================================================
__global__ void pool_kernel(const float* __restrict__ in, float* __restrict__ out)
{
    int id = blockIdx.x * 256 + threadIdx.x;
    if (id >= NQ * 64 * HP * HP) return;
    int c = id & 63;
    int j = (id >> 6) % HP;
    int r = (id >> 6) / HP;
    int i = r % HP;
    int q = r / HP;
    int n = q & 1;
    int crop = q >> 1;
    int dy = crop & 1;
    int dx = crop >> 1;
    int y = dy + 2 * i, x = dx + 2 * j;
    const float* base = in + ((size_t)(n * H1 + y) * W1 + x) * 64 + c;
    float m = fmaxf(fmaxf(base[0], base[64]),
                    fmaxf(base[W1 * 64], base[W1 * 64 + 64]));
    out[((size_t)(q * 64 + c) * HP + i) * HP + j] = m;
}

// =====================================================================
// transform: conv4 output -> [q][y63][x64][ci64] bf16 hi/lo (x=63 zero pad)
// =====================================================================
__global__ void tr_input_kernel(const float* __restrict__ src)
{
    int id = blockIdx.x * 256 + threadIdx.x;
    if (id >= NQ * 63 * 64 * 64) return;
    int ci = id & 63;
    int x  = (id >> 6) & 63;
    int qy = id >> 12;
    int y  = qy % 63;
    int q  = qy / 63;
    float v = 0.f;
    if (x < 63) v = src[((q * 64 + ci) * HP + y) * HP + x];
    __nv_bfloat16 h = __float2bfloat16(v);
    __nv_bfloat16 l = __float2bfloat16(v - __bfloat162float(h));
    ((__nv_bfloat16*)g_th)[id] = h;
    ((__nv_bfloat16*)g_tl)[id] = l;
}

// =====================================================================
// transform: w5 -> swizzled tiles (vectorized)
// =====================================================================
__global__ void tr_w5_kernel(const float* __restrict__ w5)
{
    int id = blockIdx.x * 256 + threadIdx.x;
    if (id >= 1024 * 8 * 256) return;
    int tap = id & 255;
    int j   = (id >> 8) & 7;
    int co  = id >> 11;

    uint32_t hh[4], ll[4];
    #pragma unroll
    for (int p = 0; p < 4; p++) {
        float v0 = w5[(co * 64 + j * 8 + 2 * p)     * 256 + tap];
        float v1 = w5[(co * 64 + j * 8 + 2 * p + 1) * 256 + tap];
        __nv_bfloat16 h0 = __float2bfloat16(v0);
        __nv_bfloat16 h1 = __float2bfloat16(v1);
        float r0 = v0 - __bfloat162float(h0);
        float r1 = v1 - __bfloat162float(h1);
        __nv_bfloat162 ph; ph.x = h0; ph.y = h1;
        hh[p] = *(uint32_t*)&ph;
        ll[p] = bfpack(r0, r1);
    }
    int cotile = co >> 7, co128 = co & 127;
    uint32_t off = swz((uint32_t)(co128 * 128 + j * 16)) >> 4;
    size_t base = (size_t)(cotile * 256 + tap) * 1024 + off;
    g_wh[base] = make_uint4(hh[0], hh[1], hh[2], hh[3]);
    g_wl[base] = make_uint4(ll[0], ll[1], ll[2], ll[3]);
}

// =====================================================================
// transform: w6 -> swizzled tiles
// =====================================================================
__global__ void tr_w6_kernel(const float* __restrict__ w6)
{
    int id = blockIdx.x * 256 + threadIdx.x;
    if (id >= 1024 * 16 * 8) return;
    int jj = id & 7;
    int kc = (id >> 3) & 15;
    int co = id >> 7;

    uint32_t hh[4], ll[4];
    #pragma unroll
    for (int p = 0; p < 4; p++) {
        float v0 = w6[co * 1024 + kc * 64 + jj * 8 + 2 * p];
        float v1 = w6[co * 1024 + kc * 64 + jj * 8 + 2 * p + 1];
        __nv_bfloat16 h0 = __float2bfloat16(v0);
        __nv_bfloat16 h1 = __float2bfloat16(v1);
        float r0 = v0 - __bfloat162float(h0);
        float r1 = v1 - __bfloat162float(h1);
        __nv_bfloat162 ph; ph.x = h0; ph.y = h1;
        hh[p] = *(uint32_t*)&ph;
        ll[p] = bfpack(r0, r1);
    }
    int cotile = co >> 7, co128 = co & 127;
    uint32_t off = swz((uint32_t)(co128 * 128 + jj * 16)) >> 4;
    size_t base = (size_t)(cotile * 16 + kc) * 1024 + off;
    g_w6h[base] = make_uint4(hh[0], hh[1], hh[2], hh[3]);
    g_w6l[base] = make_uint4(ll[0], ll[1], ll[2], ll[3]);
}

// =====================================================================
// transpose g_e -> bf16-split [q][px][co]
// =====================================================================
__global__ void transp_e_kernel()
{
    __shared__ float tile[32][33];
    const int tx = threadIdx.x, ty = threadIdx.y;
    const int px0 = blockIdx.x * 32, co0 = blockIdx.y * 32, q = blockIdx.z;

    #pragma unroll
    for (int i = 0; i < 4; i++)
        tile[ty + 8 * i][tx] = g_e[((size_t)(q * 1024 + co0 + ty + 8 * i)) * PX5 + px0 + tx];
    __syncthreads();
    __nv_bfloat16* oh = (__nv_bfloat16*)g_eh;
    __nv_bfloat16* ol = (__nv_bfloat16*)g_el;
    #pragma unroll
    for (int i = 0; i < 4; i++) {
        float v = tile[tx][ty + 8 * i];
        __nv_bfloat16 h = __float2bfloat16(v);
        __nv_bfloat16 l = __float2bfloat16(v - __bfloat162float(h));
        size_t o = ((size_t)(q * 2304 + px0 + ty + 8 * i)) * 1024 + co0 + tx;
        oh[o] = h;
        ol[o] = l;
    }
}

// =====================================================================
// conv5 via mma.sync, bf16 3-pass split.  Block 256 thr / 8 warps,
// tile 128co x 3 rows x 48px, grid (16,8,8)=1024 (6.92 waves, eff 98.8%).
// Warp wid: m16 = wid*16, all 144 px -> acc[3][6][4].
// =====================================================================
#define C5_ABUF 32768
#define C5_SLAB 65536
#define C5_SMEM 114688   // A 2x32K + slabs 6x8K

__global__ __launch_bounds__(256, 1) void conv5_mma(
    const float* __restrict__ bias, float* __restrict__ out)
{
    extern __shared__ char sm[];
    const uint32_t sA    = s2u(sm);
    const uint32_t sSlab = sA + C5_SLAB;
    char* Slab = sm + C5_SLAB;

    const int tid  = threadIdx.x;
    const int lane = tid & 31;
    const int wid  = tid >> 5;          // 0..7
    const int yblk = blockIdx.x, cotile = blockIdx.y, q = blockIdx.z;
    const int Y0 = yblk * 3;
    const int m  = wid * 16;

    const int ar  = lane & 15;
    const int acp = lane >> 4;
    const int bxl = lane & 7;
    const int bp  = (lane >> 3) & 1;
    const int nb  = lane >> 4;
    const uint32_t nbadd = (uint32_t)nb * 1024;

    float acc[3][6][4];
    #pragma unroll
    for (int r = 0; r < 3; r++)
        #pragma unroll
        for (int nt = 0; nt < 6; nt++)
            #pragma unroll
            for (int j = 0; j < 4; j++) acc[r][nt][j] = 0.f;

    // prologue: A tile tap 0
    {
        const uint4* sh = g_wh + (size_t)(cotile * 256) * 1024;
        const uint4* sl = g_wl + (size_t)(cotile * 256) * 1024;
        #pragma unroll
        for (int i = 0; i < 4; i++) {
            CP16(sA + (tid + i * 256) * 16,         sh + tid + i * 256);
            CP16(sA + 16384 + (tid + i * 256) * 16, sl + tid + i * 256);
        }
        CP_COMMIT;
        CP_WAIT0;
    }

    #pragma unroll 1
    for (int t = 0; t < 256; t++) {
        const int kx = t & 15;
        if (kx == 0) {
            const int ky = t >> 4;
            // 6 slabs (rr 0..2 x hi/lo), XOR-16B swizzle
            for (int i = tid; i < 3072; i += 256) {
                int s = i >> 9;
                int j = i & 511;
                int x = j >> 3, c = j & 7;
                int rr = s >> 1, sel = s & 1;
                const uint4* src = (sel ? g_tl : g_th) + (size_t)(q * 63 + Y0 + ky + rr) * 512;
                ((uint4*)Slab)[s * 512 + x * 8 + (c ^ (x & 7))] = src[j];
            }
            __syncthreads();
        }

        const uint32_t bufA = sA + (uint32_t)(t & 1) * C5_ABUF;

        uint32_t Ah[4][4], Al[4][4];
        {
            const uint32_t rowoff = bufA + (uint32_t)(m + ar) * 128;
            #pragma unroll
            for (int k = 0; k < 4; k++) {
                uint32_t ch = (uint32_t)(((2 * k + acp) ^ (ar & 7)) * 16);
                LDSM4(Ah[k], rowoff + ch);
                LDSM4(Al[k], rowoff + ch + 16384);
            }
        }

        // prefetch next tap's A
        {
            int tn = t + 1; if (tn > 255) tn = 255;
            const uint4* sh = g_wh + (size_t)(cotile * 256 + tn) * 1024;
            const uint4* sl = g_wl + (size_t)(cotile * 256 + tn) * 1024;
            uint32_t dA = sA + (uint32_t)((t + 1) & 1) * C5_ABUF;
            #pragma unroll
            for (int i = 0; i < 4; i++) {
                CP16(dA + (tid + i * 256) * 16,         sh + tid + i * 256);
                CP16(dA + 16384 + (tid + i * 256) * 16, sl + tid + i * 256);
            }
            CP_COMMIT;
        }

        const uint32_t rowbyte = (uint32_t)(kx + bxl) * 128;
        const uint32_t xorb = (uint32_t)((kx + bxl) & 7);
        #pragma unroll
        for (int rr = 0; rr < 3; rr++) {
            const uint32_t hb = sSlab + (uint32_t)(2 * rr) * 8192 + rowbyte + nbadd;
            const uint32_t lb = hb + 8192;
            #pragma unroll
            for (int k = 0; k < 4; k++) {
                const uint32_t ch = (uint32_t)(((uint32_t)(2 * k + bp) ^ xorb) * 16);
                #pragma unroll
                for (int p = 0; p < 3; p++) {
                    const uint32_t off = (uint32_t)(p * 2048) + ch;
                    uint32_t rh[4], rl[4];
                    LDSM4(rh, hb + off);
                    MMA16816(acc[rr][2 * p],     Ah[k], rh);
                    MMA16816(acc[rr][2 * p],     Al[k], rh);
                    MMA16816(acc[rr][2 * p + 1], Ah[k], rh + 2);
                    MMA16816(acc[rr][2 * p + 1], Al[k], rh + 2);
                    LDSM4(rl, lb + off);
                    MMA16816(acc[rr][2 * p],     Ah[k], rl);
                    MMA16816(acc[rr][2 * p + 1], Ah[k], rl + 2);
                }
            }
        }

        CP_WAIT0;
        __syncthreads();
    }

    // epilogue
    {
        const int co0 = cotile * 128 + m + (lane >> 2);
        const int co1 = co0 + 8;
        const float b0 = bias[co0];
        const float b1 = bias[co1];
        #pragma unroll
        for (int rr = 0; rr < 3; rr++) {
            const int y = Y0 + rr;
            float* o0 = out + ((size_t)(q * 1024 + co0) * HO + y) * HO;
            float* o1 = out + ((size_t)(q * 1024 + co1) * HO + y) * HO;
            #pragma unroll
            for (int nt = 0; nt < 6; nt++) {
                const int px = nt * 8 + 2 * (lane & 3);
                o0[px]     = fmaxf(acc[rr][nt][0] + b0, 0.f);
                o0[px + 1] = fmaxf(acc[rr][nt][1] + b0, 0.f);
                o1[px]     = fmaxf(acc[rr][nt][2] + b1, 0.f);
                o1[px + 1] = fmaxf(acc[rr][nt][3] + b1, 0.f);
            }
        }
    }
}

// =====================================================================
// conv6 via mma.sync (unchanged from R13)
// =====================================================================
#define C6_BUF  65536
#define C6_SMEM 131072

__global__ __launch_bounds__(512, 1) void conv6_mma(
    const float* __restrict__ bias, float* __restrict__ out)
{
    extern __shared__ char sm[];
    const uint32_t sB0 = s2u(sm);

    const int tid  = threadIdx.x;
    const int lane = tid & 31;
    const int wid  = tid >> 5;
    const int mw   = (wid & 7) * 16;
    const int nh   = wid >> 3;
    const int bx = blockIdx.x, cotile = blockIdx.y, q = blockIdx.z;
    const int px0 = bx * 128;

    const int ar  = lane & 15;
    const int acp = lane >> 4;
    const int bxl = lane & 7;
    const int bp  = (lane >> 3) & 1;
    const int nb  = lane >> 4;

    float acc[8][4];
    #pragma unroll
    for (int nt = 0; nt < 8; nt++)
        #pragma unroll
        for (int j = 0; j < 4; j++) acc[nt][j] = 0.f;

    auto load_chunk = [&](int kc, uint32_t dbuf) {
        const uint4* ah = g_w6h + (size_t)(cotile * 16 + kc) * 1024;
        const uint4* al = g_w6l + (size_t)(cotile * 16 + kc) * 1024;
        #pragma unroll
        for (int r = 0; r < 2; r++) {
            int i = tid + r * 512;
            CP16(dbuf + i * 16,         ah + i);
            CP16(dbuf + 16384 + i * 16, al + i);
        }
        #pragma unroll
        for (int r = 0; r < 2; r++) {
            int j = tid + r * 512;
            int n = j >> 3, c = j & 7;
            size_t src = (size_t)(q * 2304 + px0 + n) * 128 + kc * 8 + c;
            uint32_t dst = (uint32_t)(n * 128 + (c ^ (n & 7)) * 16);
            CP16(dbuf + 32768 + dst, g_eh + src);
            CP16(dbuf + 49152 + dst, g_el + src);
        }
        CP_COMMIT;
    };

    load_chunk(0, sB0);
    CP_WAIT0;
    __syncthreads();

    #pragma unroll 1
    for (int kc = 0; kc < 16; kc++) {
        const uint32_t buf = sB0 + (uint32_t)(kc & 1) * C6_BUF;

        uint32_t Ah[4][4], Al[4][4];
        {
            const uint32_t rowoff = buf + (uint32_t)(mw + ar) * 128;
            #pragma unroll
            for (int k = 0; k < 4; k++) {
                uint32_t ch = (uint32_t)(((2 * k + acp) ^ (ar & 7)) * 16);
                LDSM4(Ah[k], rowoff + ch);
                LDSM4(Al[k], rowoff + ch + 16384);
            }
        }

        {
            int kn = kc + 1; if (kn > 15) kn = 15;
            load_chunk(kn, sB0 + (uint32_t)((kc + 1) & 1) * C6_BUF);
        }

        const uint32_t hb = buf + 32768 + (uint32_t)(nh * 64 + nb * 8 + bxl) * 128;
        const uint32_t lb = hb + 16384;
        #pragma unroll
        for (int k = 0; k < 4; k++) {
            const uint32_t ch = (uint32_t)(((uint32_t)(2 * k + bp) ^ (uint32_t)bxl) * 16);
            #pragma unroll
            for (int p = 0; p < 4; p++) {
                const uint32_t off = (uint32_t)(p * 2048) + ch;
                uint32_t rh[4], rl[4];
                LDSM4(rh, hb + off);
                MMA16816(acc[2 * p],     Ah[k], rh);
                MMA16816(acc[2 * p],     Al[k], rh);
                MMA16816(acc[2 * p + 1], Ah[k], rh + 2);
                MMA16816(acc[2 * p + 1], Al[k], rh + 2);
                LDSM4(rl, lb + off);
                MMA16816(acc[2 * p],     Ah[k], rl);
                MMA16816(acc[2 * p + 1], Ah[k], rl + 2);
            }
        }

        CP_WAIT0;
        __syncthreads();
    }

    {
        const int co0 = cotile * 128 + mw + (lane >> 2);
        const int co1 = co0 + 8;
        const float b0 = bias[co0];
        const float b1 = bias[co1];
        float* o0 = out + (size_t)(q * 1024 + co0) * PX5;
        float* o1 = out + (size_t)(q * 1024 + co1) * PX5;
        #pragma unroll
        for (int nt = 0; nt < 8; nt++) {
            const int px = px0 + nh * 64 + nt * 8 + 2 * (lane & 3);
            o0[px]     = fmaxf(acc[nt][0] + b0, 0.f);
            o0[px + 1] = fmaxf(acc[nt][1] + b0, 0.f);
            o1[px]     = fmaxf(acc[nt][2] + b1, 0.f);
            o1[px + 1] = fmaxf(acc[nt][3] + b1, 0.f);
        }
    }
}

// =====================================================================
// conv7 + sigmoid + interweave
// =====================================================================
__global__ void conv7_kernel(const float* __restrict__ in,
                             const float* __restrict__ w7,
                             const float* __restrict__ b7,
                             float* __restrict__ out)
{
    int id = blockIdx.x * 256 + threadIdx.x;
    if (id >= NQ * PX5) return;
    int hw = id % PX5;
    int q  = id / PX5;
    float acc = b7[0];
    const float* p = in + (size_t)q * 1024 * PX5 + hw;
    #pragma unroll 8
    for (int ci = 0; ci < 1024; ci++)
        acc = fmaf(p[ci * PX5], w7[ci], acc);
    float s = 1.f / (1.f + expf(-acc));
    int h = hw / HO, wv = hw % HO;
    int n = q & 1, ss = (q >> 1) & 1, t = q >> 2;
    out[n * 96 * 96 + (2 * h + ss) * 96 + (2 * wv + t)] = s;
}

// =====================================================================
// launch
// =====================================================================
extern "C" void kernel_launch(void* const* d_in, const int* in_sizes, int n_in,
                              void* d_out, int out_size)
{
    const float* x  = (const float*)d_in[0];
    const float* w1 = (const float*)d_in[1];  const float* b1 = (const float*)d_in[2];
    const float* w2 = (const float*)d_in[3];  const float* b2 = (const float*)d_in[4];
    const float* w3 = (const float*)d_in[5];  const float* b3 = (const float*)d_in[6];
    const float* w4 = (const float*)d_in[7];  const float* b4 = (const float*)d_in[8];
    const float* w5 = (const float*)d_in[9];  const float* b5 = (const float*)d_in[10];
    const float* w6 = (const float*)d_in[11]; const float* b6 = (const float*)d_in[12];
    const float* w7 = (const float*)d_in[13]; const float* b7 = (const float*)d_in[14];

    void *pa2, *pb2, *pp, *pc, *pd, *pe, *pf;
    cudaGetSymbolAddress(&pa2, g_a2);
    cudaGetSymbolAddress(&pb2, g_b2);
    cudaGetSymbolAddress(&pp, g_p);
    cudaGetSymbolAddress(&pc, g_c);
    cudaGetSymbolAddress(&pd, g_d);
    cudaGetSymbolAddress(&pe, g_e);
    cudaGetSymbolAddress(&pf, g_f);

    cudaFuncSetAttribute(conv5_mma, cudaFuncAttributeMaxDynamicSharedMemorySize, C5_SMEM);
    cudaFuncSetAttribute(conv6_mma, cudaFuncAttributeMaxDynamicSharedMemorySize, C6_SMEM);
    cudaFuncSetAttribute(conv2_mma, cudaFuncAttributeMaxDynamicSharedMemorySize, C2_SMEM);

    // weight transforms (independent)
    tr_w5_kernel<<<(1024 * 8 * 256 + 255) / 256, 256>>>(w5);
    tr_w6_kernel<<<(1024 * 16 * 8 + 255) / 256, 256>>>(w6);
    tr_w2_kernel<<<(64 * 8 * 25 + 255) / 256, 256>>>(w2);

    // conv1 (channel-last out) -> pad/split transform -> conv2 (mma + LRN)
    conv_tile<7, 1, 1, false, true><<<dim3(8, 8, NB), 256>>>(x, w1, b1, (float*)pa2, H1, W1);
    tr_a_kernel<<<(NB * 132 * 136 * 64 + 255) / 256, 256>>>();
    conv2_mma<<<dim3(2, 128, 2), 256, C2_SMEM>>>(b2, (float*)pb2);

    pool_kernel<<<(NQ * 64 * HP * HP + 255) / 256, 256>>>((float*)pb2, (float*)pp);
    conv_tile<3, 64, 8, false, false><<<dim3(4, 4, NQ), 256>>>((float*)pp, w3, b3, (float*)pc, HP, HP);
    conv_tile<3, 64, 8, true, false><<<dim3(4, 4, NQ), 256>>>((float*)pc, w4, b4, (float*)pd, HP, HP);

    // conv5 (mma, 3-row tiles)
    tr_input_kernel<<<(NQ * 63 * 64 * 64 + 255) / 256, 256>>>((float*)pd);
    conv5_mma<<<dim3(16, 8, NQ), 256, C5_SMEM>>>(b5, (float*)pe);

    // conv6 (mma) + conv7
    transp_e_kernel<<<dim3(72, 32, NQ), dim3(32, 8)>>>();
    conv6_mma<<<dim3(18, 8, NQ), 512, C6_SMEM>>>(b6, (float*)pf);
    conv7_kernel<<<(NQ * PX5 + 255) / 256, 256>>>((float*)pf, w7, b7, (float*)d_out);
}

// round 16
// speedup vs baseline: 3.9880x; 1.0442x over previous
#include <cuda_runtime.h>
#include <cuda_bf16.h>
#include <math.h>
#include <stdint.h>

// ---------------- problem constants ----------------
#define NB   2
#define H1   128
#define W1   128
#define HP   63
#define NQ   8
#define HO   48
#define PX5  2304

typedef unsigned long long u64;

// ---------------- f32x2 helpers ----------------
__device__ __forceinline__ u64 pack2(float lo, float hi) {
    u64 r; asm("mov.b64 %0, {%1, %2};" : "=l"(r) : "f"(lo), "f"(hi)); return r;
}
__device__ __forceinline__ void unpack2(u64 v, float& lo, float& hi) {
    asm("mov.b64 {%0, %1}, %2;" : "=f"(lo), "=f"(hi) : "l"(v));
}
__device__ __forceinline__ void fma2(u64& d, u64 a, u64 b) {
    asm("fma.rn.f32x2 %0, %1, %2, %0;" : "+l"(d) : "l"(a), "l"(b));
}

// ---------------- intermediate buffers ----------------
__device__ float g_a2[NB*H1*W1*64];    // conv1 out, channel-last
__device__ float g_b2[NB*H1*W1*64];    // conv2+LRN out, channel-last
__device__ float g_f[NQ*1024*HO*HO];   // conv6 out

// bf16-split staging
__device__ uint4 g_wh[8*256*1024];     // w5 tiles [cotile][tap] 16KB swizzled, hi
__device__ uint4 g_wl[8*256*1024];     // lo
__device__ uint4 g_th[258048];         // conv5 input [q][y63][x64][ci64] hi (conv4 writes)
__device__ uint4 g_tl[258048];         // lo
__device__ uint4 g_w6h[131072];        // w6 tiles [cotile8][kc16] hi
__device__ uint4 g_w6l[131072];        // lo
__device__ uint4 g_eh[2359296];        // conv5 out [q][px2304][co1024] bf16 hi
__device__ uint4 g_el[2359296];        // lo
__device__ uint4 g_w2h[25*512];        // w2 tiles [tap25][64co x 64ci] hi
__device__ uint4 g_w2l[25*512];        // lo
__device__ uint4 g_tah[287424];        // conv2 input [n][y'132][x'136][ci64] hi
__device__ uint4 g_tal[287424];        // lo
__device__ uint4 g_poh[274560];        // pool out [q][y'65][x'66][ci64] hi (borders stay 0)
__device__ uint4 g_pol[274560];        // lo
__device__ uint4 g_c3h[274560];        // conv3 out, same padded fmt
__device__ uint4 g_c3l[274560];        // lo
__device__ uint4 g_w3h[9*512];         // w3 tiles [tap9][64co x 64ci] hi
__device__ uint4 g_w3l[9*512];
__device__ uint4 g_w4h[9*512];
__device__ uint4 g_w4l[9*512];

// ---------------- smem addr helper ----------------
__device__ __forceinline__ uint32_t s2u(const void* p) {
    uint32_t a;
    asm("{ .reg .u64 t; cvta.to.shared.u64 t, %1; cvt.u32.u64 %0, t; }" : "=r"(a) : "l"(p));
    return a;
}

// ---------------- portable tensor-core primitives (sm_80+) ----------------
#define LDSM4(r, addr) \
    asm volatile("ldmatrix.sync.aligned.m8n8.x4.shared.b16 {%0,%1,%2,%3}, [%4];" \
        : "=r"((r)[0]), "=r"((r)[1]), "=r"((r)[2]), "=r"((r)[3]) : "r"(addr))

#define MMA16816(c, a, b) \
    asm volatile("mma.sync.aligned.m16n8k16.row.col.f32.bf16.bf16.f32 " \
        "{%0,%1,%2,%3}, {%4,%5,%6,%7}, {%8,%9}, {%0,%1,%2,%3};" \
        : "+f"((c)[0]), "+f"((c)[1]), "+f"((c)[2]), "+f"((c)[3]) \
        : "r"((a)[0]), "r"((a)[1]), "r"((a)[2]), "r"((a)[3]), \
          "r"((b)[0]), "r"((b)[1]))

#define CP16(dst, src) \
    asm volatile("cp.async.cg.shared.global [%0], [%1], 16;" :: "r"(dst), "l"(src))
#define CP_COMMIT asm volatile("cp.async.commit_group;")
#define CP_WAIT0  asm volatile("cp.async.wait_group 0;")

__device__ __forceinline__ uint32_t swz(uint32_t x) { return x ^ ((x >> 3) & 0x70); }

__device__ __forceinline__ uint32_t bfpack(float a, float b) {
    __nv_bfloat162 p;
    p.x = __float2bfloat16(a);
    p.y = __float2bfloat16(b);
    return *(uint32_t*)&p;
}
__device__ __forceinline__ void bfsplit(float v, __nv_bfloat16& h, __nv_bfloat16& l) {
    h = __float2bfloat16(v);
    l = __float2bfloat16(v - __bfloat162float(h));
}

// =====================================================================
// conv1 (7x7, 1->64), fp32 f32x2, channel-last out
// =====================================================================
__global__ __launch_bounds__(256, 2) void conv1_kernel(
    const float* __restrict__ in, const float* __restrict__ w,
    const float* __restrict__ bias, float* __restrict__ out)
{
    constexpr int K = 7, PH = 22;
    __shared__ float patch[PH * 48];
    __shared__ u64   wsm2[64 * 49];

    const int tid   = threadIdx.x;
    const int cog   = tid >> 5;
    const int pxt   = tid & 31;
    const int col   = pxt & 15;
    const int rbase = pxt >> 4;
    const int x0 = blockIdx.x * 16;
    const int y0 = blockIdx.y * 16;
    const int n  = blockIdx.z;

    u64 acc2[8][4];
    #pragma unroll
    for (int c = 0; c < 8; c++)
        #pragma unroll
        for (int j = 0; j < 4; j++) acc2[c][j] = 0ull;

    for (int idx = tid; idx < PH * PH; idx += 256) {
        int rr = idx / PH, cc = idx % PH;
        int gy = y0 - 3 + rr, gx = x0 - 3 + cc;
        float v = 0.f;
        if (gy >= 0 && gy < H1 && gx >= 0 && gx < W1)
            v = in[(n * H1 + gy) * W1 + gx];
        patch[rr * 48 + cc] = v;
    }
    for (int idx = tid; idx < 64 * 49; idx += 256) {
        float wv = w[idx];
        wsm2[idx] = pack2(wv, wv);
    }
    __syncthreads();

    const u64* wrow = &wsm2[cog * 8 * 49];
    #pragma unroll 1
    for (int ky = 0; ky < K; ky++) {
        #pragma unroll
        for (int kx = 0; kx < K; kx++) {
            float v[8];
            #pragma unroll
            for (int i = 0; i < 8; i++)
                v[i] = patch[(rbase + 2 * i + ky) * 48 + col + kx];
            u64 vp[4];
            #pragma unroll
            for (int j = 0; j < 4; j++)
                vp[j] = pack2(v[2 * j], v[2 * j + 1]);
            #pragma unroll
            for (int c = 0; c < 8; c++) {
                u64 wp = wrow[c * 49 + ky * K + kx];
                #pragma unroll
                for (int j = 0; j < 4; j++)
                    fma2(acc2[c][j], wp, vp[j]);
            }
        }
    }

    #pragma unroll
    for (int c = 0; c < 8; c++) {
        int co = cog * 8 + c;
        float bb = bias[co];
        #pragma unroll
        for (int j = 0; j < 4; j++) {
            float lo, hi;
            unpack2(acc2[c][j], lo, hi);
            int y = y0 + rbase + 4 * j;
            int x = x0 + col;
            out[((n * H1 + y) * W1 + x) * 64 + co]       = fmaxf(lo + bb, 0.f);
            out[((n * H1 + y + 2) * W1 + x) * 64 + co]   = fmaxf(hi + bb, 0.f);
        }
    }
}

// =====================================================================
// transform: conv1 out -> padded transposed bf16 split [n][y'132][x'136][ci]
// =====================================================================
__global__ void tr_a_kernel()
{
    int id = blockIdx.x * 256 + threadIdx.x;
    if (id >= NB * 132 * 136 * 64) return;
    int ci = id & 63;
    int x  = (id >> 6) % 136;
    int r  = (id >> 6) / 136;
    int y  = r % 132;
    int n  = r / 132;
    float v = 0.f;
    if (y >= 2 && y < 130 && x >= 2 && x < 130)
        v = g_a2[((n * H1 + (y - 2)) * W1 + (x - 2)) * 64 + ci];
    __nv_bfloat16 h, l; bfsplit(v, h, l);
    ((__nv_bfloat16*)g_tah)[id] = h;
    ((__nv_bfloat16*)g_tal)[id] = l;
}

// =====================================================================
// generic square-weight transform -> swizzled tiles [tap][64co x 64ci] hi/lo
// =====================================================================
__global__ void tr_wsq_kernel(const float* __restrict__ w, uint4* dh, uint4* dl, int ntap)
{
    int id = blockIdx.x * 256 + threadIdx.x;
    if (id >= 64 * 8 * ntap) return;
    int tap = id % ntap;
    int j   = (id / ntap) & 7;
    int co  = id / (8 * ntap);

    uint32_t hh[4], ll[4];
    #pragma unroll
    for (int p = 0; p < 4; p++) {
        float v0 = w[(co * 64 + j * 8 + 2 * p)     * ntap + tap];
        float v1 = w[(co * 64 + j * 8 + 2 * p + 1) * ntap + tap];
        __nv_bfloat16 h0, l0, h1, l1;
        bfsplit(v0, h0, l0); bfsplit(v1, h1, l1);
        __nv_bfloat162 ph; ph.x = h0; ph.y = h1;
        hh[p] = *(uint32_t*)&ph;
        ll[p] = bfpack(__bfloat162float(l0), __bfloat162float(l1));
    }
    uint32_t off = swz((uint32_t)(co * 128 + j * 16)) >> 4;
    size_t base = (size_t)tap * 512 + off;
    dh[base] = make_uint4(hh[0], hh[1], hh[2], hh[3]);
    dl[base] = make_uint4(ll[0], ll[1], ll[2], ll[3]);
}

// =====================================================================
// conv2 via mma.sync + fused LRN (unchanged from R14)
// =====================================================================
#define C2_SLAB  32768
#define C2_SMEM  119808

__global__ __launch_bounds__(256, 1) void conv2_mma(
    const float* __restrict__ bias, float* __restrict__ out)
{
    extern __shared__ char sm[];
    const uint32_t sA    = s2u(sm);
    const uint32_t sSlab = sA + C2_SLAB;

    const int tid  = threadIdx.x;
    const int lane = tid & 31;
    const int wid  = tid >> 5;
    const int mw   = (wid & 3) * 16;
    const int nh   = wid >> 2;
    const int xh = blockIdx.x, y = blockIdx.y, n = blockIdx.z;

    const int ar  = lane & 15;
    const int acp = lane >> 4;
    const int bxl = lane & 7;
    const int bp  = (lane >> 3) & 1;
    const int nb  = lane >> 4;

    float acc[4][4];
    #pragma unroll
    for (int nt = 0; nt < 4; nt++)
        #pragma unroll
        for (int j = 0; j < 4; j++) acc[nt][j] = 0.f;

    for (int i = tid; i < 5440; i += 256) {
        int sel = i >= 2720;
        int j = sel ? i - 2720 : i;
        int ky = j / 544;
        int jj = j % 544;
        int r = jj >> 3, c = jj & 7;
        const uint4* src = (sel ? g_tal : g_tah)
            + ((size_t)(n * 132 + y + ky) * 136 + xh * 64 + r) * 8;
        ((uint4*)(sm + C2_SLAB))[(size_t)sel * 2720 + ky * 544 + r * 8 + (c ^ (r & 7))] = src[c];
    }
    {
        #pragma unroll
        for (int i = 0; i < 2; i++) {
            CP16(sA + (tid + i * 256) * 16,        g_w2h + tid + i * 256);
            CP16(sA + 8192 + (tid + i * 256) * 16, g_w2l + tid + i * 256);
        }
        CP_COMMIT;
        CP_WAIT0;
    }
    __syncthreads();

    #pragma unroll 1
    for (int t = 0; t < 25; t++) {
        const int ky = t / 5, kx = t % 5;
        const uint32_t bufA = sA + (uint32_t)(t & 1) * 16384;

        uint32_t Ah[4][4], Al[4][4];
        {
            const uint32_t rowoff = bufA + (uint32_t)(mw + ar) * 128;
            #pragma unroll
            for (int k = 0; k < 4; k++) {
                uint32_t ch = (uint32_t)(((2 * k + acp) ^ (ar & 7)) * 16);
                LDSM4(Ah[k], rowoff + ch);
                LDSM4(Al[k], rowoff + ch + 8192);
            }
        }
        {
            int tn = t + 1; if (tn > 24) tn = 24;
            uint32_t dA = sA + (uint32_t)((t + 1) & 1) * 16384;
            #pragma unroll
            for (int i = 0; i < 2; i++) {
                CP16(dA + (tid + i * 256) * 16,        g_w2h + (size_t)tn * 512 + tid + i * 256);
                CP16(dA + 8192 + (tid + i * 256) * 16, g_w2l + (size_t)tn * 512 + tid + i * 256);
            }
            CP_COMMIT;
        }

        const uint32_t slabh = sSlab + (uint32_t)ky * 8704;
        const uint32_t slabl = slabh + 43520;
        const uint32_t rowbyte = (uint32_t)(kx + nh * 32 + nb * 8 + bxl) * 128;
        const uint32_t xorb = (uint32_t)((kx + bxl) & 7);
        #pragma unroll
        for (int k = 0; k < 4; k++) {
            const uint32_t ch = (uint32_t)(((uint32_t)(2 * k + bp) ^ xorb) * 16);
            #pragma unroll
            for (int p = 0; p < 2; p++) {
                const uint32_t off = rowbyte + (uint32_t)(p * 2048) + ch;
                uint32_t rh[4], rl[4];
                LDSM4(rh, slabh + off);
                MMA16816(acc[2 * p],     Ah[k], rh);
                MMA16816(acc[2 * p],     Al[k], rh);
                MMA16816(acc[2 * p + 1], Ah[k], rh + 2);
                MMA16816(acc[2 * p + 1], Al[k], rh + 2);
                LDSM4(rl, slabl + off);
                MMA16816(acc[2 * p],     Ah[k], rl);
                MMA16816(acc[2 * p + 1], Ah[k], rl + 2);
            }
        }

        CP_WAIT0;
        __syncthreads();
    }

    float* L = (float*)sm;
    {
        const int r0 = mw + (lane >> 2);
        const int r1 = r0 + 8;
        const float b0 = bias[r0];
        const float b1 = bias[r1];
        #pragma unroll
        for (int nt = 0; nt < 4; nt++) {
            const int px = nh * 32 + nt * 8 + 2 * (lane & 3);
            L[r0 * 65 + px]     = fmaxf(acc[nt][0] + b0, 0.f);
            L[r0 * 65 + px + 1] = fmaxf(acc[nt][1] + b0, 0.f);
            L[r1 * 65 + px]     = fmaxf(acc[nt][2] + b1, 0.f);
            L[r1 * 65 + px + 1] = fmaxf(acc[nt][3] + b1, 0.f);
        }
    }
    __syncthreads();
    {
        const int co = tid >> 2;
        const int pxb = (tid & 3) * 16;
        float* o = out + ((size_t)(n * H1 + y) * W1 + xh * 64 + pxb) * 64 + co;
        #pragma unroll
        for (int e = 0; e < 16; e++) {
            int px = pxb + e;
            float cur = L[co * 65 + px];
            float pv  = co ? L[(co - 1) * 65 + px] : 0.f;
            float dnm = 1.f + 1e-5f * (pv * pv + cur * cur);
            o[e * 64] = cur * powf(dnm, -0.75f);
        }
    }
}

// =====================================================================
// crops + maxpool -> padded bf16-split channel-last [q][y'65][x'66][ci]
// (borders never written; .bss zero-init provides the padding)
// =====================================================================
__global__ void pool_kernel()
{
    int id = blockIdx.x * 256 + threadIdx.x;
    if (id >= NQ * 63 * 63 * 64) return;
    int ci = id & 63;
    int j = (id >> 6) % 63;
    int r = (id >> 6) / 63;
    int i = r % 63;
    int q = r / 63;
    int n = q & 1;
    int crop = q >> 1;
    int dy = crop & 1;
    int dx = crop >> 1;
    int y = dy + 2 * i, x = dx + 2 * j;
    const float* base = g_b2 + ((size_t)(n * H1 + y) * W1 + x) * 64 + ci;
    float m = fmaxf(fmaxf(base[0], base[64]),
                    fmaxf(base[W1 * 64], base[W1 * 64 + 64]));
    __nv_bfloat16 h, l; bfsplit(m, h, l);
    size_t o = ((size_t)(q * 65 + i + 1) * 66 + j + 1) * 64 + ci;
    ((__nv_bfloat16*)g_poh)[o] = h;
    ((__nv_bfloat16*)g_pol)[o] = l;
}

// =====================================================================
// conv3/conv4 via mma.sync, bf16 3-pass.  Block 256 thr / 8 warps,
// tile M=64co x N=64px (63 valid), one row y, 9 taps.  Grid (63, 8).
// DO_LRN=false: conv3 -> padded fmt out.  DO_LRN=true: conv4 -> conv5 fmt.
// =====================================================================
#define C34_SMEM 83456   // A 2x16384 + slabs 2x25344

template<bool DO_LRN>
__global__ __launch_bounds__(256, 2) void conv34_mma(
    const uint4* __restrict__ inh, const uint4* __restrict__ inl,
    const uint4* __restrict__ wth, const uint4* __restrict__ wtl,
    const float* __restrict__ bias,
    __nv_bfloat16* __restrict__ outh, __nv_bfloat16* __restrict__ outl)
{
    extern __shared__ char sm[];
    const uint32_t sA    = s2u(sm);
    const uint32_t sSlab = sA + 32768;

    const int tid  = threadIdx.x;
    const int lane = tid & 31;
    const int wid  = tid >> 5;
    const int mw   = (wid & 3) * 16;
    const int nh   = wid >> 2;
    const int y = blockIdx.x, q = blockIdx.y;

    const int ar  = lane & 15;
    const int acp = lane >> 4;
    const int bxl = lane & 7;
    const int bp  = (lane >> 3) & 1;
    const int nb  = lane >> 4;

    float acc[4][4];
    #pragma unroll
    for (int nt = 0; nt < 4; nt++)
        #pragma unroll
        for (int j = 0; j < 4; j++) acc[nt][j] = 0.f;

    // load 3 slabs (rows y..y+2 in padded coords), hi+lo, swizzled
    for (int i = tid; i < 3168; i += 256) {
        int sel = i >= 1584;
        int j = sel ? i - 1584 : i;
        int ky = j / 528;
        int jj = j % 528;
        int r = jj >> 3, c = jj & 7;
        const uint4* src = (sel ? inl : inh) + ((size_t)(q * 65 + y + ky) * 66 + r) * 8;
        ((uint4*)(sm + 32768))[(size_t)sel * 1584 + ky * 528 + r * 8 + (c ^ (r & 7))] = src[c];
    }
    // prologue: A tap 0
    {
        #pragma unroll
        for (int i = 0; i < 2; i++) {
            CP16(sA + (tid + i * 256) * 16,        wth + tid + i * 256);
            CP16(sA + 8192 + (tid + i * 256) * 16, wtl + tid + i * 256);
        }
        CP_COMMIT;
        CP_WAIT0;
    }
    __syncthreads();

    #pragma unroll 1
    for (int t = 0; t < 9; t++) {
        const int ky = t / 3, kx = t % 3;
        const uint32_t bufA = sA + (uint32_t)(t & 1) * 16384;

        uint32_t Ah[4][4], Al[4][4];
        {
            const uint32_t rowoff = bufA + (uint32_t)(mw + ar) * 128;
            #pragma unroll
            for (int k = 0; k < 4; k++) {
                uint32_t ch = (uint32_t)(((2 * k + acp) ^ (ar & 7)) * 16);
                LDSM4(Ah[k], rowoff + ch);
                LDSM4(Al[k], rowoff + ch + 8192);
            }
        }
        {
            int tn = t + 1; if (tn > 8) tn = 8;
            uint32_t dA = sA + (uint32_t)((t + 1) & 1) * 16384;
            #pragma unroll
            for (int i = 0; i < 2; i++) {
                CP16(dA + (tid + i * 256) * 16,        wth + (size_t)tn * 512 + tid + i * 256);
                CP16(dA + 8192 + (tid + i * 256) * 16, wtl + (size_t)tn * 512 + tid + i * 256);
            }
            CP_COMMIT;
        }

        const uint32_t slabh = sSlab + (uint32_t)ky * 8448;
        const uint32_t slabl = slabh + 25344;
        const uint32_t rowbyte = (uint32_t)(kx + nh * 32 + nb * 8 + bxl) * 128;
        const uint32_t xorb = (uint32_t)((kx + bxl) & 7);
        #pragma unroll
        for (int k = 0; k < 4; k++) {
            const uint32_t ch = (uint32_t)(((uint32_t)(2 * k + bp) ^ xorb) * 16);
            #pragma unroll
            for (int p = 0; p < 2; p++) {
                const uint32_t off = rowbyte + (uint32_t)(p * 2048) + ch;
                uint32_t rh[4], rl[4];
                LDSM4(rh, slabh + off);
                MMA16816(acc[2 * p],     Ah[k], rh);
                MMA16816(acc[2 * p],     Al[k], rh);
                MMA16816(acc[2 * p + 1], Ah[k], rh + 2);
                MMA16816(acc[2 * p + 1], Al[k], rh + 2);
                LDSM4(rl, slabl + off);
                MMA16816(acc[2 * p],     Ah[k], rl);
                MMA16816(acc[2 * p + 1], Ah[k], rl + 2);
            }
        }

        CP_WAIT0;
        __syncthreads();
    }

    // epilogue: bias + relu into smem, (LRN), bf16-split store
    float* L = (float*)sm;
    {
        const int r0 = mw + (lane >> 2);
        const int r1 = r0 + 8;
        const float b0 = bias[r0];
        const float b1 = bias[r1];
        #pragma unroll
        for (int nt = 0; nt < 4; nt++) {
            const int px = nh * 32 + nt * 8 + 2 * (lane & 3);
            L[r0 * 65 + px]     = fmaxf(acc[nt][0] + b0, 0.f);
            L[r0 * 65 + px + 1] = fmaxf(acc[nt][1] + b0, 0.f);
            L[r1 * 65 + px]     = fmaxf(acc[nt][2] + b1, 0.f);
            L[r1 * 65 + px + 1] = fmaxf(acc[nt][3] + b1, 0.f);
        }
    }
    __syncthreads();
    {
        const int co = tid >> 2;
        const int pxb = (tid & 3) * 16;
        #pragma unroll
        for (int e = 0; e < 16; e++) {
            int px = pxb + e;
            if (px >= 63) continue;
            float cur = L[co * 65 + px];
            if (DO_LRN) {
                float pv = co ? L[(co - 1) * 65 + px] : 0.f;
                float dnm = 1.f + 1e-5f * (pv * pv + cur * cur);
                cur = cur * powf(dnm, -0.75f);
            }
            __nv_bfloat16 h, l; bfsplit(cur, h, l);
            size_t o;
            if (DO_LRN)  // conv5 input format [q][y63][x64][ci64]
                o = ((size_t)(q * 63 + y) * 64 + px) * 64 + co;
            else         // padded format [q][y'65][x'66][ci64]
                o = ((size_t)(q * 65 + y + 1) * 66 + px + 1) * 64 + co;
            outh[o] = h;
            outl[o] = l;
        }
    }
}

// =====================================================================
// transform: w5 -> swizzled tiles (vectorized)
// =====================================================================
__global__ void tr_w5_kernel(const float* __restrict__ w5)
{
    int id = blockIdx.x * 256 + threadIdx.x;
    if (id >= 1024 * 8 * 256) return;
    int tap = id & 255;
    int j   = (id >> 8) & 7;
    int co  = id >> 11;

    uint32_t hh[4], ll[4];
    #pragma unroll
    for (int p = 0; p < 4; p++) {
        float v0 = w5[(co * 64 + j * 8 + 2 * p)     * 256 + tap];
        float v1 = w5[(co * 64 + j * 8 + 2 * p + 1) * 256 + tap];
        __nv_bfloat16 h0, l0, h1, l1;
        bfsplit(v0, h0, l0); bfsplit(v1, h1, l1);
        __nv_bfloat162 ph; ph.x = h0; ph.y = h1;
        hh[p] = *(uint32_t*)&ph;
        ll[p] = bfpack(__bfloat162float(l0), __bfloat162float(l1));
    }
    int cotile = co >> 7, co128 = co & 127;
    uint32_t off = swz((uint32_t)(co128 * 128 + j * 16)) >> 4;
    size_t base = (size_t)(cotile * 256 + tap) * 1024 + off;
    g_wh[base] = make_uint4(hh[0], hh[1], hh[2], hh[3]);
    g_wl[base] = make_uint4(ll[0], ll[1], ll[2], ll[3]);
}

// =====================================================================
// transform: w6 -> swizzled tiles
// =====================================================================
__global__ void tr_w6_kernel(const float* __restrict__ w6)
{
    int id = blockIdx.x * 256 + threadIdx.x;
    if (id >= 1024 * 16 * 8) return;
    int jj = id & 7;
    int kc = (id >> 3) & 15;
    int co = id >> 7;

    uint32_t hh[4], ll[4];
    #pragma unroll
    for (int p = 0; p < 4; p++) {
        float v0 = w6[co * 1024 + kc * 64 + jj * 8 + 2 * p];
        float v1 = w6[co * 1024 + kc * 64 + jj * 8 + 2 * p + 1];
        __nv_bfloat16 h0, l0, h1, l1;
        bfsplit(v0, h0, l0); bfsplit(v1, h1, l1);
        __nv_bfloat162 ph; ph.x = h0; ph.y = h1;
        hh[p] = *(uint32_t*)&ph;
        ll[p] = bfpack(__bfloat162float(l0), __bfloat162float(l1));
    }
    int cotile = co >> 7, co128 = co & 127;
    uint32_t off = swz((uint32_t)(co128 * 128 + jj * 16)) >> 4;
    size_t base = (size_t)(cotile * 16 + kc) * 1024 + off;
    g_w6h[base] = make_uint4(hh[0], hh[1], hh[2], hh[3]);
    g_w6l[base] = make_uint4(ll[0], ll[1], ll[2], ll[3]);
}

// =====================================================================
// conv5 via mma.sync (3-row tiles); epilogue writes bf16-split [q][px][co]
// =====================================================================
#define C5_ABUF 32768
#define C5_SLAB 65536
#define C5_SMEM 114688

__global__ __launch_bounds__(256, 1) void conv5_mma(
    const float* __restrict__ bias)
{
    extern __shared__ char sm[];
    const uint32_t sA    = s2u(sm);
    const uint32_t sSlab = sA + C5_SLAB;
    char* Slab = sm + C5_SLAB;

    const int tid  = threadIdx.x;
    const int lane = tid & 31;
    const int wid  = tid >> 5;
    const int yblk = blockIdx.x, cotile = blockIdx.y, q = blockIdx.z;
    const int Y0 = yblk * 3;
    const int m  = wid * 16;

    const int ar  = lane & 15;
    const int acp = lane >> 4;
    const int bxl = lane & 7;
    const int bp  = (lane >> 3) & 1;
    const int nb  = lane >> 4;
    const uint32_t nbadd = (uint32_t)nb * 1024;

    float acc[3][6][4];
    #pragma unroll
    for (int r = 0; r < 3; r++)
        #pragma unroll
        for (int nt = 0; nt < 6; nt++)
            #pragma unroll
            for (int j = 0; j < 4; j++) acc[r][nt][j] = 0.f;

    {
        const uint4* sh = g_wh + (size_t)(cotile * 256) * 1024;
        const uint4* sl = g_wl + (size_t)(cotile * 256) * 1024;
        #pragma unroll
        for (int i = 0; i < 4; i++) {
            CP16(sA + (tid + i * 256) * 16,         sh + tid + i * 256);
            CP16(sA + 16384 + (tid + i * 256) * 16, sl + tid + i * 256);
        }
        CP_COMMIT;
        CP_WAIT0;
    }

    #pragma unroll 1
    for (int t = 0; t < 256; t++) {
        const int kx = t & 15;
        if (kx == 0) {
            const int ky = t >> 4;
            for (int i = tid; i < 3072; i += 256) {
                int s = i >> 9;
                int j = i & 511;
                int x = j >> 3, c = j & 7;
                int rr = s >> 1, sel = s & 1;
                const uint4* src = (sel ? g_tl : g_th) + (size_t)(q * 63 + Y0 + ky + rr) * 512;
                ((uint4*)Slab)[s * 512 + x * 8 + (c ^ (x & 7))] = src[j];
            }
            __syncthreads();
        }

        const uint32_t bufA = sA + (uint32_t)(t & 1) * C5_ABUF;

        uint32_t Ah[4][4], Al[4][4];
        {
            const uint32_t rowoff = bufA + (uint32_t)(m + ar) * 128;
            #pragma unroll
            for (int k = 0; k < 4; k++) {
                uint32_t ch = (uint32_t)(((2 * k + acp) ^ (ar & 7)) * 16);
                LDSM4(Ah[k], rowoff + ch);
                LDSM4(Al[k], rowoff + ch + 16384);
            }
        }

        {
            int tn = t + 1; if (tn > 255) tn = 255;
            const uint4* sh = g_wh + (size_t)(cotile * 256 + tn) * 1024;
            const uint4* sl = g_wl + (size_t)(cotile * 256 + tn) * 1024;
            uint32_t dA = sA + (uint32_t)((t + 1) & 1) * C5_ABUF;
            #pragma unroll
            for (int i = 0; i < 4; i++) {
                CP16(dA + (tid + i * 256) * 16,         sh + tid + i * 256);
                CP16(dA + 16384 + (tid + i * 256) * 16, sl + tid + i * 256);
            }
            CP_COMMIT;
        }

        const uint32_t rowbyte = (uint32_t)(kx + bxl) * 128;
        const uint32_t xorb = (uint32_t)((kx + bxl) & 7);
        #pragma unroll
        for (int rr = 0; rr < 3; rr++) {
            const uint32_t hb = sSlab + (uint32_t)(2 * rr) * 8192 + rowbyte + nbadd;
            const uint32_t lb = hb + 8192;
            #pragma unroll
            for (int k = 0; k < 4; k++) {
                const uint32_t ch = (uint32_t)(((uint32_t)(2 * k + bp) ^ xorb) * 16);
                #pragma unroll
                for (int p = 0; p < 3; p++) {
                    const uint32_t off = (uint32_t)(p * 2048) + ch;
                    uint32_t rh[4], rl[4];
                    LDSM4(rh, hb + off);
                    MMA16816(acc[rr][2 * p],     Ah[k], rh);
                    MMA16816(acc[rr][2 * p],     Al[k], rh);
                    MMA16816(acc[rr][2 * p + 1], Ah[k], rh + 2);
                    MMA16816(acc[rr][2 * p + 1], Al[k], rh + 2);
                    LDSM4(rl, lb + off);
                    MMA16816(acc[rr][2 * p],     Ah[k], rl);
                    MMA16816(acc[rr][2 * p + 1], Ah[k], rl + 2);
                }
            }
        }

        CP_WAIT0;
        __syncthreads();
    }

    // epilogue: bias+relu, bf16-split store to [q][px][co]
    {
        __nv_bfloat16* eh = (__nv_bfloat16*)g_eh;
        __nv_bfloat16* el = (__nv_bfloat16*)g_el;
        const int co0 = cotile * 128 + m + (lane >> 2);
        const int co1 = co0 + 8;
        const float b0 = bias[co0];
        const float b1 = bias[co1];
        #pragma unroll
        for (int rr = 0; rr < 3; rr++) {
            const int gy = Y0 + rr;
            #pragma unroll
            for (int nt = 0; nt < 6; nt++) {
                const int px = nt * 8 + 2 * (lane & 3);
                size_t base = ((size_t)(q * 2304 + gy * 48 + px)) * 1024;
                float v00 = fmaxf(acc[rr][nt][0] + b0, 0.f);
                float v01 = fmaxf(acc[rr][nt][1] + b0, 0.f);
                float v10 = fmaxf(acc[rr][nt][2] + b1, 0.f);
                float v11 = fmaxf(acc[rr][nt][3] + b1, 0.f);
                __nv_bfloat16 h, l;
                bfsplit(v00, h, l); eh[base + co0] = h;        el[base + co0] = l;
                bfsplit(v01, h, l); eh[base + 1024 + co0] = h; el[base + 1024 + co0] = l;
                bfsplit(v10, h, l); eh[base + co1] = h;        el[base + co1] = l;
                bfsplit(v11, h, l); eh[base + 1024 + co1] = h; el[base + 1024 + co1] = l;
            }
        }
    }
}

// =====================================================================
// conv6 via mma.sync (unchanged)
// =====================================================================
#define C6_BUF  65536
#define C6_SMEM 131072

__global__ __launch_bounds__(512, 1) void conv6_mma(
    const float* __restrict__ bias, float* __restrict__ out)
{
    extern __shared__ char sm[];
    const uint32_t sB0 = s2u(sm);

    const int tid  = threadIdx.x;
    const int lane = tid & 31;
    const int wid  = tid >> 5;
    const int mw   = (wid & 7) * 16;
    const int nh   = wid >> 3;
    const int bx = blockIdx.x, cotile = blockIdx.y, q = blockIdx.z;
    const int px0 = bx * 128;

    const int ar  = lane & 15;
    const int acp = lane >> 4;
    const int bxl = lane & 7;
    const int bp  = (lane >> 3) & 1;
    const int nb  = lane >> 4;

    float acc[8][4];
    #pragma unroll
    for (int nt = 0; nt < 8; nt++)
        #pragma unroll
        for (int j = 0; j < 4; j++) acc[nt][j] = 0.f;

    auto load_chunk = [&](int kc, uint32_t dbuf) {
        const uint4* ah = g_w6h + (size_t)(cotile * 16 + kc) * 1024;
        const uint4* al = g_w6l + (size_t)(cotile * 16 + kc) * 1024;
        #pragma unroll
        for (int r = 0; r < 2; r++) {
            int i = tid + r * 512;
            CP16(dbuf + i * 16,         ah + i);
            CP16(dbuf + 16384 + i * 16, al + i);
        }
        #pragma unroll
        for (int r = 0; r < 2; r++) {
            int j = tid + r * 512;
            int n = j >> 3, c = j & 7;
            size_t src = (size_t)(q * 2304 + px0 + n) * 128 + kc * 8 + c;
            uint32_t dst = (uint32_t)(n * 128 + (c ^ (n & 7)) * 16);
            CP16(dbuf + 32768 + dst, g_eh + src);
            CP16(dbuf + 49152 + dst, g_el + src);
        }
        CP_COMMIT;
    };

    load_chunk(0, sB0);
    CP_WAIT0;
    __syncthreads();

    #pragma unroll 1
    for (int kc = 0; kc < 16; kc++) {
        const uint32_t buf = sB0 + (uint32_t)(kc & 1) * C6_BUF;

        uint32_t Ah[4][4], Al[4][4];
        {
            const uint32_t rowoff = buf + (uint32_t)(mw + ar) * 128;
            #pragma unroll
            for (int k = 0; k < 4; k++) {
                uint32_t ch = (uint32_t)(((2 * k + acp) ^ (ar & 7)) * 16);
                LDSM4(Ah[k], rowoff + ch);
                LDSM4(Al[k], rowoff + ch + 16384);
            }
        }

        {
            int kn = kc + 1; if (kn > 15) kn = 15;
            load_chunk(kn, sB0 + (uint32_t)((kc + 1) & 1) * C6_BUF);
        }

        const uint32_t hb = sB0 + (uint32_t)(kc & 1) * C6_BUF + 32768
                            + (uint32_t)(nh * 64 + nb * 8 + bxl) * 128;
        const uint32_t lb = hb + 16384;
        #pragma unroll
        for (int k = 0; k < 4; k++) {
            const uint32_t ch = (uint32_t)(((uint32_t)(2 * k + bp) ^ (uint32_t)bxl) * 16);
            #pragma unroll
            for (int p = 0; p < 4; p++) {
                const uint32_t off = (uint32_t)(p * 2048) + ch;
                uint32_t rh[4], rl[4];
                LDSM4(rh, hb + off);
                MMA16816(acc[2 * p],     Ah[k], rh);
                MMA16816(acc[2 * p],     Al[k], rh);
                MMA16816(acc[2 * p + 1], Ah[k], rh + 2);
                MMA16816(acc[2 * p + 1], Al[k], rh + 2);
                LDSM4(rl, lb + off);
                MMA16816(acc[2 * p],     Ah[k], rl);
                MMA16816(acc[2 * p + 1], Ah[k], rl + 2);
            }
        }

        CP_WAIT0;
        __syncthreads();
    }

    {
        const int co0 = cotile * 128 + mw + (lane >> 2);
        const int co1 = co0 + 8;
        const float b0 = bias[co0];
        const float b1 = bias[co1];
        float* o0 = out + (size_t)(q * 1024 + co0) * PX5;
        float* o1 = out + (size_t)(q * 1024 + co1) * PX5;
        #pragma unroll
        for (int nt = 0; nt < 8; nt++) {
            const int px = px0 + nh * 64 + nt * 8 + 2 * (lane & 3);
            o0[px]     = fmaxf(acc[nt][0] + b0, 0.f);
            o0[px + 1] = fmaxf(acc[nt][1] + b0, 0.f);
            o1[px]     = fmaxf(acc[nt][2] + b1, 0.f);
            o1[px + 1] = fmaxf(acc[nt][3] + b1, 0.f);
        }
    }
}

// =====================================================================
// conv7 + sigmoid + interweave
// =====================================================================
__global__ void conv7_kernel(const float* __restrict__ in,
                             const float* __restrict__ w7,
                             const float* __restrict__ b7,
                             float* __restrict__ out)
{
    int id = blockIdx.x * 256 + threadIdx.x;
    if (id >= NQ * PX5) return;
    int hw = id % PX5;
    int q  = id / PX5;
    float acc = b7[0];
    const float* p = in + (size_t)q * 1024 * PX5 + hw;
    #pragma unroll 8
    for (int ci = 0; ci < 1024; ci++)
        acc = fmaf(p[ci * PX5], w7[ci], acc);
    float s = 1.f / (1.f + expf(-acc));
    int h = hw / HO, wv = hw % HO;
    int n = q & 1, ss = (q >> 1) & 1, t = q >> 2;
    out[n * 96 * 96 + (2 * h + ss) * 96 + (2 * wv + t)] = s;
}

// =====================================================================
// launch
// =====================================================================
extern "C" void kernel_launch(void* const* d_in, const int* in_sizes, int n_in,
                              void* d_out, int out_size)
{
    const float* x  = (const float*)d_in[0];
    const float* w1 = (const float*)d_in[1];  const float* b1 = (const float*)d_in[2];
    const float* w2 = (const float*)d_in[3];  const float* b2 = (const float*)d_in[4];
    const float* w3 = (const float*)d_in[5];  const float* b3 = (const float*)d_in[6];
    const float* w4 = (const float*)d_in[7];  const float* b4 = (const float*)d_in[8];
    const float* w5 = (const float*)d_in[9];  const float* b5 = (const float*)d_in[10];
    const float* w6 = (const float*)d_in[11]; const float* b6 = (const float*)d_in[12];
    const float* w7 = (const float*)d_in[13]; const float* b7 = (const float*)d_in[14];

    void *pa2, *pb2, *pf;
    void *pw2h, *pw2l, *pw3h, *pw3l, *pw4h, *pw4l;
    void *ppoh, *ppol, *pc3h, *pc3l, *pth, *ptl;
    cudaGetSymbolAddress(&pa2, g_a2);
    cudaGetSymbolAddress(&pb2, g_b2);
    cudaGetSymbolAddress(&pf, g_f);
    cudaGetSymbolAddress(&pw2h, g_w2h); cudaGetSymbolAddress(&pw2l, g_w2l);
    cudaGetSymbolAddress(&pw3h, g_w3h); cudaGetSymbolAddress(&pw3l, g_w3l);
    cudaGetSymbolAddress(&pw4h, g_w4h); cudaGetSymbolAddress(&pw4l, g_w4l);
    cudaGetSymbolAddress(&ppoh, g_poh); cudaGetSymbolAddress(&ppol, g_pol);
    cudaGetSymbolAddress(&pc3h, g_c3h); cudaGetSymbolAddress(&pc3l, g_c3l);
    cudaGetSymbolAddress(&pth, g_th);   cudaGetSymbolAddress(&ptl, g_tl);

    cudaFuncSetAttribute(conv5_mma, cudaFuncAttributeMaxDynamicSharedMemorySize, C5_SMEM);
    cudaFuncSetAttribute(conv6_mma, cudaFuncAttributeMaxDynamicSharedMemorySize, C6_SMEM);
    cudaFuncSetAttribute(conv2_mma, cudaFuncAttributeMaxDynamicSharedMemorySize, C2_SMEM);
    cudaFuncSetAttribute(conv34_mma<false>, cudaFuncAttributeMaxDynamicSharedMemorySize, C34_SMEM);
    cudaFuncSetAttribute(conv34_mma<true>,  cudaFuncAttributeMaxDynamicSharedMemorySize, C34_SMEM);

    // weight transforms (independent)
    tr_w5_kernel<<<(1024 * 8 * 256 + 255) / 256, 256>>>(w5);
    tr_w6_kernel<<<(1024 * 16 * 8 + 255) / 256, 256>>>(w6);
    tr_wsq_kernel<<<(64 * 8 * 25 + 255) / 256, 256>>>(w2, (uint4*)pw2h, (uint4*)pw2l, 25);
    tr_wsq_kernel<<<(64 * 8 * 9 + 255) / 256, 256>>>(w3, (uint4*)pw3h, (uint4*)pw3l, 9);
    tr_wsq_kernel<<<(64 * 8 * 9 + 255) / 256, 256>>>(w4, (uint4*)pw4h, (uint4*)pw4l, 9);

    // conv1 -> pad/split -> conv2 (mma + LRN)
    conv1_kernel<<<dim3(8, 8, NB), 256>>>(x, w1, b1, (float*)pa2);
    tr_a_kernel<<<(NB * 132 * 136 * 64 + 255) / 256, 256>>>();
    conv2_mma<<<dim3(2, 128, 2), 256, C2_SMEM>>>(b2, (float*)pb2);

    // pool (emits padded bf16-split), conv3, conv4 (emits conv5 input fmt)
    pool_kernel<<<(NQ * 63 * 63 * 64 + 255) / 256, 256>>>();
    conv34_mma<false><<<dim3(63, NQ), 256, C34_SMEM>>>(
        (const uint4*)ppoh, (const uint4*)ppol, (const uint4*)pw3h, (const uint4*)pw3l,
        b3, (__nv_bfloat16*)pc3h, (__nv_bfloat16*)pc3l);
    conv34_mma<true><<<dim3(63, NQ), 256, C34_SMEM>>>(
        (const uint4*)pc3h, (const uint4*)pc3l, (const uint4*)pw4h, (const uint4*)pw4l,
        b4, (__nv_bfloat16*)pth, (__nv_bfloat16*)ptl);

    // conv5 (writes transposed bf16-split directly), conv6, conv7
    conv5_mma<<<dim3(16, 8, NQ), 256, C5_SMEM>>>(b5);
    conv6_mma<<<dim3(18, 8, NQ), 512, C6_SMEM>>>(b6, (float*)pf);
    conv7_kernel<<<(NQ * PX5 + 255) / 256, 256>>>((float*)pf, w7, b7, (float*)d_out);
}

// round 17
// speedup vs baseline: 4.0916x; 1.0260x over previous
#include <cuda_runtime.h>
#include <cuda_bf16.h>
#include <math.h>
#include <stdint.h>

// ---------------- problem constants ----------------
#define NB   2
#define H1   128
#define W1   128
#define HP   63
#define NQ   8
#define HO   48
#define PX5  2304

typedef unsigned long long u64;

// ---------------- f32x2 helpers ----------------
__device__ __forceinline__ u64 pack2(float lo, float hi) {
    u64 r; asm("mov.b64 %0, {%1, %2};" : "=l"(r) : "f"(lo), "f"(hi)); return r;
}
__device__ __forceinline__ void unpack2(u64 v, float& lo, float& hi) {
    asm("mov.b64 {%0, %1}, %2;" : "=f"(lo), "=f"(hi) : "l"(v));
}
__device__ __forceinline__ void fma2(u64& d, u64 a, u64 b) {
    asm("fma.rn.f32x2 %0, %1, %2, %0;" : "+l"(d) : "l"(a), "l"(b));
}

// ---------------- intermediate buffers ----------------
__device__ float g_a2[NB*H1*W1*64];    // conv1 out, channel-last
__device__ float g_b2[NB*H1*W1*64];    // conv2+LRN out, channel-last
__device__ float g_part[NQ*PX5*8];     // conv6/7 fused partials [q][px][cotile]

// bf16-split staging
__device__ uint4 g_wh[8*256*1024];     // w5 tiles [cotile][tap] 16KB swizzled, hi
__device__ uint4 g_wl[8*256*1024];     // lo
__device__ uint4 g_th[258048];         // conv5 input [q][y63][x64][ci64] hi (conv4 writes)
__device__ uint4 g_tl[258048];         // lo
__device__ uint4 g_w6h[131072];        // w6 tiles [cotile8][kc16] hi
__device__ uint4 g_w6l[131072];        // lo
__device__ uint4 g_eh[2359296];        // conv5 out [q][px2304][co1024] bf16 hi
__device__ uint4 g_el[2359296];        // lo
__device__ uint4 g_w2h[25*512];        // w2 tiles [tap25][64co x 64ci] hi
__device__ uint4 g_w2l[25*512];        // lo
__device__ uint4 g_tah[287424];        // conv2 input [n][y'132][x'136][ci64] hi
__device__ uint4 g_tal[287424];        // lo
__device__ uint4 g_poh[274560];        // pool out [q][y'65][x'66][ci64] hi (borders stay 0)
__device__ uint4 g_pol[274560];        // lo
__device__ uint4 g_c3h[274560];        // conv3 out, same padded fmt
__device__ uint4 g_c3l[274560];        // lo
__device__ uint4 g_w3h[9*512];         // w3 tiles [tap9][64co x 64ci] hi
__device__ uint4 g_w3l[9*512];
__device__ uint4 g_w4h[9*512];
__device__ uint4 g_w4l[9*512];

// ---------------- smem addr helper ----------------
__device__ __forceinline__ uint32_t s2u(const void* p) {
    uint32_t a;
    asm("{ .reg .u64 t; cvta.to.shared.u64 t, %1; cvt.u32.u64 %0, t; }" : "=r"(a) : "l"(p));
    return a;
}

// ---------------- portable tensor-core primitives (sm_80+) ----------------
#define LDSM4(r, addr) \
    asm volatile("ldmatrix.sync.aligned.m8n8.x4.shared.b16 {%0,%1,%2,%3}, [%4];" \
        : "=r"((r)[0]), "=r"((r)[1]), "=r"((r)[2]), "=r"((r)[3]) : "r"(addr))

#define MMA16816(c, a, b) \
    asm volatile("mma.sync.aligned.m16n8k16.row.col.f32.bf16.bf16.f32 " \
        "{%0,%1,%2,%3}, {%4,%5,%6,%7}, {%8,%9}, {%0,%1,%2,%3};" \
        : "+f"((c)[0]), "+f"((c)[1]), "+f"((c)[2]), "+f"((c)[3]) \
        : "r"((a)[0]), "r"((a)[1]), "r"((a)[2]), "r"((a)[3]), \
          "r"((b)[0]), "r"((b)[1]))

#define CP16(dst, src) \
    asm volatile("cp.async.cg.shared.global [%0], [%1], 16;" :: "r"(dst), "l"(src))
#define CP_COMMIT asm volatile("cp.async.commit_group;")
#define CP_WAIT0  asm volatile("cp.async.wait_group 0;")

__device__ __forceinline__ uint32_t swz(uint32_t x) { return x ^ ((x >> 3) & 0x70); }

__device__ __forceinline__ uint32_t bfpack(float a, float b) {
    __nv_bfloat162 p;
    p.x = __float2bfloat16(a);
    p.y = __float2bfloat16(b);
    return *(uint32_t*)&p;
}
__device__ __forceinline__ void bfsplit(float v, __nv_bfloat16& h, __nv_bfloat16& l) {
    h = __float2bfloat16(v);
    l = __float2bfloat16(v - __bfloat162float(h));
}

// =====================================================================
// conv1 (7x7, 1->64), fp32 f32x2, channel-last out
// =====================================================================
__global__ __launch_bounds__(256, 2) void conv1_kernel(
    const float* __restrict__ in, const float* __restrict__ w,
    const float* __restrict__ bias, float* __restrict__ out)
{
    constexpr int K = 7, PH = 22;
    __shared__ float patch[PH * 48];
    __shared__ u64   wsm2[64 * 49];

    const int tid   = threadIdx.x;
    const int cog   = tid >> 5;
    const int pxt   = tid & 31;
    const int col   = pxt & 15;
    const int rbase = pxt >> 4;
    const int x0 = blockIdx.x * 16;
    const int y0 = blockIdx.y * 16;
    const int n  = blockIdx.z;

    u64 acc2[8][4];
    #pragma unroll
    for (int c = 0; c < 8; c++)
        #pragma unroll
        for (int j = 0; j < 4; j++) acc2[c][j] = 0ull;

    for (int idx = tid; idx < PH * PH; idx += 256) {
        int rr = idx / PH, cc = idx % PH;
        int gy = y0 - 3 + rr, gx = x0 - 3 + cc;
        float v = 0.f;
        if (gy >= 0 && gy < H1 && gx >= 0 && gx < W1)
            v = in[(n * H1 + gy) * W1 + gx];
        patch[rr * 48 + cc] = v;
    }
    for (int idx = tid; idx < 64 * 49; idx += 256) {
        float wv = w[idx];
        wsm2[idx] = pack2(wv, wv);
    }
    __syncthreads();

    const u64* wrow = &wsm2[cog * 8 * 49];
    #pragma unroll 1
    for (int ky = 0; ky < K; ky++) {
        #pragma unroll
        for (int kx = 0; kx < K; kx++) {
            float v[8];
            #pragma unroll
            for (int i = 0; i < 8; i++)
                v[i] = patch[(rbase + 2 * i + ky) * 48 + col + kx];
            u64 vp[4];
            #pragma unroll
            for (int j = 0; j < 4; j++)
                vp[j] = pack2(v[2 * j], v[2 * j + 1]);
            #pragma unroll
            for (int c = 0; c < 8; c++) {
                u64 wp = wrow[c * 49 + ky * K + kx];
                #pragma unroll
                for (int j = 0; j < 4; j++)
                    fma2(acc2[c][j], wp, vp[j]);
            }
        }
    }

    #pragma unroll
    for (int c = 0; c < 8; c++) {
        int co = cog * 8 + c;
        float bb = bias[co];
        #pragma unroll
        for (int j = 0; j < 4; j++) {
            float lo, hi;
            unpack2(acc2[c][j], lo, hi);
            int y = y0 + rbase + 4 * j;
            int x = x0 + col;
            out[((n * H1 + y) * W1 + x) * 64 + co]       = fmaxf(lo + bb, 0.f);
            out[((n * H1 + y + 2) * W1 + x) * 64 + co]   = fmaxf(hi + bb, 0.f);
        }
    }
}

// =====================================================================
// transform: conv1 out -> padded transposed bf16 split [n][y'132][x'136][ci]
// =====================================================================
__global__ void tr_a_kernel()
{
    int id = blockIdx.x * 256 + threadIdx.x;
    if (id >= NB * 132 * 136 * 64) return;
    int ci = id & 63;
    int x  = (id >> 6) % 136;
    int r  = (id >> 6) / 136;
    int y  = r % 132;
    int n  = r / 132;
    float v = 0.f;
    if (y >= 2 && y < 130 && x >= 2 && x < 130)
        v = g_a2[((n * H1 + (y - 2)) * W1 + (x - 2)) * 64 + ci];
    __nv_bfloat16 h, l; bfsplit(v, h, l);
    ((__nv_bfloat16*)g_tah)[id] = h;
    ((__nv_bfloat16*)g_tal)[id] = l;
}

// =====================================================================
// generic square-weight transform -> swizzled tiles [tap][64co x 64ci] hi/lo
// =====================================================================
__global__ void tr_wsq_kernel(const float* __restrict__ w, uint4* dh, uint4* dl, int ntap)
{
    int id = blockIdx.x * 256 + threadIdx.x;
    if (id >= 64 * 8 * ntap) return;
    int tap = id % ntap;
    int j   = (id / ntap) & 7;
    int co  = id / (8 * ntap);

    uint32_t hh[4], ll[4];
    #pragma unroll
    for (int p = 0; p < 4; p++) {
        float v0 = w[(co * 64 + j * 8 + 2 * p)     * ntap + tap];
        float v1 = w[(co * 64 + j * 8 + 2 * p + 1) * ntap + tap];
        __nv_bfloat16 h0, l0, h1, l1;
        bfsplit(v0, h0, l0); bfsplit(v1, h1, l1);
        __nv_bfloat162 ph; ph.x = h0; ph.y = h1;
        hh[p] = *(uint32_t*)&ph;
        ll[p] = bfpack(__bfloat162float(l0), __bfloat162float(l1));
    }
    uint32_t off = swz((uint32_t)(co * 128 + j * 16)) >> 4;
    size_t base = (size_t)tap * 512 + off;
    dh[base] = make_uint4(hh[0], hh[1], hh[2], hh[3]);
    dl[base] = make_uint4(ll[0], ll[1], ll[2], ll[3]);
}

// =====================================================================
// conv2 via mma.sync + fused LRN
// =====================================================================
#define C2_SLAB  32768
#define C2_SMEM  119808

__global__ __launch_bounds__(256, 1) void conv2_mma(
    const float* __restrict__ bias, float* __restrict__ out)
{
    extern __shared__ char sm[];
    const uint32_t sA    = s2u(sm);
    const uint32_t sSlab = sA + C2_SLAB;

    const int tid  = threadIdx.x;
    const int lane = tid & 31;
    const int wid  = tid >> 5;
    const int mw   = (wid & 3) * 16;
    const int nh   = wid >> 2;
    const int xh = blockIdx.x, y = blockIdx.y, n = blockIdx.z;

    const int ar  = lane & 15;
    const int acp = lane >> 4;
    const int bxl = lane & 7;
    const int bp  = (lane >> 3) & 1;
    const int nb  = lane >> 4;

    float acc[4][4];
    #pragma unroll
    for (int nt = 0; nt < 4; nt++)
        #pragma unroll
        for (int j = 0; j < 4; j++) acc[nt][j] = 0.f;

    for (int i = tid; i < 5440; i += 256) {
        int sel = i >= 2720;
        int j = sel ? i - 2720 : i;
        int ky = j / 544;
        int jj = j % 544;
        int r = jj >> 3, c = jj & 7;
        const uint4* src = (sel ? g_tal : g_tah)
            + ((size_t)(n * 132 + y + ky) * 136 + xh * 64 + r) * 8;
        ((uint4*)(sm + C2_SLAB))[(size_t)sel * 2720 + ky * 544 + r * 8 + (c ^ (r & 7))] = src[c];
    }
    {
        #pragma unroll
        for (int i = 0; i < 2; i++) {
            CP16(sA + (tid + i * 256) * 16,        g_w2h + tid + i * 256);
            CP16(sA + 8192 + (tid + i * 256) * 16, g_w2l + tid + i * 256);
        }
        CP_COMMIT;
        CP_WAIT0;
    }
    __syncthreads();

    #pragma unroll 1
    for (int t = 0; t < 25; t++) {
        const int ky = t / 5, kx = t % 5;
        const uint32_t bufA = sA + (uint32_t)(t & 1) * 16384;

        uint32_t Ah[4][4], Al[4][4];
        {
            const uint32_t rowoff = bufA + (uint32_t)(mw + ar) * 128;
            #pragma unroll
            for (int k = 0; k < 4; k++) {
                uint32_t ch = (uint32_t)(((2 * k + acp) ^ (ar & 7)) * 16);
                LDSM4(Ah[k], rowoff + ch);
                LDSM4(Al[k], rowoff + ch + 8192);
            }
        }
        {
            int tn = t + 1; if (tn > 24) tn = 24;
            uint32_t dA = sA + (uint32_t)((t + 1) & 1) * 16384;
            #pragma unroll
            for (int i = 0; i < 2; i++) {
                CP16(dA + (tid + i * 256) * 16,        g_w2h + (size_t)tn * 512 + tid + i * 256);
                CP16(dA + 8192 + (tid + i * 256) * 16, g_w2l + (size_t)tn * 512 + tid + i * 256);
            }
            CP_COMMIT;
        }

        const uint32_t slabh = sSlab + (uint32_t)ky * 8704;
        const uint32_t slabl = slabh + 43520;
        const uint32_t rowbyte = (uint32_t)(kx + nh * 32 + nb * 8 + bxl) * 128;
        const uint32_t xorb = (uint32_t)((kx + bxl) & 7);
        #pragma unroll
        for (int k = 0; k < 4; k++) {
            const uint32_t ch = (uint32_t)(((uint32_t)(2 * k + bp) ^ xorb) * 16);
            #pragma unroll
            for (int p = 0; p < 2; p++) {
                const uint32_t off = rowbyte + (uint32_t)(p * 2048) + ch;
                uint32_t rh[4], rl[4];
                LDSM4(rh, slabh + off);
                MMA16816(acc[2 * p],     Ah[k], rh);
                MMA16816(acc[2 * p],     Al[k], rh);
                MMA16816(acc[2 * p + 1], Ah[k], rh + 2);
                MMA16816(acc[2 * p + 1], Al[k], rh + 2);
                LDSM4(rl, slabl + off);
                MMA16816(acc[2 * p],     Ah[k], rl);
                MMA16816(acc[2 * p + 1], Ah[k], rl + 2);
            }
        }

        CP_WAIT0;
        __syncthreads();
    }

    float* L = (float*)sm;
    {
        const int r0 = mw + (lane >> 2);
        const int r1 = r0 + 8;
        const float b0 = bias[r0];
        const float b1 = bias[r1];
        #pragma unroll
        for (int nt = 0; nt < 4; nt++) {
            const int px = nh * 32 + nt * 8 + 2 * (lane & 3);
            L[r0 * 65 + px]     = fmaxf(acc[nt][0] + b0, 0.f);
            L[r0 * 65 + px + 1] = fmaxf(acc[nt][1] + b0, 0.f);
            L[r1 * 65 + px]     = fmaxf(acc[nt][2] + b1, 0.f);
            L[r1 * 65 + px + 1] = fmaxf(acc[nt][3] + b1, 0.f);
        }
    }
    __syncthreads();
    {
        const int co = tid >> 2;
        const int pxb = (tid & 3) * 16;
        float* o = out + ((size_t)(n * H1 + y) * W1 + xh * 64 + pxb) * 64 + co;
        #pragma unroll
        for (int e = 0; e < 16; e++) {
            int px = pxb + e;
            float cur = L[co * 65 + px];
            float pv  = co ? L[(co - 1) * 65 + px] : 0.f;
            float dnm = 1.f + 1e-5f * (pv * pv + cur * cur);
            o[e * 64] = cur * powf(dnm, -0.75f);
        }
    }
}

// =====================================================================
// crops + maxpool -> padded bf16-split channel-last [q][y'65][x'66][ci]
// =====================================================================
__global__ void pool_kernel()
{
    int id = blockIdx.x * 256 + threadIdx.x;
    if (id >= NQ * 63 * 63 * 64) return;
    int ci = id & 63;
    int j = (id >> 6) % 63;
    int r = (id >> 6) / 63;
    int i = r % 63;
    int q = r / 63;
    int n = q & 1;
    int crop = q >> 1;
    int dy = crop & 1;
    int dx = crop >> 1;
    int y = dy + 2 * i, x = dx + 2 * j;
    const float* base = g_b2 + ((size_t)(n * H1 + y) * W1 + x) * 64 + ci;
    float m = fmaxf(fmaxf(base[0], base[64]),
                    fmaxf(base[W1 * 64], base[W1 * 64 + 64]));
    __nv_bfloat16 h, l; bfsplit(m, h, l);
    size_t o = ((size_t)(q * 65 + i + 1) * 66 + j + 1) * 64 + ci;
    ((__nv_bfloat16*)g_poh)[o] = h;
    ((__nv_bfloat16*)g_pol)[o] = l;
}

// =====================================================================
// conv3/conv4 via mma.sync, bf16 3-pass.
// =====================================================================
#define C34_SMEM 83456

template<bool DO_LRN>
__global__ __launch_bounds__(256, 2) void conv34_mma(
    const uint4* __restrict__ inh, const uint4* __restrict__ inl,
    const uint4* __restrict__ wth, const uint4* __restrict__ wtl,
    const float* __restrict__ bias,
    __nv_bfloat16* __restrict__ outh, __nv_bfloat16* __restrict__ outl)
{
    extern __shared__ char sm[];
    const uint32_t sA    = s2u(sm);
    const uint32_t sSlab = sA + 32768;

    const int tid  = threadIdx.x;
    const int lane = tid & 31;
    const int wid  = tid >> 5;
    const int mw   = (wid & 3) * 16;
    const int nh   = wid >> 2;
    const int y = blockIdx.x, q = blockIdx.y;

    const int ar  = lane & 15;
    const int acp = lane >> 4;
    const int bxl = lane & 7;
    const int bp  = (lane >> 3) & 1;
    const int nb  = lane >> 4;

    float acc[4][4];
    #pragma unroll
    for (int nt = 0; nt < 4; nt++)
        #pragma unroll
        for (int j = 0; j < 4; j++) acc[nt][j] = 0.f;

    for (int i = tid; i < 3168; i += 256) {
        int sel = i >= 1584;
        int j = sel ? i - 1584 : i;
        int ky = j / 528;
        int jj = j % 528;
        int r = jj >> 3, c = jj & 7;
        const uint4* src = (sel ? inl : inh) + ((size_t)(q * 65 + y + ky) * 66 + r) * 8;
        ((uint4*)(sm + 32768))[(size_t)sel * 1584 + ky * 528 + r * 8 + (c ^ (r & 7))] = src[c];
    }
    {
        #pragma unroll
        for (int i = 0; i < 2; i++) {
            CP16(sA + (tid + i * 256) * 16,        wth + tid + i * 256);
            CP16(sA + 8192 + (tid + i * 256) * 16, wtl + tid + i * 256);
        }
        CP_COMMIT;
        CP_WAIT0;
    }
    __syncthreads();

    #pragma unroll 1
    for (int t = 0; t < 9; t++) {
        const int ky = t / 3, kx = t % 3;
        const uint32_t bufA = sA + (uint32_t)(t & 1) * 16384;

        uint32_t Ah[4][4], Al[4][4];
        {
            const uint32_t rowoff = bufA + (uint32_t)(mw + ar) * 128;
            #pragma unroll
            for (int k = 0; k < 4; k++) {
                uint32_t ch = (uint32_t)(((2 * k + acp) ^ (ar & 7)) * 16);
                LDSM4(Ah[k], rowoff + ch);
                LDSM4(Al[k], rowoff + ch + 8192);
            }
        }
        {
            int tn = t + 1; if (tn > 8) tn = 8;
            uint32_t dA = sA + (uint32_t)((t + 1) & 1) * 16384;
            #pragma unroll
            for (int i = 0; i < 2; i++) {
                CP16(dA + (tid + i * 256) * 16,        wth + (size_t)tn * 512 + tid + i * 256);
                CP16(dA + 8192 + (tid + i * 256) * 16, wtl + (size_t)tn * 512 + tid + i * 256);
            }
            CP_COMMIT;
        }

        const uint32_t slabh = sSlab + (uint32_t)ky * 8448;
        const uint32_t slabl = slabh + 25344;
        const uint32_t rowbyte = (uint32_t)(kx + nh * 32 + nb * 8 + bxl) * 128;
        const uint32_t xorb = (uint32_t)((kx + bxl) & 7);
        #pragma unroll
        for (int k = 0; k < 4; k++) {
            const uint32_t ch = (uint32_t)(((uint32_t)(2 * k + bp) ^ xorb) * 16);
            #pragma unroll
            for (int p = 0; p < 2; p++) {
                const uint32_t off = rowbyte + (uint32_t)(p * 2048) + ch;
                uint32_t rh[4], rl[4];
                LDSM4(rh, slabh + off);
                MMA16816(acc[2 * p],     Ah[k], rh);
                MMA16816(acc[2 * p],     Al[k], rh);
                MMA16816(acc[2 * p + 1], Ah[k], rh + 2);
                MMA16816(acc[2 * p + 1], Al[k], rh + 2);
                LDSM4(rl, slabl + off);
                MMA16816(acc[2 * p],     Ah[k], rl);
                MMA16816(acc[2 * p + 1], Ah[k], rl + 2);
            }
        }

        CP_WAIT0;
        __syncthreads();
    }

    float* L = (float*)sm;
    {
        const int r0 = mw + (lane >> 2);
        const int r1 = r0 + 8;
        const float b0 = bias[r0];
        const float b1 = bias[r1];
        #pragma unroll
        for (int nt = 0; nt < 4; nt++) {
            const int px = nh * 32 + nt * 8 + 2 * (lane & 3);
            L[r0 * 65 + px]     = fmaxf(acc[nt][0] + b0, 0.f);
            L[r0 * 65 + px + 1] = fmaxf(acc[nt][1] + b0, 0.f);
            L[r1 * 65 + px]     = fmaxf(acc[nt][2] + b1, 0.f);
            L[r1 * 65 + px + 1] = fmaxf(acc[nt][3] + b1, 0.f);
        }
    }
    __syncthreads();
    {
        const int co = tid >> 2;
        const int pxb = (tid & 3) * 16;
        #pragma unroll
        for (int e = 0; e < 16; e++) {
            int px = pxb + e;
            if (px >= 63) continue;
            float cur = L[co * 65 + px];
            if (DO_LRN) {
                float pv = co ? L[(co - 1) * 65 + px] : 0.f;
                float dnm = 1.f + 1e-5f * (pv * pv + cur * cur);
                cur = cur * powf(dnm, -0.75f);
            }
            __nv_bfloat16 h, l; bfsplit(cur, h, l);
            size_t o;
            if (DO_LRN)
                o = ((size_t)(q * 63 + y) * 64 + px) * 64 + co;
            else
                o = ((size_t)(q * 65 + y + 1) * 66 + px + 1) * 64 + co;
            outh[o] = h;
            outl[o] = l;
        }
    }
}

// =====================================================================
// transform: w5 -> swizzled tiles (vectorized)
// =====================================================================
__global__ void tr_w5_kernel(const float* __restrict__ w5)
{
    int id = blockIdx.x * 256 + threadIdx.x;
    if (id >= 1024 * 8 * 256) return;
    int tap = id & 255;
    int j   = (id >> 8) & 7;
    int co  = id >> 11;

    uint32_t hh[4], ll[4];
    #pragma unroll
    for (int p = 0; p < 4; p++) {
        float v0 = w5[(co * 64 + j * 8 + 2 * p)     * 256 + tap];
        float v1 = w5[(co * 64 + j * 8 + 2 * p + 1) * 256 + tap];
        __nv_bfloat16 h0, l0, h1, l1;
        bfsplit(v0, h0, l0); bfsplit(v1, h1, l1);
        __nv_bfloat162 ph; ph.x = h0; ph.y = h1;
        hh[p] = *(uint32_t*)&ph;
        ll[p] = bfpack(__bfloat162float(l0), __bfloat162float(l1));
    }
    int cotile = co >> 7, co128 = co & 127;
    uint32_t off = swz((uint32_t)(co128 * 128 + j * 16)) >> 4;
    size_t base = (size_t)(cotile * 256 + tap) * 1024 + off;
    g_wh[base] = make_uint4(hh[0], hh[1], hh[2], hh[3]);
    g_wl[base] = make_uint4(ll[0], ll[1], ll[2], ll[3]);
}

// =====================================================================
// transform: w6 -> swizzled tiles
// =====================================================================
__global__ void tr_w6_kernel(const float* __restrict__ w6)
{
    int id = blockIdx.x * 256 + threadIdx.x;
    if (id >= 1024 * 16 * 8) return;
    int jj = id & 7;
    int kc = (id >> 3) & 15;
    int co = id >> 7;

    uint32_t hh[4], ll[4];
    #pragma unroll
    for (int p = 0; p < 4; p++) {
        float v0 = w6[co * 1024 + kc * 64 + jj * 8 + 2 * p];
        float v1 = w6[co * 1024 + kc * 64 + jj * 8 + 2 * p + 1];
        __nv_bfloat16 h0, l0, h1, l1;
        bfsplit(v0, h0, l0); bfsplit(v1, h1, l1);
        __nv_bfloat162 ph; ph.x = h0; ph.y = h1;
        hh[p] = *(uint32_t*)&ph;
        ll[p] = bfpack(__bfloat162float(l0), __bfloat162float(l1));
    }
    int cotile = co >> 7, co128 = co & 127;
    uint32_t off = swz((uint32_t)(co128 * 128 + jj * 16)) >> 4;
    size_t base = (size_t)(cotile * 16 + kc) * 1024 + off;
    g_w6h[base] = make_uint4(hh[0], hh[1], hh[2], hh[3]);
    g_w6l[base] = make_uint4(ll[0], ll[1], ll[2], ll[3]);
}

// =====================================================================
// conv5 via mma.sync (3-row tiles); epilogue writes bf16-split [q][px][co]
// =====================================================================
#define C5_ABUF 32768
#define C5_SLAB 65536
#define C5_SMEM 114688

__global__ __launch_bounds__(256, 1) void conv5_mma(
    const float* __restrict__ bias)
{
    extern __shared__ char sm[];
    const uint32_t sA    = s2u(sm);
    const uint32_t sSlab = sA + C5_SLAB;
    char* Slab = sm + C5_SLAB;

    const int tid  = threadIdx.x;
    const int lane = tid & 31;
    const int wid  = tid >> 5;
    const int yblk = blockIdx.x, cotile = blockIdx.y, q = blockIdx.z;
    const int Y0 = yblk * 3;
    const int m  = wid * 16;

    const int ar  = lane & 15;
    const int acp = lane >> 4;
    const int bxl = lane & 7;
    const int bp  = (lane >> 3) & 1;
    const int nb  = lane >> 4;
    const uint32_t nbadd = (uint32_t)nb * 1024;

    float acc[3][6][4];
    #pragma unroll
    for (int r = 0; r < 3; r++)
        #pragma unroll
        for (int nt = 0; nt < 6; nt++)
            #pragma unroll
            for (int j = 0; j < 4; j++) acc[r][nt][j] = 0.f;

    {
        const uint4* sh = g_wh + (size_t)(cotile * 256) * 1024;
        const uint4* sl = g_wl + (size_t)(cotile * 256) * 1024;
        #pragma unroll
        for (int i = 0; i < 4; i++) {
            CP16(sA + (tid + i * 256) * 16,         sh + tid + i * 256);
            CP16(sA + 16384 + (tid + i * 256) * 16, sl + tid + i * 256);
        }
        CP_COMMIT;
        CP_WAIT0;
    }

    #pragma unroll 1
    for (int t = 0; t < 256; t++) {
        const int kx = t & 15;
        if (kx == 0) {
            const int ky = t >> 4;
            for (int i = tid; i < 3072; i += 256) {
                int s = i >> 9;
                int j = i & 511;
                int x = j >> 3, c = j & 7;
                int rr = s >> 1, sel = s & 1;
                const uint4* src = (sel ? g_tl : g_th) + (size_t)(q * 63 + Y0 + ky + rr) * 512;
                ((uint4*)Slab)[s * 512 + x * 8 + (c ^ (x & 7))] = src[j];
            }
            __syncthreads();
        }

        const uint32_t bufA = sA + (uint32_t)(t & 1) * C5_ABUF;

        uint32_t Ah[4][4], Al[4][4];
        {
            const uint32_t rowoff = bufA + (uint32_t)(m + ar) * 128;
            #pragma unroll
            for (int k = 0; k < 4; k++) {
                uint32_t ch = (uint32_t)(((2 * k + acp) ^ (ar & 7)) * 16);
                LDSM4(Ah[k], rowoff + ch);
                LDSM4(Al[k], rowoff + ch + 16384);
            }
        }

        {
            int tn = t + 1; if (tn > 255) tn = 255;
            const uint4* sh = g_wh + (size_t)(cotile * 256 + tn) * 1024;
            const uint4* sl = g_wl + (size_t)(cotile * 256 + tn) * 1024;
            uint32_t dA = sA + (uint32_t)((t + 1) & 1) * C5_ABUF;
            #pragma unroll
            for (int i = 0; i < 4; i++) {
                CP16(dA + (tid + i * 256) * 16,         sh + tid + i * 256);
                CP16(dA + 16384 + (tid + i * 256) * 16, sl + tid + i * 256);
            }
            CP_COMMIT;
        }

        const uint32_t rowbyte = (uint32_t)(kx + bxl) * 128;
        const uint32_t xorb = (uint32_t)((kx + bxl) & 7);
        #pragma unroll
        for (int rr = 0; rr < 3; rr++) {
            const uint32_t hb = sSlab + (uint32_t)(2 * rr) * 8192 + rowbyte + nbadd;
            const uint32_t lb = hb + 8192;
            #pragma unroll
            for (int k = 0; k < 4; k++) {
                const uint32_t ch = (uint32_t)(((uint32_t)(2 * k + bp) ^ xorb) * 16);
                #pragma unroll
                for (int p = 0; p < 3; p++) {
                    const uint32_t off = (uint32_t)(p * 2048) + ch;
                    uint32_t rh[4], rl[4];
                    LDSM4(rh, hb + off);
                    MMA16816(acc[rr][2 * p],     Ah[k], rh);
                    MMA16816(acc[rr][2 * p],     Al[k], rh);
                    MMA16816(acc[rr][2 * p + 1], Ah[k], rh + 2);
                    MMA16816(acc[rr][2 * p + 1], Al[k], rh + 2);
                    LDSM4(rl, lb + off);
                    MMA16816(acc[rr][2 * p],     Ah[k], rl);
                    MMA16816(acc[rr][2 * p + 1], Ah[k], rl + 2);
                }
            }
        }

        CP_WAIT0;
        __syncthreads();
    }

    // epilogue: bias+relu, bf16-split store to [q][px][co]
    {
        __nv_bfloat16* eh = (__nv_bfloat16*)g_eh;
        __nv_bfloat16* el = (__nv_bfloat16*)g_el;
        const int co0 = cotile * 128 + m + (lane >> 2);
        const int co1 = co0 + 8;
        const float b0 = bias[co0];
        const float b1 = bias[co1];
        #pragma unroll
        for (int rr = 0; rr < 3; rr++) {
            const int gy = Y0 + rr;
            #pragma unroll
            for (int nt = 0; nt < 6; nt++) {
                const int px = nt * 8 + 2 * (lane & 3);
                size_t base = ((size_t)(q * 2304 + gy * 48 + px)) * 1024;
                float v00 = fmaxf(acc[rr][nt][0] + b0, 0.f);
                float v01 = fmaxf(acc[rr][nt][1] + b0, 0.f);
                float v10 = fmaxf(acc[rr][nt][2] + b1, 0.f);
                float v11 = fmaxf(acc[rr][nt][3] + b1, 0.f);
                __nv_bfloat16 h, l;
                bfsplit(v00, h, l); eh[base + co0] = h;        el[base + co0] = l;
                bfsplit(v01, h, l); eh[base + 1024 + co0] = h; el[base + 1024 + co0] = l;
                bfsplit(v10, h, l); eh[base + co1] = h;        el[base + co1] = l;
                bfsplit(v11, h, l); eh[base + 1024 + co1] = h; el[base + 1024 + co1] = l;
            }
        }
    }
}

// =====================================================================
// conv6 via mma.sync, m32xn64 warp-tiles (256 thr), fused conv7 partials.
// Block: M=128co x N=128px, K=1024 in 16 chunks; double-buffered cp.async.
// Epilogue: partial dot with w7 over the block's 128 co (deterministic
// shfl+smem tree) -> g_part[q][px][cotile].
// =====================================================================
#define C6_BUF  65536
#define C6_SMEM 131072

__global__ __launch_bounds__(256, 1) void conv6_mma(
    const float* __restrict__ bias, const float* __restrict__ w7,
    float* __restrict__ part)
{
    extern __shared__ char sm[];
    const uint32_t sB0 = s2u(sm);

    const int tid  = threadIdx.x;
    const int lane = tid & 31;
    const int wid  = tid >> 5;       // 0..7
    const int mq   = wid & 3;        // m32 tile index
    const int nq   = wid >> 2;       // n64 half
    const int bx = blockIdx.x, cotile = blockIdx.y, q = blockIdx.z;
    const int px0 = bx * 128;

    const int ar  = lane & 15;
    const int acp = lane >> 4;
    const int bxl = lane & 7;
    const int bp  = (lane >> 3) & 1;
    const int nb  = lane >> 4;

    float acc[2][8][4];   // [m-sub][n-tile][frag]
    #pragma unroll
    for (int ms = 0; ms < 2; ms++)
        #pragma unroll
        for (int nt = 0; nt < 8; nt++)
            #pragma unroll
            for (int j = 0; j < 4; j++) acc[ms][nt][j] = 0.f;

    auto load_chunk = [&](int kc, uint32_t dbuf) {
        const uint4* ah = g_w6h + (size_t)(cotile * 16 + kc) * 1024;
        const uint4* al = g_w6l + (size_t)(cotile * 16 + kc) * 1024;
        #pragma unroll
        for (int r = 0; r < 4; r++) {
            int i = tid + r * 256;
            CP16(dbuf + i * 16,         ah + i);
            CP16(dbuf + 16384 + i * 16, al + i);
        }
        #pragma unroll
        for (int r = 0; r < 4; r++) {
            int j = tid + r * 256;
            int n = j >> 3, c = j & 7;
            size_t src = (size_t)(q * 2304 + px0 + n) * 128 + kc * 8 + c;
            uint32_t dst = (uint32_t)(n * 128 + (c ^ (n & 7)) * 16);
            CP16(dbuf + 32768 + dst, g_eh + src);
            CP16(dbuf + 49152 + dst, g_el + src);
        }
        CP_COMMIT;
    };

    load_chunk(0, sB0);
    CP_WAIT0;
    __syncthreads();

    #pragma unroll 1
    for (int kc = 0; kc < 16; kc++) {
        const uint32_t buf = sB0 + (uint32_t)(kc & 1) * C6_BUF;

        {
            int kn = kc + 1; if (kn > 15) kn = 15;
            load_chunk(kn, sB0 + (uint32_t)((kc + 1) & 1) * C6_BUF);
        }

        const uint32_t hbb = buf + 32768 + (uint32_t)(nq * 64 + nb * 8 + bxl) * 128;
        #pragma unroll
        for (int k = 0; k < 4; k++) {
            // A frags for both m16 sub-tiles
            uint32_t Ah[2][4], Al[2][4];
            #pragma unroll
            for (int ms = 0; ms < 2; ms++) {
                const uint32_t rowoff = buf + (uint32_t)(mq * 32 + ms * 16 + ar) * 128;
                uint32_t ch = (uint32_t)(((2 * k + acp) ^ (ar & 7)) * 16);
                LDSM4(Ah[ms], rowoff + ch);
                LDSM4(Al[ms], rowoff + ch + 16384);
            }
            const uint32_t ch = (uint32_t)(((uint32_t)(2 * k + bp) ^ (uint32_t)bxl) * 16);
            #pragma unroll
            for (int p = 0; p < 4; p++) {
                const uint32_t off = (uint32_t)(p * 2048) + ch;
                uint32_t rh[4], rl[4];
                LDSM4(rh, hbb + off);
                LDSM4(rl, hbb + 16384 + off);
                #pragma unroll
                for (int ms = 0; ms < 2; ms++) {
                    MMA16816(acc[ms][2 * p],     Ah[ms], rh);
                    MMA16816(acc[ms][2 * p],     Al[ms], rh);
                    MMA16816(acc[ms][2 * p + 1], Ah[ms], rh + 2);
                    MMA16816(acc[ms][2 * p + 1], Al[ms], rh + 2);
                    MMA16816(acc[ms][2 * p],     Ah[ms], rl);
                    MMA16816(acc[ms][2 * p + 1], Ah[ms], rl + 2);
                }
            }
        }

        CP_WAIT0;
        __syncthreads();
    }

    // ---- fused conv7 partial: sum over this block's 128 co of w7*relu(.+b6)
    float* red = (float*)sm;   // [4 mq][128 px]
    {
        float w0[2], w1[2], bb0[2], bb1[2];
        #pragma unroll
        for (int ms = 0; ms < 2; ms++) {
            int co0 = cotile * 128 + mq * 32 + ms * 16 + (lane >> 2);
            int co1 = co0 + 8;
            w0[ms] = w7[co0];  w1[ms] = w7[co1];
            bb0[ms] = bias[co0]; bb1[ms] = bias[co1];
        }
        float s[16];
        #pragma unroll
        for (int nt = 0; nt < 8; nt++)
            #pragma unroll
            for (int c2 = 0; c2 < 2; c2++) {
                float sum = 0.f;
                #pragma unroll
                for (int ms = 0; ms < 2; ms++) {
                    sum += fmaxf(acc[ms][nt][c2]     + bb0[ms], 0.f) * w0[ms];
                    sum += fmaxf(acc[ms][nt][c2 + 2] + bb1[ms], 0.f) * w1[ms];
                }
                s[nt * 2 + c2] = sum;
            }
        #pragma unroll
        for (int i = 0; i < 16; i++) {
            s[i] += __shfl_down_sync(0xffffffffu, s[i], 16);
            s[i] += __shfl_down_sync(0xffffffffu, s[i], 8);
            s[i] += __shfl_down_sync(0xffffffffu, s[i], 4);
        }
        if (lane < 4) {
            #pragma unroll
            for (int nt = 0; nt < 8; nt++)
                #pragma unroll
                for (int c2 = 0; c2 < 2; c2++)
                    red[mq * 128 + nq * 64 + nt * 8 + 2 * lane + c2] = s[nt * 2 + c2];
        }
    }
    __syncthreads();
    if (tid < 128) {
        float sum = red[tid] + red[128 + tid] + red[256 + tid] + red[384 + tid];
        part[((size_t)(q * 2304 + px0 + tid)) * 8 + cotile] = sum;
    }
}

// =====================================================================
// conv7b: sum 8 partials + bias, sigmoid, interweave -> d_out (2,1,96,96)
// =====================================================================
__global__ void conv7b_kernel(const float* __restrict__ part,
                              const float* __restrict__ b7,
                              float* __restrict__ out)
{
    int id = blockIdx.x * 256 + threadIdx.x;
    if (id >= NQ * PX5) return;
    const float* p = part + (size_t)id * 8;
    float acc = b7[0];
    #pragma unroll
    for (int i = 0; i < 8; i++) acc += p[i];
    float s = 1.f / (1.f + expf(-acc));
    int hw = id % PX5;
    int q  = id / PX5;
    int h = hw / HO, wv = hw % HO;
    int n = q & 1, ss = (q >> 1) & 1, t = q >> 2;
    out[n * 96 * 96 + (2 * h + ss) * 96 + (2 * wv + t)] = s;
}

// =====================================================================
// launch
// =====================================================================
extern "C" void kernel_launch(void* const* d_in, const int* in_sizes, int n_in,
                              void* d_out, int out_size)
{
    const float* x  = (const float*)d_in[0];
    const float* w1 = (const float*)d_in[1];  const float* b1 = (const float*)d_in[2];
    const float* w2 = (const float*)d_in[3];  const float* b2 = (const float*)d_in[4];
    const float* w3 = (const float*)d_in[5];  const float* b3 = (const float*)d_in[6];
    const float* w4 = (const float*)d_in[7];  const float* b4 = (const float*)d_in[8];
    const float* w5 = (const float*)d_in[9];  const float* b5 = (const float*)d_in[10];
    const float* w6 = (const float*)d_in[11]; const float* b6 = (const float*)d_in[12];
    const float* w7 = (const float*)d_in[13]; const float* b7 = (const float*)d_in[14];

    void *pa2, *pb2, *ppart;
    void *pw2h, *pw2l, *pw3h, *pw3l, *pw4h, *pw4l;
    void *ppoh, *ppol, *pc3h, *pc3l, *pth, *ptl;
    cudaGetSymbolAddress(&pa2, g_a2);
    cudaGetSymbolAddress(&pb2, g_b2);
    cudaGetSymbolAddress(&ppart, g_part);
    cudaGetSymbolAddress(&pw2h, g_w2h); cudaGetSymbolAddress(&pw2l, g_w2l);
    cudaGetSymbolAddress(&pw3h, g_w3h); cudaGetSymbolAddress(&pw3l, g_w3l);
    cudaGetSymbolAddress(&pw4h, g_w4h); cudaGetSymbolAddress(&pw4l, g_w4l);
    cudaGetSymbolAddress(&ppoh, g_poh); cudaGetSymbolAddress(&ppol, g_pol);
    cudaGetSymbolAddress(&pc3h, g_c3h); cudaGetSymbolAddress(&pc3l, g_c3l);
    cudaGetSymbolAddress(&pth, g_th);   cudaGetSymbolAddress(&ptl, g_tl);

    cudaFuncSetAttribute(conv5_mma, cudaFuncAttributeMaxDynamicSharedMemorySize, C5_SMEM);
    cudaFuncSetAttribute(conv6_mma, cudaFuncAttributeMaxDynamicSharedMemorySize, C6_SMEM);
    cudaFuncSetAttribute(conv2_mma, cudaFuncAttributeMaxDynamicSharedMemorySize, C2_SMEM);
    cudaFuncSetAttribute(conv34_mma<false>, cudaFuncAttributeMaxDynamicSharedMemorySize, C34_SMEM);
    cudaFuncSetAttribute(conv34_mma<true>,  cudaFuncAttributeMaxDynamicSharedMemorySize, C34_SMEM);

    // weight transforms (independent)
    tr_w5_kernel<<<(1024 * 8 * 256 + 255) / 256, 256>>>(w5);
    tr_w6_kernel<<<(1024 * 16 * 8 + 255) / 256, 256>>>(w6);
    tr_wsq_kernel<<<(64 * 8 * 25 + 255) / 256, 256>>>(w2, (uint4*)pw2h, (uint4*)pw2l, 25);
    tr_wsq_kernel<<<(64 * 8 * 9 + 255) / 256, 256>>>(w3, (uint4*)pw3h, (uint4*)pw3l, 9);
    tr_wsq_kernel<<<(64 * 8 * 9 + 255) / 256, 256>>>(w4, (uint4*)pw4h, (uint4*)pw4l, 9);

    // conv1 -> pad/split -> conv2 (mma + LRN)
    conv1_kernel<<<dim3(8, 8, NB), 256>>>(x, w1, b1, (float*)pa2);
    tr_a_kernel<<<(NB * 132 * 136 * 64 + 255) / 256, 256>>>();
    conv2_mma<<<dim3(2, 128, 2), 256, C2_SMEM>>>(b2, (float*)pb2);

    // pool (padded bf16-split), conv3, conv4 (emits conv5 input fmt)
    pool_kernel<<<(NQ * 63 * 63 * 64 + 255) / 256, 256>>>();
    conv34_mma<false><<<dim3(63, NQ), 256, C34_SMEM>>>(
        (const uint4*)ppoh, (const uint4*)ppol, (const uint4*)pw3h, (const uint4*)pw3l,
        b3, (__nv_bfloat16*)pc3h, (__nv_bfloat16*)pc3l);
    conv34_mma<true><<<dim3(63, NQ), 256, C34_SMEM>>>(
        (const uint4*)pc3h, (const uint4*)pc3l, (const uint4*)pw4h, (const uint4*)pw4l,
        b4, (__nv_bfloat16*)pth, (__nv_bfloat16*)ptl);

    // conv5 (writes transposed bf16-split), conv6 (fused conv7 partials), conv7b
    conv5_mma<<<dim3(16, 8, NQ), 256, C5_SMEM>>>(b5);
    conv6_mma<<<dim3(18, 8, NQ), 256, C6_SMEM>>>(b6, w7, (float*)ppart);
    conv7b_kernel<<<(NQ * PX5 + 255) / 256, 256>>>((const float*)ppart, b7, (float*)d_out);
}